// round 4
// baseline (speedup 1.0000x reference)
#include <cuda_runtime.h>

#define N_NODES 2048
#define IN_F    512
#define HID     256
#define OUT_F   128
#define H1      8
#define F1      32   // HID / H1
#define NWORDS  64   // N_NODES / 32
#define JSPLIT1 8
#define JSPLIT2 16
#define KS1     4    // gemm1 K-split
#define KS2     8    // gemm2 K-split

typedef unsigned long long ull;

__device__ __forceinline__ ull fma2(ull a, ull b, ull c) {
    ull d;
    asm("fma.rn.f32x2 %0, %1, %2, %3;" : "=l"(d) : "l"(a), "l"(b), "l"(c));
    return d;
}
__device__ __forceinline__ ull pack2(float v) {
    ull d;
    asm("mov.b64 %0, {%1, %1};" : "=l"(d) : "f"(v));
    return d;
}
__device__ __forceinline__ void unpack2(ull v, float& lo, float& hi) {
    asm("mov.b64 {%0, %1}, %2;" : "=f"(lo), "=f"(hi) : "l"(v));
}

// ---------------- scratch ----------------
__device__ __align__(16) float  g_gp1[KS1 * N_NODES * HID];
__device__ __align__(16) float  g_g1[N_NODES * HID];
__device__ __align__(16) float4 g_eli1[N_NODES * H1];   // {-el, exp(el), exp(0.2el), 0}
__device__ __align__(16) float4 g_ebd1[N_NODES * H1];   // {er, exp(er), exp(0.2er), 0}
__device__ unsigned g_bits[N_NODES * NWORDS];
__device__ __align__(16) float  g_n1[JSPLIT1 * N_NODES * HID];
__device__ float  g_d1[JSPLIT1 * N_NODES * H1];
__device__ __align__(16) float  g_h1[N_NODES * HID];
__device__ __align__(16) float  g_gp2[KS2 * N_NODES * OUT_F];
__device__ __align__(16) float  g_g2[N_NODES * OUT_F];
__device__ __align__(16) float4 g_eli2[N_NODES];
__device__ __align__(16) float4 g_ebd2[N_NODES];
__device__ __align__(16) float  g_part[JSPLIT2 * N_NODES * OUT_F];
__device__ float  g_psum[JSPLIT2 * N_NODES];

// ---------------- pack adjacency ----------------
__global__ void pack_adj_kernel(const int* __restrict__ adj) {
    int i = blockIdx.x;
    int t = threadIdx.x;  // 256
    const int* row = adj + (size_t)i * N_NODES;
#pragma unroll
    for (int k = 0; k < 8; k++) {
        int j = k * 256 + t;
        unsigned b = __ballot_sync(0xffffffffu, row[j] != 0);
        if ((t & 31) == 0) g_bits[i * NWORDS + (j >> 5)] = b;
    }
}

// ---------------- GEMM 128x128xK, 8x8 per thread, K-split via blockIdx.z ----------------
__global__ __launch_bounds__(256) void gemm_kernel(const float* __restrict__ A,
                                                   const float* __restrict__ B,
                                                   float* __restrict__ C,
                                                   int M, int N, int Klen, int lda) {
    __shared__ float As[128][33];
    __shared__ __align__(16) float Bs[32][128];
    const float* Ap = A + (size_t)blockIdx.z * Klen;
    const float* Bp = B + (size_t)blockIdx.z * Klen * N;
    float* Cp = C + (size_t)blockIdx.z * M * N;
    int bi = blockIdx.y * 128;
    int bn = blockIdx.x * 128;
    int t = threadIdx.x;
    int tn = (t & 15) * 8;
    int ti = (t >> 4) * 8;
    ull acc[8][4] = {};
    for (int k0 = 0; k0 < Klen; k0 += 32) {
        __syncthreads();
        // A: 128x32, 1024 float4, 4 per thread -> As[i][k]
#pragma unroll
        for (int e = t; e < 1024; e += 256) {
            int i = e >> 3, kq = e & 7;
            float4 a4 = *(const float4*)(Ap + (size_t)(bi + i) * lda + k0 + kq * 4);
            As[i][kq * 4 + 0] = a4.x; As[i][kq * 4 + 1] = a4.y;
            As[i][kq * 4 + 2] = a4.z; As[i][kq * 4 + 3] = a4.w;
        }
        // B: 32x128
#pragma unroll
        for (int e = t; e < 1024; e += 256) {
            int k = e >> 5, q = e & 31;
            *(float4*)&Bs[k][q * 4] = *(const float4*)(Bp + (size_t)(k0 + k) * N + bn + q * 4);
        }
        __syncthreads();
#pragma unroll 8
        for (int k = 0; k < 32; k++) {
            ulonglong2 b0 = *(const ulonglong2*)&Bs[k][tn];
            ulonglong2 b1 = *(const ulonglong2*)&Bs[k][tn + 4];
#pragma unroll
            for (int r = 0; r < 8; r++) {
                ull a2 = pack2(As[ti + r][k]);
                acc[r][0] = fma2(a2, b0.x, acc[r][0]);
                acc[r][1] = fma2(a2, b0.y, acc[r][1]);
                acc[r][2] = fma2(a2, b1.x, acc[r][2]);
                acc[r][3] = fma2(a2, b1.y, acc[r][3]);
            }
        }
    }
#pragma unroll
    for (int r = 0; r < 8; r++) {
        float v[8];
        unpack2(acc[r][0], v[0], v[1]);
        unpack2(acc[r][1], v[2], v[3]);
        unpack2(acc[r][2], v[4], v[5]);
        unpack2(acc[r][3], v[6], v[7]);
        float* dst = Cp + (size_t)(bi + ti + r) * N + bn + tn;
        *(float4*)dst = make_float4(v[0], v[1], v[2], v[3]);
        *(float4*)(dst + 4) = make_float4(v[4], v[5], v[6], v[7]);
    }
}

// ---------------- layer1: add K-partials, el/er exponentials ----------------
__global__ void elr1_kernel(const float* __restrict__ al, const float* __restrict__ ar) {
    int i = blockIdx.x;
    int t = threadIdx.x;  // 256
    float v = 0.f;
#pragma unroll
    for (int z = 0; z < KS1; z++) v += g_gp1[((size_t)z * N_NODES + i) * HID + t];
    g_g1[(size_t)i * HID + t] = v;
    float pl = v * al[t & 31];
    float pr = v * ar[t & 31];
#pragma unroll
    for (int o = 16; o; o >>= 1) {
        pl += __shfl_down_sync(0xffffffffu, pl, o);
        pr += __shfl_down_sync(0xffffffffu, pr, o);
    }
    if ((t & 31) == 0) {
        int h = t >> 5;
        g_eli1[i * H1 + h] = make_float4(-pl, __expf(pl), __expf(0.2f * pl), 0.f);
        g_ebd1[i * H1 + h] = make_float4(pr, __expf(pr), __expf(0.2f * pr), 0.f);
    }
}

// ---------------- layer1 aggregation: 256i x 32f tile, 8i x 4f per thread ----------------
__global__ __launch_bounds__(256) void agg1_kernel() {
    __shared__ float w_s[32][256];          // 32KB [j][i]
    __shared__ __align__(16) ull G2_s[32][32]; // 8KB duplicated G pairs [j][f]
    __shared__ __align__(16) float4 ebd_s[32];
    int h = blockIdx.x >> 3;
    int p = blockIdx.x & 7;
    int bi = blockIdx.y * 256;
    int t = threadIdx.x;  // 256

    float4 eli = g_eli1[(bi + t) * H1 + h];
    float negEl = eli.x, Ai = eli.y, Ci = eli.z;
    int fg = t & 7, ig = t >> 3;
    int f0 = fg * 4, i0 = ig * 8;
    ull acc[4][4] = {};
    float lsum = 0.f;
    int jstart = p * (N_NODES / JSPLIT1);  // 256 j per block

    for (int j0 = jstart; j0 < jstart + N_NODES / JSPLIT1; j0 += 32) {
        __syncthreads();
        // stage G duplicated: 32j x 32f -> 256 float4, 1 per thread
        {
            int j = t >> 3, q = t & 7;
            float4 g4 = *(const float4*)(g_g1 + (size_t)(j0 + j) * HID + h * F1 + q * 4);
            ulonglong2 d0 = {pack2(g4.x), pack2(g4.y)};
            ulonglong2 d1 = {pack2(g4.z), pack2(g4.w)};
            ((ulonglong2*)&G2_s[j][q * 4])[0] = d0;
            ((ulonglong2*)&G2_s[j][q * 4])[1] = d1;
        }
        if (t < 32) ebd_s[t] = g_ebd1[(size_t)(j0 + t) * H1 + h];
        __syncthreads();
        // weights: thread t owns row i = bi+t, 32 j
        unsigned word = g_bits[(bi + t) * NWORDS + (j0 >> 5)];
#pragma unroll 8
        for (int jj = 0; jj < 32; jj++) {
            float4 e4 = ebd_s[jj];  // broadcast
            float w = (e4.x > negEl) ? Ai * e4.y : Ci * e4.z;
            w = ((word >> jj) & 1u) ? w : 0.f;
            lsum += w;
            w_s[jj][t] = w;
        }
        __syncthreads();
        // FMA: 4 LDS.128 + 16 FFMA2 per jj, no packs
#pragma unroll 8
        for (int jj = 0; jj < 32; jj++) {
            ulonglong2 wa = *(const ulonglong2*)&w_s[jj][i0];
            ulonglong2 wb = *(const ulonglong2*)&w_s[jj][i0 + 4];
            ulonglong2 ga = *(const ulonglong2*)&G2_s[jj][f0];
            ulonglong2 gb = *(const ulonglong2*)&G2_s[jj][f0 + 2];
            acc[0][0] = fma2(wa.x, ga.x, acc[0][0]); acc[0][1] = fma2(wa.x, ga.y, acc[0][1]);
            acc[0][2] = fma2(wa.x, gb.x, acc[0][2]); acc[0][3] = fma2(wa.x, gb.y, acc[0][3]);
            acc[1][0] = fma2(wa.y, ga.x, acc[1][0]); acc[1][1] = fma2(wa.y, ga.y, acc[1][1]);
            acc[1][2] = fma2(wa.y, gb.x, acc[1][2]); acc[1][3] = fma2(wa.y, gb.y, acc[1][3]);
            acc[2][0] = fma2(wb.x, ga.x, acc[2][0]); acc[2][1] = fma2(wb.x, ga.y, acc[2][1]);
            acc[2][2] = fma2(wb.x, gb.x, acc[2][2]); acc[2][3] = fma2(wb.x, gb.y, acc[2][3]);
            acc[3][0] = fma2(wb.y, ga.x, acc[3][0]); acc[3][1] = fma2(wb.y, ga.y, acc[3][1]);
            acc[3][2] = fma2(wb.y, gb.x, acc[3][2]); acc[3][3] = fma2(wb.y, gb.y, acc[3][3]);
        }
    }
    size_t base = (size_t)p * N_NODES + bi;
#pragma unroll
    for (int r = 0; r < 4; r++) {
        float lo[4], hi[4];
#pragma unroll
        for (int c = 0; c < 4; c++) unpack2(acc[r][c], lo[c], hi[c]);
        *(float4*)(g_n1 + (base + i0 + 2 * r) * HID + h * F1 + f0) =
            make_float4(lo[0], lo[1], lo[2], lo[3]);
        *(float4*)(g_n1 + (base + i0 + 2 * r + 1) * HID + h * F1 + f0) =
            make_float4(hi[0], hi[1], hi[2], hi[3]);
    }
    g_d1[(base + t) * H1 + h] = lsum;
}

// ---------------- layer1 reduce + divide + ELU ----------------
__global__ void reduce1_kernel() {
    int i = blockIdx.x;
    int t = threadIdx.x;  // 256
    int h = t >> 5;
    float num = 0.f, den = 0.f;
#pragma unroll
    for (int p = 0; p < JSPLIT1; p++) {
        num += g_n1[((size_t)p * N_NODES + i) * HID + t];
        den += g_d1[(p * N_NODES + i) * H1 + h];
    }
    float o = num / den;
    g_h1[(size_t)i * HID + t] = o > 0.f ? o : expm1f(o);
}

// ---------------- layer2 el/er ----------------
__global__ void elr2_kernel(const float* __restrict__ al, const float* __restrict__ ar) {
    __shared__ float sl[4], sr[4];
    int i = blockIdx.x;
    int t = threadIdx.x;  // 128
    float v = 0.f;
#pragma unroll
    for (int z = 0; z < KS2; z++) v += g_gp2[((size_t)z * N_NODES + i) * OUT_F + t];
    g_g2[(size_t)i * OUT_F + t] = v;
    float pl = v * al[t];
    float pr = v * ar[t];
#pragma unroll
    for (int o = 16; o; o >>= 1) {
        pl += __shfl_down_sync(0xffffffffu, pl, o);
        pr += __shfl_down_sync(0xffffffffu, pr, o);
    }
    if ((t & 31) == 0) { sl[t >> 5] = pl; sr[t >> 5] = pr; }
    __syncthreads();
    if (t == 0) {
        float el = sl[0] + sl[1] + sl[2] + sl[3];
        float er = sr[0] + sr[1] + sr[2] + sr[3];
        g_eli2[i] = make_float4(-el, __expf(el), __expf(0.2f * el), 0.f);
        g_ebd2[i] = make_float4(er, __expf(er), __expf(0.2f * er), 0.f);
    }
}

// ---------------- layer2 aggregation: 128i x 128f tile, 8i x 8f per thread ----------------
__global__ __launch_bounds__(256) void agg2_kernel() {
    __shared__ float w_s[32][128];             // 16KB
    __shared__ __align__(16) ull G2_s[32][128]; // 32KB
    __shared__ __align__(16) float4 ebd_s[32];
    __shared__ float rowsum_s[256];
    int p = blockIdx.x;        // 0..15
    int bi = blockIdx.y * 128;
    int t = threadIdx.x;       // 256

    int iw = t & 127;          // weight-phase row
    int jh = t >> 7;           // j-half (16 each)
    float4 eli = g_eli2[bi + iw];
    float negEl = eli.x, Ai = eli.y, Ci = eli.z;
    int fg = t & 15, ig = t >> 4;
    int f0 = fg * 8, i0 = ig * 8;
    ull acc[4][8] = {};
    float lsum = 0.f;
    int jstart = p * (N_NODES / JSPLIT2);  // 128 j per block

    for (int j0 = jstart; j0 < jstart + N_NODES / JSPLIT2; j0 += 32) {
        __syncthreads();
        // stage G duplicated: 32j x 128f -> 1024 float4, 4 per thread
#pragma unroll
        for (int e = t; e < 1024; e += 256) {
            int j = e >> 5, q = e & 31;
            float4 g4 = *(const float4*)(g_g2 + (size_t)(j0 + j) * OUT_F + q * 4);
            ulonglong2 d0 = {pack2(g4.x), pack2(g4.y)};
            ulonglong2 d1 = {pack2(g4.z), pack2(g4.w)};
            ((ulonglong2*)&G2_s[j][q * 4])[0] = d0;
            ((ulonglong2*)&G2_s[j][q * 4])[1] = d1;
        }
        if (t < 32) ebd_s[t] = g_ebd2[j0 + t];
        __syncthreads();
        unsigned word = g_bits[(bi + iw) * NWORDS + (j0 >> 5)];
        int jb = jh * 16;
#pragma unroll 8
        for (int jj = 0; jj < 16; jj++) {
            float4 e4 = ebd_s[jb + jj];
            float w = (e4.x > negEl) ? Ai * e4.y : Ci * e4.z;
            w = ((word >> (jb + jj)) & 1u) ? w : 0.f;
            lsum += w;
            w_s[jb + jj][iw] = w;
        }
        __syncthreads();
#pragma unroll 4
        for (int jj = 0; jj < 32; jj++) {
            ulonglong2 wa = *(const ulonglong2*)&w_s[jj][i0];
            ulonglong2 wb = *(const ulonglong2*)&w_s[jj][i0 + 4];
            ulonglong2 ga = *(const ulonglong2*)&G2_s[jj][f0];
            ulonglong2 gb = *(const ulonglong2*)&G2_s[jj][f0 + 2];
            ulonglong2 gc = *(const ulonglong2*)&G2_s[jj][f0 + 4];
            ulonglong2 gd = *(const ulonglong2*)&G2_s[jj][f0 + 6];
            ull wr;
            wr = wa.x;
            acc[0][0] = fma2(wr, ga.x, acc[0][0]); acc[0][1] = fma2(wr, ga.y, acc[0][1]);
            acc[0][2] = fma2(wr, gb.x, acc[0][2]); acc[0][3] = fma2(wr, gb.y, acc[0][3]);
            acc[0][4] = fma2(wr, gc.x, acc[0][4]); acc[0][5] = fma2(wr, gc.y, acc[0][5]);
            acc[0][6] = fma2(wr, gd.x, acc[0][6]); acc[0][7] = fma2(wr, gd.y, acc[0][7]);
            wr = wa.y;
            acc[1][0] = fma2(wr, ga.x, acc[1][0]); acc[1][1] = fma2(wr, ga.y, acc[1][1]);
            acc[1][2] = fma2(wr, gb.x, acc[1][2]); acc[1][3] = fma2(wr, gb.y, acc[1][3]);
            acc[1][4] = fma2(wr, gc.x, acc[1][4]); acc[1][5] = fma2(wr, gc.y, acc[1][5]);
            acc[1][6] = fma2(wr, gd.x, acc[1][6]); acc[1][7] = fma2(wr, gd.y, acc[1][7]);
            wr = wb.x;
            acc[2][0] = fma2(wr, ga.x, acc[2][0]); acc[2][1] = fma2(wr, ga.y, acc[2][1]);
            acc[2][2] = fma2(wr, gb.x, acc[2][2]); acc[2][3] = fma2(wr, gb.y, acc[2][3]);
            acc[2][4] = fma2(wr, gc.x, acc[2][4]); acc[2][5] = fma2(wr, gc.y, acc[2][5]);
            acc[2][6] = fma2(wr, gd.x, acc[2][6]); acc[2][7] = fma2(wr, gd.y, acc[2][7]);
            wr = wb.y;
            acc[3][0] = fma2(wr, ga.x, acc[3][0]); acc[3][1] = fma2(wr, ga.y, acc[3][1]);
            acc[3][2] = fma2(wr, gb.x, acc[3][2]); acc[3][3] = fma2(wr, gb.y, acc[3][3]);
            acc[3][4] = fma2(wr, gc.x, acc[3][4]); acc[3][5] = fma2(wr, gc.y, acc[3][5]);
            acc[3][6] = fma2(wr, gd.x, acc[3][6]); acc[3][7] = fma2(wr, gd.y, acc[3][7]);
        }
    }
    rowsum_s[t] = lsum;
    __syncthreads();

#pragma unroll
    for (int r = 0; r < 4; r++) {
        float lo[8], hi[8];
#pragma unroll
        for (int c = 0; c < 8; c++) unpack2(acc[r][c], lo[c], hi[c]);
        float* d0 = g_part + (size_t)p * N_NODES * OUT_F + (size_t)(bi + i0 + 2 * r) * OUT_F + f0;
        float* d1 = d0 + OUT_F;
        *(float4*)d0 = make_float4(lo[0], lo[1], lo[2], lo[3]);
        *(float4*)(d0 + 4) = make_float4(lo[4], lo[5], lo[6], lo[7]);
        *(float4*)d1 = make_float4(hi[0], hi[1], hi[2], hi[3]);
        *(float4*)(d1 + 4) = make_float4(hi[4], hi[5], hi[6], hi[7]);
    }
    if (t < 128) g_psum[p * N_NODES + bi + t] = rowsum_s[t] + rowsum_s[128 + t];
}

// ---------------- final reduce + divide ----------------
__global__ void reduce2_kernel(float* __restrict__ out) {
    int i = blockIdx.x;
    int f = threadIdx.x;  // 128
    float num = 0.f, den = 0.f;
#pragma unroll
    for (int p = 0; p < JSPLIT2; p++) {
        num += g_part[(size_t)p * N_NODES * OUT_F + (size_t)i * OUT_F + f];
        den += g_psum[p * N_NODES + i];
    }
    out[i * OUT_F + f] = num / den;
}

// ---------------- launch ----------------
extern "C" void kernel_launch(void* const* d_in, const int* in_sizes, int n_in,
                              void* d_out, int out_size) {
    const float* x    = (const float*)d_in[0];
    const float* W1   = (const float*)d_in[1];
    const float* a1_l = (const float*)d_in[2];
    const float* a1_r = (const float*)d_in[3];
    const float* W2   = (const float*)d_in[4];
    const float* a2_l = (const float*)d_in[5];
    const float* a2_r = (const float*)d_in[6];
    const int*   adj  = (const int*)d_in[7];
    float* out = (float*)d_out;

    float* gp1 = nullptr; float* h1 = nullptr; float* gp2 = nullptr;
    cudaGetSymbolAddress((void**)&gp1, g_gp1);
    cudaGetSymbolAddress((void**)&h1, g_h1);
    cudaGetSymbolAddress((void**)&gp2, g_gp2);

    pack_adj_kernel<<<N_NODES, 256>>>(adj);
    gemm_kernel<<<dim3(HID / 128, N_NODES / 128, KS1), 256>>>(
        x, W1, gp1, N_NODES, HID, IN_F / KS1, IN_F);
    elr1_kernel<<<N_NODES, 256>>>(a1_l, a1_r);
    agg1_kernel<<<dim3(H1 * JSPLIT1, N_NODES / 256), 256>>>();
    reduce1_kernel<<<N_NODES, 256>>>();
    gemm_kernel<<<dim3(OUT_F / 128, N_NODES / 128, KS2), 256>>>(
        h1, W2, gp2, N_NODES, OUT_F, HID / KS2, HID);
    elr2_kernel<<<N_NODES, 128>>>(a2_l, a2_r);
    agg2_kernel<<<dim3(JSPLIT2, N_NODES / 128), 256>>>();
    reduce2_kernel<<<N_NODES, 128>>>(out);
}

// round 5
// speedup vs baseline: 1.3171x; 1.3171x over previous
#include <cuda_runtime.h>

#define NN     2048
#define IN_F   512
#define HID    256
#define OUT_F  128
#define H1     8
#define NWORDS 64   // NN/32
#define JS1    2    // agg1 j-split
#define JS2    8    // agg2 j-split
#define KS     2    // gemm K-split

typedef unsigned long long ull;
typedef unsigned u32;

__device__ __forceinline__ ull fma2(ull a, ull b, ull c) {
    ull d; asm("fma.rn.f32x2 %0, %1, %2, %3;" : "=l"(d) : "l"(a), "l"(b), "l"(c)); return d;
}
__device__ __forceinline__ ull pack2(float v) {
    ull d; asm("mov.b64 %0, {%1, %1};" : "=l"(d) : "f"(v)); return d;
}
__device__ __forceinline__ void unpack2(ull v, float& lo, float& hi) {
    asm("mov.b64 {%0, %1}, %2;" : "=f"(lo), "=f"(hi) : "l"(v));
}
__device__ __forceinline__ u32 cvt_tf32(float x) {
    u32 u; asm("cvt.rna.tf32.f32 %0, %1;" : "=r"(u) : "f"(x)); return u;
}
__device__ __forceinline__ void mma8(float* d, const u32* a, u32 b0, u32 b1) {
    asm volatile(
        "mma.sync.aligned.m16n8k8.row.col.f32.tf32.tf32.f32 "
        "{%0,%1,%2,%3}, {%4,%5,%6,%7}, {%8,%9}, {%0,%1,%2,%3};"
        : "+f"(d[0]), "+f"(d[1]), "+f"(d[2]), "+f"(d[3])
        : "r"(a[0]), "r"(a[1]), "r"(a[2]), "r"(a[3]), "r"(b0), "r"(b1));
}

// ---------------- scratch ----------------
__device__ __align__(16) float  g_gp1[KS * NN * HID];
__device__ __align__(16) float  g_g1[NN * HID];
__device__ __align__(16) float4 g_eli1[NN * H1];   // {-el, exp(el), exp(0.2el), 0}
__device__ __align__(16) float4 g_ebd1[NN * H1];   // {er, exp(er), exp(0.2er), 0}
__device__ unsigned g_bits[NN * NWORDS];
__device__ __align__(16) float  g_n1[JS1 * NN * HID];
__device__ float  g_d1[JS1 * NN * H1];
__device__ __align__(16) float  g_h1[NN * HID];
__device__ __align__(16) float  g_gp2[KS * NN * OUT_F];
__device__ __align__(16) float  g_g2[NN * OUT_F];
__device__ __align__(16) float4 g_eli2[NN];
__device__ __align__(16) float4 g_ebd2[NN];
__device__ __align__(16) float  g_part[JS2 * NN * OUT_F];
__device__ float  g_psum[JS2 * NN];

// ---------------- pack adjacency ----------------
__global__ void pack_adj_kernel(const int* __restrict__ adj) {
    int i = blockIdx.x;
    int t = threadIdx.x;  // 256
    const int* row = adj + (size_t)i * NN;
#pragma unroll
    for (int k = 0; k < 8; k++) {
        int j = k * 256 + t;
        unsigned b = __ballot_sync(0xffffffffu, row[j] != 0);
        if ((t & 31) == 0) g_bits[i * NWORDS + (j >> 5)] = b;
    }
}

// ---------------- fp32 tiled GEMM (round-3 config), K-split via blockIdx.z ----------------
template <int BM, int BN, int BK>
__global__ __launch_bounds__(256) void gemm_kernel(const float* __restrict__ A,
                                                   const float* __restrict__ B,
                                                   float* __restrict__ C,
                                                   int M, int N, int Klen, int lda) {
    __shared__ float As[BM][BK + 1];
    __shared__ __align__(16) float Bs[BK][BN];
    const float* Ap = A + (size_t)blockIdx.z * Klen;
    const float* Bp = B + (size_t)blockIdx.z * Klen * N;
    float* Cp = C + (size_t)blockIdx.z * M * N;
    int bi = blockIdx.y * BM;
    int bn = blockIdx.x * BN;
    int t = threadIdx.x;
    int tn = (t % (BN / 4)) * 4;
    int ti = (t / (BN / 4)) * 4;
    ull acc2[4][2] = {};
    for (int k0 = 0; k0 < Klen; k0 += BK) {
        for (int e = t; e < BM * BK; e += 256) {
            int i = e / BK, k = e % BK;
            As[i][k] = Ap[(size_t)(bi + i) * lda + k0 + k];
        }
        for (int e = t; e < BK * BN; e += 256) {
            int k = e / BN, n = e % BN;
            Bs[k][n] = Bp[(size_t)(k0 + k) * N + bn + n];
        }
        __syncthreads();
#pragma unroll
        for (int k = 0; k < BK; k++) {
            ulonglong2 b2 = *(const ulonglong2*)&Bs[k][tn];
            ull a0 = pack2(As[ti + 0][k]);
            ull a1 = pack2(As[ti + 1][k]);
            ull a2 = pack2(As[ti + 2][k]);
            ull a3 = pack2(As[ti + 3][k]);
            acc2[0][0] = fma2(a0, b2.x, acc2[0][0]); acc2[0][1] = fma2(a0, b2.y, acc2[0][1]);
            acc2[1][0] = fma2(a1, b2.x, acc2[1][0]); acc2[1][1] = fma2(a1, b2.y, acc2[1][1]);
            acc2[2][0] = fma2(a2, b2.x, acc2[2][0]); acc2[2][1] = fma2(a2, b2.y, acc2[2][1]);
            acc2[3][0] = fma2(a3, b2.x, acc2[3][0]); acc2[3][1] = fma2(a3, b2.y, acc2[3][1]);
        }
        __syncthreads();
    }
#pragma unroll
    for (int r = 0; r < 4; r++) {
        float v0, v1, v2, v3;
        unpack2(acc2[r][0], v0, v1);
        unpack2(acc2[r][1], v2, v3);
        float* dst = Cp + (size_t)(bi + ti + r) * N + bn + tn;
        dst[0] = v0; dst[1] = v1; dst[2] = v2; dst[3] = v3;
    }
}

// ---------------- layer1: add K-partials, el/er exponentials ----------------
__global__ void elr1_kernel(const float* __restrict__ al, const float* __restrict__ ar) {
    int i = blockIdx.x;
    int t = threadIdx.x;  // 256
    float v = g_gp1[(size_t)i * HID + t] + g_gp1[(size_t)(NN + i) * HID + t];
    g_g1[(size_t)i * HID + t] = v;
    float pl = v * al[t & 31];
    float pr = v * ar[t & 31];
#pragma unroll
    for (int o = 16; o; o >>= 1) {
        pl += __shfl_down_sync(0xffffffffu, pl, o);
        pr += __shfl_down_sync(0xffffffffu, pr, o);
    }
    if ((t & 31) == 0) {
        int h = t >> 5;
        g_eli1[i * H1 + h] = make_float4(-pl, __expf(pl), __expf(0.2f * pl), 0.f);
        g_ebd1[i * H1 + h] = make_float4(pr, __expf(pr), __expf(0.2f * pr), 0.f);
    }
}

// ---------------- layer1 aggregation: tf32 mma.sync, A generated in registers ----------------
// Block: 128 i-rows (8 warps x 16), one head, j-range NN/JS1. N=32 feats = 4 n-tiles.
__global__ __launch_bounds__(256) void agg1_mma_kernel() {
    __shared__ float2 S[2][4][4][32];   // [hi/lo][chunk c][k][f ^ (k<<3)] = {g[8c+k], g[8c+k+4]}
    __shared__ __align__(16) float4 ebd_s[32];
    int h = blockIdx.x >> 1;
    int p = blockIdx.x & 1;
    int bi = blockIdx.y * 128;
    int t = threadIdx.x;
    int lane = t & 31, w = t >> 5;
    int g = lane >> 2, tq = lane & 3;
    int iA = bi + w * 16 + g;
    int iB = iA + 8;
    float4 eA = g_eli1[iA * H1 + h];
    float4 eB = g_eli1[iB * H1 + h];

    float acc[4][4] = {};
    float lsA = 0.f, lsB = 0.f;

    int sj = t >> 3, sfq = t & 7;                   // staging roles
    int sc = sj >> 3, sr = sj & 7, sk = sr & 3, ss = sr >> 2;

    int jstart = p * (NN / JS1);
    for (int j0 = jstart; j0 < jstart + NN / JS1; j0 += 32) {
        __syncthreads();
        // stage B: 32 j x 32 f, split hi/lo tf32
        {
            const float4 g4 = *(const float4*)(g_g1 + (size_t)(j0 + sj) * HID + h * 32 + sfq * 4);
#pragma unroll
            for (int i2 = 0; i2 < 4; i2++) {
                float v = (&g4.x)[i2];
                u32 hu = cvt_tf32(v);
                float hf = __uint_as_float(hu);
                u32 lu = cvt_tf32(v - hf);
                int ff = (sfq * 4 + i2) ^ (sk << 3);
                ((float*)&S[0][sc][sk][ff])[ss] = hf;
                ((float*)&S[1][sc][sk][ff])[ss] = __uint_as_float(lu);
            }
            if (t < 32) ebd_s[t] = g_ebd1[(size_t)(j0 + t) * H1 + h];
        }
        __syncthreads();
        unsigned wordA = g_bits[(size_t)iA * NWORDS + (j0 >> 5)];
        unsigned wordB = g_bits[(size_t)iB * NWORDS + (j0 >> 5)];
#pragma unroll
        for (int cc = 0; cc < 4; cc++) {
            int jt = cc * 8 + tq;
            float4 e0 = ebd_s[jt];
            float4 e1 = ebd_s[jt + 4];
            float wA0 = (e0.x > eA.x) ? eA.y * e0.y : eA.z * e0.z;
            float wB0 = (e0.x > eB.x) ? eB.y * e0.y : eB.z * e0.z;
            float wA1 = (e1.x > eA.x) ? eA.y * e1.y : eA.z * e1.z;
            float wB1 = (e1.x > eB.x) ? eB.y * e1.y : eB.z * e1.z;
            wA0 = ((wordA >> jt) & 1u) ? wA0 : 0.f;
            wB0 = ((wordB >> jt) & 1u) ? wB0 : 0.f;
            wA1 = ((wordA >> (jt + 4)) & 1u) ? wA1 : 0.f;
            wB1 = ((wordB >> (jt + 4)) & 1u) ? wB1 : 0.f;
            lsA += wA0 + wA1;
            lsB += wB0 + wB1;
            u32 ah[4], al4[4];
            ah[0] = cvt_tf32(wA0); al4[0] = cvt_tf32(wA0 - __uint_as_float(ah[0]));
            ah[1] = cvt_tf32(wB0); al4[1] = cvt_tf32(wB0 - __uint_as_float(ah[1]));
            ah[2] = cvt_tf32(wA1); al4[2] = cvt_tf32(wA1 - __uint_as_float(ah[2]));
            ah[3] = cvt_tf32(wB1); al4[3] = cvt_tf32(wB1 - __uint_as_float(ah[3]));
#pragma unroll
            for (int nt = 0; nt < 4; nt++) {
                int ff = (nt * 8 + g) ^ (tq << 3);
                float2 bh = S[0][cc][tq][ff];
                float2 bl = S[1][cc][tq][ff];
                u32 bh0 = __float_as_uint(bh.x), bh1 = __float_as_uint(bh.y);
                u32 bl0 = __float_as_uint(bl.x), bl1 = __float_as_uint(bl.y);
                mma8(acc[nt], ah, bh0, bh1);
                mma8(acc[nt], ah, bl0, bl1);
                mma8(acc[nt], al4, bh0, bh1);
            }
        }
    }
    lsA += __shfl_xor_sync(0xffffffffu, lsA, 1);
    lsA += __shfl_xor_sync(0xffffffffu, lsA, 2);
    lsB += __shfl_xor_sync(0xffffffffu, lsB, 1);
    lsB += __shfl_xor_sync(0xffffffffu, lsB, 2);
    size_t rbase = (size_t)p * NN;
    if (tq == 0) {
        g_d1[(rbase + iA) * H1 + h] = lsA;
        g_d1[(rbase + iB) * H1 + h] = lsB;
    }
#pragma unroll
    for (int nt = 0; nt < 4; nt++) {
        int f = h * 32 + nt * 8 + tq * 2;
        *(float2*)(g_n1 + (rbase + iA) * HID + f) = make_float2(acc[nt][0], acc[nt][1]);
        *(float2*)(g_n1 + (rbase + iB) * HID + f) = make_float2(acc[nt][2], acc[nt][3]);
    }
}

// ---------------- layer1 reduce + divide + ELU ----------------
__global__ void reduce1_kernel() {
    int i = blockIdx.x;
    int t = threadIdx.x;  // 256
    int h = t >> 5;
    float num = 0.f, den = 0.f;
#pragma unroll
    for (int p = 0; p < JS1; p++) {
        num += g_n1[((size_t)p * NN + i) * HID + t];
        den += g_d1[(p * NN + i) * H1 + h];
    }
    float o = num / den;
    g_h1[(size_t)i * HID + t] = o > 0.f ? o : expm1f(o);
}

// ---------------- layer2 el/er ----------------
__global__ void elr2_kernel(const float* __restrict__ al, const float* __restrict__ ar) {
    __shared__ float sl[4], sr[4];
    int i = blockIdx.x;
    int t = threadIdx.x;  // 128
    float v = g_gp2[(size_t)i * OUT_F + t] + g_gp2[(size_t)(NN + i) * OUT_F + t];
    g_g2[(size_t)i * OUT_F + t] = v;
    float pl = v * al[t];
    float pr = v * ar[t];
#pragma unroll
    for (int o = 16; o; o >>= 1) {
        pl += __shfl_down_sync(0xffffffffu, pl, o);
        pr += __shfl_down_sync(0xffffffffu, pr, o);
    }
    if ((t & 31) == 0) { sl[t >> 5] = pl; sr[t >> 5] = pr; }
    __syncthreads();
    if (t == 0) {
        float el = sl[0] + sl[1] + sl[2] + sl[3];
        float er = sr[0] + sr[1] + sr[2] + sr[3];
        g_eli2[i] = make_float4(-el, __expf(el), __expf(0.2f * el), 0.f);
        g_ebd2[i] = make_float4(er, __expf(er), __expf(0.2f * er), 0.f);
    }
}

// ---------------- layer2 aggregation: tf32 mma.sync, N=128 = 16 n-tiles ----------------
__global__ __launch_bounds__(256) void agg2_mma_kernel() {
    __shared__ float2 S[2][4][4][128];  // 32KB
    __shared__ __align__(16) float4 ebd_s[32];
    int p = blockIdx.x;
    int bi = blockIdx.y * 128;
    int t = threadIdx.x;
    int lane = t & 31, w = t >> 5;
    int g = lane >> 2, tq = lane & 3;
    int iA = bi + w * 16 + g;
    int iB = iA + 8;
    float4 eA = g_eli2[iA];
    float4 eB = g_eli2[iB];

    float acc[16][4] = {};
    float lsA = 0.f, lsB = 0.f;

    int sj = t >> 3, sfq = t & 7;
    int sc = sj >> 3, sr = sj & 7, sk = sr & 3, ss = sr >> 2;

    int jstart = p * (NN / JS2);
    for (int j0 = jstart; j0 < jstart + NN / JS2; j0 += 32) {
        __syncthreads();
        // stage B: 32 j x 128 f, split hi/lo
#pragma unroll
        for (int fb = 0; fb < 4; fb++) {
            const float4 g4 = *(const float4*)(g_g2 + (size_t)(j0 + sj) * OUT_F + fb * 32 + sfq * 4);
#pragma unroll
            for (int i2 = 0; i2 < 4; i2++) {
                float v = (&g4.x)[i2];
                u32 hu = cvt_tf32(v);
                float hf = __uint_as_float(hu);
                u32 lu = cvt_tf32(v - hf);
                int ff = (fb * 32 + sfq * 4 + i2) ^ (sk << 3);
                ((float*)&S[0][sc][sk][ff])[ss] = hf;
                ((float*)&S[1][sc][sk][ff])[ss] = __uint_as_float(lu);
            }
        }
        if (t < 32) ebd_s[t] = g_ebd2[j0 + t];
        __syncthreads();
        unsigned wordA = g_bits[(size_t)iA * NWORDS + (j0 >> 5)];
        unsigned wordB = g_bits[(size_t)iB * NWORDS + (j0 >> 5)];
#pragma unroll
        for (int cc = 0; cc < 4; cc++) {
            int jt = cc * 8 + tq;
            float4 e0 = ebd_s[jt];
            float4 e1 = ebd_s[jt + 4];
            float wA0 = (e0.x > eA.x) ? eA.y * e0.y : eA.z * e0.z;
            float wB0 = (e0.x > eB.x) ? eB.y * e0.y : eB.z * e0.z;
            float wA1 = (e1.x > eA.x) ? eA.y * e1.y : eA.z * e1.z;
            float wB1 = (e1.x > eB.x) ? eB.y * e1.y : eB.z * e1.z;
            wA0 = ((wordA >> jt) & 1u) ? wA0 : 0.f;
            wB0 = ((wordB >> jt) & 1u) ? wB0 : 0.f;
            wA1 = ((wordA >> (jt + 4)) & 1u) ? wA1 : 0.f;
            wB1 = ((wordB >> (jt + 4)) & 1u) ? wB1 : 0.f;
            lsA += wA0 + wA1;
            lsB += wB0 + wB1;
            u32 ah[4], al4[4];
            ah[0] = cvt_tf32(wA0); al4[0] = cvt_tf32(wA0 - __uint_as_float(ah[0]));
            ah[1] = cvt_tf32(wB0); al4[1] = cvt_tf32(wB0 - __uint_as_float(ah[1]));
            ah[2] = cvt_tf32(wA1); al4[2] = cvt_tf32(wA1 - __uint_as_float(ah[2]));
            ah[3] = cvt_tf32(wB1); al4[3] = cvt_tf32(wB1 - __uint_as_float(ah[3]));
#pragma unroll
            for (int nt = 0; nt < 16; nt++) {
                int ff = (nt * 8 + g) ^ (tq << 3);
                float2 bh = S[0][cc][tq][ff];
                float2 bl = S[1][cc][tq][ff];
                u32 bh0 = __float_as_uint(bh.x), bh1 = __float_as_uint(bh.y);
                u32 bl0 = __float_as_uint(bl.x), bl1 = __float_as_uint(bl.y);
                mma8(acc[nt], ah, bh0, bh1);
                mma8(acc[nt], ah, bl0, bl1);
                mma8(acc[nt], al4, bh0, bh1);
            }
        }
    }
    lsA += __shfl_xor_sync(0xffffffffu, lsA, 1);
    lsA += __shfl_xor_sync(0xffffffffu, lsA, 2);
    lsB += __shfl_xor_sync(0xffffffffu, lsB, 1);
    lsB += __shfl_xor_sync(0xffffffffu, lsB, 2);
    if (tq == 0) {
        g_psum[p * NN + iA] = lsA;
        g_psum[p * NN + iB] = lsB;
    }
    float* pb = g_part + (size_t)p * NN * OUT_F;
#pragma unroll
    for (int nt = 0; nt < 16; nt++) {
        int f = nt * 8 + tq * 2;
        *(float2*)(pb + (size_t)iA * OUT_F + f) = make_float2(acc[nt][0], acc[nt][1]);
        *(float2*)(pb + (size_t)iB * OUT_F + f) = make_float2(acc[nt][2], acc[nt][3]);
    }
}

// ---------------- final reduce + divide ----------------
__global__ void reduce2_kernel(float* __restrict__ out) {
    int i = blockIdx.x;
    int f = threadIdx.x;  // 128
    float num = 0.f, den = 0.f;
#pragma unroll
    for (int p = 0; p < JS2; p++) {
        num += g_part[(size_t)p * NN * OUT_F + (size_t)i * OUT_F + f];
        den += g_psum[p * NN + i];
    }
    out[i * OUT_F + f] = num / den;
}

// ---------------- launch ----------------
extern "C" void kernel_launch(void* const* d_in, const int* in_sizes, int n_in,
                              void* d_out, int out_size) {
    const float* x    = (const float*)d_in[0];
    const float* W1   = (const float*)d_in[1];
    const float* a1_l = (const float*)d_in[2];
    const float* a1_r = (const float*)d_in[3];
    const float* W2   = (const float*)d_in[4];
    const float* a2_l = (const float*)d_in[5];
    const float* a2_r = (const float*)d_in[6];
    const int*   adj  = (const int*)d_in[7];
    float* out = (float*)d_out;

    float* gp1 = nullptr; float* h1 = nullptr; float* gp2 = nullptr;
    cudaGetSymbolAddress((void**)&gp1, g_gp1);
    cudaGetSymbolAddress((void**)&h1, g_h1);
    cudaGetSymbolAddress((void**)&gp2, g_gp2);

    pack_adj_kernel<<<NN, 256>>>(adj);
    gemm_kernel<64, 64, 16><<<dim3(HID / 64, NN / 64, KS), 256>>>(
        x, W1, gp1, NN, HID, IN_F / KS, IN_F);
    elr1_kernel<<<NN, 256>>>(a1_l, a1_r);
    agg1_mma_kernel<<<dim3(H1 * JS1, NN / 128), 256>>>();
    reduce1_kernel<<<NN, 256>>>();
    gemm_kernel<64, 64, 16><<<dim3(OUT_F / 64, NN / 64, KS), 256>>>(
        h1, W2, gp2, NN, OUT_F, HID / KS, HID);
    elr2_kernel<<<NN, 128>>>(a2_l, a2_r);
    agg2_mma_kernel<<<dim3(JS2, NN / 128), 256>>>();
    reduce2_kernel<<<NN, 128>>>(out);
}

// round 6
// speedup vs baseline: 1.4487x; 1.0999x over previous
#include <cuda_runtime.h>

#define NN     2048
#define IN_F   512
#define HID    256
#define OUT_F  128
#define H1     8
#define NWORDS 64   // NN/32
#define JS1    4    // agg1 j-split
#define JS2    16   // agg2 j-split
#define KS     2    // gemm K-split

typedef unsigned long long ull;
typedef unsigned u32;

__device__ __forceinline__ ull fma2(ull a, ull b, ull c) {
    ull d; asm("fma.rn.f32x2 %0, %1, %2, %3;" : "=l"(d) : "l"(a), "l"(b), "l"(c)); return d;
}
__device__ __forceinline__ ull pack2(float v) {
    ull d; asm("mov.b64 %0, {%1, %1};" : "=l"(d) : "f"(v)); return d;
}
__device__ __forceinline__ void unpack2(ull v, float& lo, float& hi) {
    asm("mov.b64 {%0, %1}, %2;" : "=f"(lo), "=f"(hi) : "l"(v));
}
__device__ __forceinline__ u32 cvt_tf32(float x) {
    u32 u; asm("cvt.rna.tf32.f32 %0, %1;" : "=r"(u) : "f"(x)); return u;
}
__device__ __forceinline__ void mma8(float* d, const u32* a, u32 b0, u32 b1) {
    asm volatile(
        "mma.sync.aligned.m16n8k8.row.col.f32.tf32.tf32.f32 "
        "{%0,%1,%2,%3}, {%4,%5,%6,%7}, {%8,%9}, {%0,%1,%2,%3};"
        : "+f"(d[0]), "+f"(d[1]), "+f"(d[2]), "+f"(d[3])
        : "r"(a[0]), "r"(a[1]), "r"(a[2]), "r"(a[3]), "r"(b0), "r"(b1));
}

// ---------------- scratch ----------------
__device__ __align__(16) float  g_gp1[KS * NN * HID];
__device__ __align__(16) float  g_g1[NN * HID];
__device__ __align__(16) float4 g_eli1[NN * H1];   // {-el, exp(el), exp(0.2el), 0}
__device__ __align__(16) float4 g_ebd1[NN * H1];   // {er, exp(er), exp(0.2er), 0}
__device__ unsigned g_bits[NN * NWORDS];
__device__ __align__(16) float  g_n1[JS1 * NN * HID];
__device__ float  g_d1[JS1 * NN * H1];
__device__ __align__(16) float  g_h1[NN * HID];
__device__ __align__(16) float  g_gp2[KS * NN * OUT_F];
__device__ __align__(16) float  g_g2[NN * OUT_F];
__device__ __align__(16) float4 g_eli2[NN];
__device__ __align__(16) float4 g_ebd2[NN];
__device__ __align__(16) float  g_part[JS2 * NN * OUT_F];
__device__ float  g_psum[JS2 * NN];

// ---------------- pack adjacency ----------------
__global__ void pack_adj_kernel(const int* __restrict__ adj) {
    int i = blockIdx.x;
    int t = threadIdx.x;  // 256
    const int* row = adj + (size_t)i * NN;
#pragma unroll
    for (int k = 0; k < 8; k++) {
        int j = k * 256 + t;
        unsigned b = __ballot_sync(0xffffffffu, row[j] != 0);
        if ((t & 31) == 0) g_bits[i * NWORDS + (j >> 5)] = b;
    }
}

// ---------------- fp32 tiled GEMM, K-split via blockIdx.z ----------------
template <int BM, int BN, int BK>
__global__ __launch_bounds__(256) void gemm_kernel(const float* __restrict__ A,
                                                   const float* __restrict__ B,
                                                   float* __restrict__ C,
                                                   int M, int N, int Klen, int lda) {
    __shared__ float As[BM][BK + 1];
    __shared__ __align__(16) float Bs[BK][BN];
    const float* Ap = A + (size_t)blockIdx.z * Klen;
    const float* Bp = B + (size_t)blockIdx.z * Klen * N;
    float* Cp = C + (size_t)blockIdx.z * M * N;
    int bi = blockIdx.y * BM;
    int bn = blockIdx.x * BN;
    int t = threadIdx.x;
    int tn = (t % (BN / 4)) * 4;
    int ti = (t / (BN / 4)) * 4;
    ull acc2[4][2] = {};
    for (int k0 = 0; k0 < Klen; k0 += BK) {
        for (int e = t; e < BM * BK; e += 256) {
            int i = e / BK, k = e % BK;
            As[i][k] = Ap[(size_t)(bi + i) * lda + k0 + k];
        }
        for (int e = t; e < BK * BN; e += 256) {
            int k = e / BN, n = e % BN;
            Bs[k][n] = Bp[(size_t)(k0 + k) * N + bn + n];
        }
        __syncthreads();
#pragma unroll
        for (int k = 0; k < BK; k++) {
            ulonglong2 b2 = *(const ulonglong2*)&Bs[k][tn];
            ull a0 = pack2(As[ti + 0][k]);
            ull a1 = pack2(As[ti + 1][k]);
            ull a2 = pack2(As[ti + 2][k]);
            ull a3 = pack2(As[ti + 3][k]);
            acc2[0][0] = fma2(a0, b2.x, acc2[0][0]); acc2[0][1] = fma2(a0, b2.y, acc2[0][1]);
            acc2[1][0] = fma2(a1, b2.x, acc2[1][0]); acc2[1][1] = fma2(a1, b2.y, acc2[1][1]);
            acc2[2][0] = fma2(a2, b2.x, acc2[2][0]); acc2[2][1] = fma2(a2, b2.y, acc2[2][1]);
            acc2[3][0] = fma2(a3, b2.x, acc2[3][0]); acc2[3][1] = fma2(a3, b2.y, acc2[3][1]);
        }
        __syncthreads();
    }
#pragma unroll
    for (int r = 0; r < 4; r++) {
        float v0, v1, v2, v3;
        unpack2(acc2[r][0], v0, v1);
        unpack2(acc2[r][1], v2, v3);
        float* dst = Cp + (size_t)(bi + ti + r) * N + bn + tn;
        dst[0] = v0; dst[1] = v1; dst[2] = v2; dst[3] = v3;
    }
}

// ---------------- layer1: add K-partials, el/er exponentials ----------------
__global__ void elr1_kernel(const float* __restrict__ al, const float* __restrict__ ar) {
    int i = blockIdx.x;
    int t = threadIdx.x;  // 256
    float v = g_gp1[(size_t)i * HID + t] + g_gp1[(size_t)(NN + i) * HID + t];
    g_g1[(size_t)i * HID + t] = v;
    float pl = v * al[t & 31];
    float pr = v * ar[t & 31];
#pragma unroll
    for (int o = 16; o; o >>= 1) {
        pl += __shfl_down_sync(0xffffffffu, pl, o);
        pr += __shfl_down_sync(0xffffffffu, pr, o);
    }
    if ((t & 31) == 0) {
        int h = t >> 5;
        g_eli1[i * H1 + h] = make_float4(-pl, __expf(pl), __expf(0.2f * pl), 0.f);
        g_ebd1[i * H1 + h] = make_float4(pr, __expf(pr), __expf(0.2f * pr), 0.f);
    }
}

// ---------------- layer1 aggregation: tf32 mma, fragment-exact conflict-free smem ----------------
// S4[cc][k][col] (col = f = nt*8+g, row stride 34) = {bh(j=cc*8+k), bh(j+4), bl(j), bl(j+4)}
__global__ __launch_bounds__(256) void agg1_mma_kernel() {
    __shared__ __align__(16) float4 S4[4][4][34];   // 8.5KB
    __shared__ __align__(16) float4 ebd_s[32];
    int h = blockIdx.x >> 2;
    int p = blockIdx.x & 3;
    int bi = blockIdx.y * 128;
    int t = threadIdx.x;
    int lane = t & 31, w = t >> 5;
    int g = lane >> 2, tq = lane & 3;
    int iA = bi + w * 16 + g;
    int iB = iA + 8;
    float4 eA = g_eli1[iA * H1 + h];
    float4 eB = g_eli1[iB * H1 + h];
    float acc[4][4] = {};
    float lsA = 0.f, lsB = 0.f;

    int sk = t & 3, sf = (t >> 2) & 31, sc2 = (t >> 7) * 2;

    int jstart = p * (NN / JS1);
    for (int j0 = jstart; j0 < jstart + NN / JS1; j0 += 32) {
        __syncthreads();
        // stage fragment words: 2 global loads + 4 cvt + 1 STS.128 each
#pragma unroll
        for (int c2 = 0; c2 < 2; c2++) {
            int cc = sc2 + c2;
            const float* src = g_g1 + (size_t)(j0 + cc * 8 + sk) * HID + h * 32 + sf;
            float v0 = src[0];
            float v1 = src[4 * HID];
            u32 h0 = cvt_tf32(v0); float h0f = __uint_as_float(h0);
            u32 h1 = cvt_tf32(v1); float h1f = __uint_as_float(h1);
            u32 l0 = cvt_tf32(v0 - h0f);
            u32 l1 = cvt_tf32(v1 - h1f);
            S4[cc][sk][sf] = make_float4(h0f, h1f, __uint_as_float(l0), __uint_as_float(l1));
        }
        if (t < 32) ebd_s[t] = g_ebd1[(size_t)(j0 + t) * H1 + h];
        __syncthreads();
        unsigned wordA = g_bits[(size_t)iA * NWORDS + (j0 >> 5)];
        unsigned wordB = g_bits[(size_t)iB * NWORDS + (j0 >> 5)];
#pragma unroll
        for (int cc = 0; cc < 4; cc++) {
            int jt = cc * 8 + tq;
            float4 e0 = ebd_s[jt];
            float4 e1 = ebd_s[jt + 4];
            float wA0 = (e0.x > eA.x) ? eA.y * e0.y : eA.z * e0.z;
            float wB0 = (e0.x > eB.x) ? eB.y * e0.y : eB.z * e0.z;
            float wA1 = (e1.x > eA.x) ? eA.y * e1.y : eA.z * e1.z;
            float wB1 = (e1.x > eB.x) ? eB.y * e1.y : eB.z * e1.z;
            wA0 = ((wordA >> jt) & 1u) ? wA0 : 0.f;
            wB0 = ((wordB >> jt) & 1u) ? wB0 : 0.f;
            wA1 = ((wordA >> (jt + 4)) & 1u) ? wA1 : 0.f;
            wB1 = ((wordB >> (jt + 4)) & 1u) ? wB1 : 0.f;
            lsA += wA0 + wA1;
            lsB += wB0 + wB1;
            u32 ah[4], al4[4];
            ah[0] = cvt_tf32(wA0); al4[0] = cvt_tf32(wA0 - __uint_as_float(ah[0]));
            ah[1] = cvt_tf32(wB0); al4[1] = cvt_tf32(wB0 - __uint_as_float(ah[1]));
            ah[2] = cvt_tf32(wA1); al4[2] = cvt_tf32(wA1 - __uint_as_float(ah[2]));
            ah[3] = cvt_tf32(wB1); al4[3] = cvt_tf32(wB1 - __uint_as_float(ah[3]));
#pragma unroll
            for (int nt = 0; nt < 4; nt++) {
                float4 b = S4[cc][tq][nt * 8 + g];
                u32 bh0 = __float_as_uint(b.x), bh1 = __float_as_uint(b.y);
                u32 bl0 = __float_as_uint(b.z), bl1 = __float_as_uint(b.w);
                mma8(acc[nt], ah, bh0, bh1);
                mma8(acc[nt], ah, bl0, bl1);
                mma8(acc[nt], al4, bh0, bh1);
            }
        }
    }
    lsA += __shfl_xor_sync(0xffffffffu, lsA, 1);
    lsA += __shfl_xor_sync(0xffffffffu, lsA, 2);
    lsB += __shfl_xor_sync(0xffffffffu, lsB, 1);
    lsB += __shfl_xor_sync(0xffffffffu, lsB, 2);
    size_t rbase = (size_t)p * NN;
    if (tq == 0) {
        g_d1[(rbase + iA) * H1 + h] = lsA;
        g_d1[(rbase + iB) * H1 + h] = lsB;
    }
#pragma unroll
    for (int nt = 0; nt < 4; nt++) {
        int f = h * 32 + nt * 8 + tq * 2;
        *(float2*)(g_n1 + (rbase + iA) * HID + f) = make_float2(acc[nt][0], acc[nt][1]);
        *(float2*)(g_n1 + (rbase + iB) * HID + f) = make_float2(acc[nt][2], acc[nt][3]);
    }
}

// ---------------- layer1 reduce + divide + ELU ----------------
__global__ void reduce1_kernel() {
    int i = blockIdx.x;
    int t = threadIdx.x;  // 256
    int h = t >> 5;
    float num = 0.f, den = 0.f;
#pragma unroll
    for (int p = 0; p < JS1; p++) {
        num += g_n1[((size_t)p * NN + i) * HID + t];
        den += g_d1[(p * NN + i) * H1 + h];
    }
    float o = num / den;
    g_h1[(size_t)i * HID + t] = o > 0.f ? o : expm1f(o);
}

// ---------------- layer2 el/er ----------------
__global__ void elr2_kernel(const float* __restrict__ al, const float* __restrict__ ar) {
    __shared__ float sl[4], sr[4];
    int i = blockIdx.x;
    int t = threadIdx.x;  // 128
    float v = g_gp2[(size_t)i * OUT_F + t] + g_gp2[(size_t)(NN + i) * OUT_F + t];
    g_g2[(size_t)i * OUT_F + t] = v;
    float pl = v * al[t];
    float pr = v * ar[t];
#pragma unroll
    for (int o = 16; o; o >>= 1) {
        pl += __shfl_down_sync(0xffffffffu, pl, o);
        pr += __shfl_down_sync(0xffffffffu, pr, o);
    }
    if ((t & 31) == 0) { sl[t >> 5] = pl; sr[t >> 5] = pr; }
    __syncthreads();
    if (t == 0) {
        float el = sl[0] + sl[1] + sl[2] + sl[3];
        float er = sr[0] + sr[1] + sr[2] + sr[3];
        g_eli2[i] = make_float4(-el, __expf(el), __expf(0.2f * el), 0.f);
        g_ebd2[i] = make_float4(er, __expf(er), __expf(0.2f * er), 0.f);
    }
}

// ---------------- layer2 aggregation: tf32 mma, 16 n-tiles ----------------
__global__ __launch_bounds__(256) void agg2_mma_kernel() {
    __shared__ __align__(16) float4 S4[4][4][130];  // 33.3KB
    __shared__ __align__(16) float4 ebd_s[32];
    int p = blockIdx.x;
    int bi = blockIdx.y * 128;
    int t = threadIdx.x;
    int lane = t & 31, w = t >> 5;
    int g = lane >> 2, tq = lane & 3;
    int iA = bi + w * 16 + g;
    int iB = iA + 8;
    float4 eA = g_eli2[iA];
    float4 eB = g_eli2[iB];
    float acc[16][4] = {};
    float lsA = 0.f, lsB = 0.f;

    int sk = t & 3, sf = (t >> 2) & 31, sc2 = (t >> 7) * 2;

    int jstart = p * (NN / JS2);
    for (int j0 = jstart; j0 < jstart + NN / JS2; j0 += 32) {
        __syncthreads();
#pragma unroll
        for (int c2 = 0; c2 < 2; c2++) {
            int cc = sc2 + c2;
            const float* src = g_g2 + (size_t)(j0 + cc * 8 + sk) * OUT_F + sf;
#pragma unroll
            for (int fb = 0; fb < 4; fb++) {
                float v0 = src[fb * 32];
                float v1 = src[4 * OUT_F + fb * 32];
                u32 h0 = cvt_tf32(v0); float h0f = __uint_as_float(h0);
                u32 h1 = cvt_tf32(v1); float h1f = __uint_as_float(h1);
                u32 l0 = cvt_tf32(v0 - h0f);
                u32 l1 = cvt_tf32(v1 - h1f);
                S4[cc][sk][fb * 32 + sf] =
                    make_float4(h0f, h1f, __uint_as_float(l0), __uint_as_float(l1));
            }
        }
        if (t < 32) ebd_s[t] = g_ebd2[j0 + t];
        __syncthreads();
        unsigned wordA = g_bits[(size_t)iA * NWORDS + (j0 >> 5)];
        unsigned wordB = g_bits[(size_t)iB * NWORDS + (j0 >> 5)];
#pragma unroll
        for (int cc = 0; cc < 4; cc++) {
            int jt = cc * 8 + tq;
            float4 e0 = ebd_s[jt];
            float4 e1 = ebd_s[jt + 4];
            float wA0 = (e0.x > eA.x) ? eA.y * e0.y : eA.z * e0.z;
            float wB0 = (e0.x > eB.x) ? eB.y * e0.y : eB.z * e0.z;
            float wA1 = (e1.x > eA.x) ? eA.y * e1.y : eA.z * e1.z;
            float wB1 = (e1.x > eB.x) ? eB.y * e1.y : eB.z * e1.z;
            wA0 = ((wordA >> jt) & 1u) ? wA0 : 0.f;
            wB0 = ((wordB >> jt) & 1u) ? wB0 : 0.f;
            wA1 = ((wordA >> (jt + 4)) & 1u) ? wA1 : 0.f;
            wB1 = ((wordB >> (jt + 4)) & 1u) ? wB1 : 0.f;
            lsA += wA0 + wA1;
            lsB += wB0 + wB1;
            u32 ah[4], al4[4];
            ah[0] = cvt_tf32(wA0); al4[0] = cvt_tf32(wA0 - __uint_as_float(ah[0]));
            ah[1] = cvt_tf32(wB0); al4[1] = cvt_tf32(wB0 - __uint_as_float(ah[1]));
            ah[2] = cvt_tf32(wA1); al4[2] = cvt_tf32(wA1 - __uint_as_float(ah[2]));
            ah[3] = cvt_tf32(wB1); al4[3] = cvt_tf32(wB1 - __uint_as_float(ah[3]));
#pragma unroll
            for (int nt = 0; nt < 16; nt++) {
                float4 b = S4[cc][tq][nt * 8 + g];
                u32 bh0 = __float_as_uint(b.x), bh1 = __float_as_uint(b.y);
                u32 bl0 = __float_as_uint(b.z), bl1 = __float_as_uint(b.w);
                mma8(acc[nt], ah, bh0, bh1);
                mma8(acc[nt], ah, bl0, bl1);
                mma8(acc[nt], al4, bh0, bh1);
            }
        }
    }
    lsA += __shfl_xor_sync(0xffffffffu, lsA, 1);
    lsA += __shfl_xor_sync(0xffffffffu, lsA, 2);
    lsB += __shfl_xor_sync(0xffffffffu, lsB, 1);
    lsB += __shfl_xor_sync(0xffffffffu, lsB, 2);
    if (tq == 0) {
        g_psum[p * NN + iA] = lsA;
        g_psum[p * NN + iB] = lsB;
    }
    float* pb = g_part + (size_t)p * NN * OUT_F;
#pragma unroll
    for (int nt = 0; nt < 16; nt++) {
        int f = nt * 8 + tq * 2;
        *(float2*)(pb + (size_t)iA * OUT_F + f) = make_float2(acc[nt][0], acc[nt][1]);
        *(float2*)(pb + (size_t)iB * OUT_F + f) = make_float2(acc[nt][2], acc[nt][3]);
    }
}

// ---------------- final reduce + divide ----------------
__global__ void reduce2_kernel(float* __restrict__ out) {
    int i = blockIdx.x;
    int f = threadIdx.x;  // 128
    float num = 0.f, den = 0.f;
#pragma unroll
    for (int p = 0; p < JS2; p++) {
        num += g_part[(size_t)p * NN * OUT_F + (size_t)i * OUT_F + f];
        den += g_psum[p * NN + i];
    }
    out[i * OUT_F + f] = num / den;
}

// ---------------- launch ----------------
extern "C" void kernel_launch(void* const* d_in, const int* in_sizes, int n_in,
                              void* d_out, int out_size) {
    const float* x    = (const float*)d_in[0];
    const float* W1   = (const float*)d_in[1];
    const float* a1_l = (const float*)d_in[2];
    const float* a1_r = (const float*)d_in[3];
    const float* W2   = (const float*)d_in[4];
    const float* a2_l = (const float*)d_in[5];
    const float* a2_r = (const float*)d_in[6];
    const int*   adj  = (const int*)d_in[7];
    float* out = (float*)d_out;

    float* gp1 = nullptr; float* h1 = nullptr; float* gp2 = nullptr;
    cudaGetSymbolAddress((void**)&gp1, g_gp1);
    cudaGetSymbolAddress((void**)&h1, g_h1);
    cudaGetSymbolAddress((void**)&gp2, g_gp2);

    pack_adj_kernel<<<NN, 256>>>(adj);
    gemm_kernel<64, 64, 16><<<dim3(HID / 64, NN / 64, KS), 256>>>(
        x, W1, gp1, NN, HID, IN_F / KS, IN_F);
    elr1_kernel<<<NN, 256>>>(a1_l, a1_r);
    agg1_mma_kernel<<<dim3(H1 * JS1, NN / 128), 256>>>();
    reduce1_kernel<<<NN, 256>>>();
    gemm_kernel<64, 64, 16><<<dim3(OUT_F / 64, NN / 64, KS), 256>>>(
        h1, W2, gp2, NN, OUT_F, HID / KS, HID);
    elr2_kernel<<<NN, 128>>>(a2_l, a2_r);
    agg2_mma_kernel<<<dim3(JS2, NN / 128), 256>>>();
    reduce2_kernel<<<NN, 128>>>(out);
}

// round 7
// speedup vs baseline: 1.4644x; 1.0108x over previous
#include <cuda_runtime.h>

#define NN     2048
#define IN_F   512
#define HID    256
#define OUT_F  128
#define H1     8
#define NWORDS 64   // NN/32
#define JS1    4    // agg1 j-split
#define JS2    16   // agg2 j-split
#define KS     2    // gemm K-split

typedef unsigned long long ull;
typedef unsigned u32;

__device__ __forceinline__ ull fma2(ull a, ull b, ull c) {
    ull d; asm("fma.rn.f32x2 %0, %1, %2, %3;" : "=l"(d) : "l"(a), "l"(b), "l"(c)); return d;
}
__device__ __forceinline__ ull pack2(float v) {
    ull d; asm("mov.b64 %0, {%1, %1};" : "=l"(d) : "f"(v)); return d;
}
__device__ __forceinline__ void unpack2(ull v, float& lo, float& hi) {
    asm("mov.b64 {%0, %1}, %2;" : "=f"(lo), "=f"(hi) : "l"(v));
}
__device__ __forceinline__ u32 cvt_tf32(float x) {
    u32 u; asm("cvt.rna.tf32.f32 %0, %1;" : "=r"(u) : "f"(x)); return u;
}
__device__ __forceinline__ void mma8(float* d, const u32* a, u32 b0, u32 b1) {
    asm volatile(
        "mma.sync.aligned.m16n8k8.row.col.f32.tf32.tf32.f32 "
        "{%0,%1,%2,%3}, {%4,%5,%6,%7}, {%8,%9}, {%0,%1,%2,%3};"
        : "+f"(d[0]), "+f"(d[1]), "+f"(d[2]), "+f"(d[3])
        : "r"(a[0]), "r"(a[1]), "r"(a[2]), "r"(a[3]), "r"(b0), "r"(b1));
}
__device__ __forceinline__ void cpa16(u32 s, const void* g) {
    asm volatile("cp.async.ca.shared.global [%0], [%1], 16;" :: "r"(s), "l"(g));
}
#define CP_COMMIT asm volatile("cp.async.commit_group;")
#define CP_WAIT1  asm volatile("cp.async.wait_group 1;")
#define CP_WAIT0  asm volatile("cp.async.wait_group 0;")

// ---------------- scratch ----------------
__device__ __align__(16) float  g_gp1[KS * NN * HID];
__device__ __align__(16) float  g_g1[NN * HID];
__device__ __align__(16) float4 g_eli1t[H1 * NN];   // [h][i] {-el, exp(el), exp(0.2el), 0}
__device__ __align__(16) float4 g_ebd1t[H1 * NN];   // [h][j] {er, exp(er), exp(0.2er), 0}
__device__ __align__(16) float4 g_frag1[H1 * (NN / 8) * 4 * 32];   // 4MB fragment-ready g1
__device__ unsigned g_bits[NN * NWORDS];
__device__ __align__(16) float  g_n1[JS1 * NN * HID];
__device__ float  g_d1[JS1 * NN * H1];
__device__ __align__(16) float  g_h1[NN * HID];
__device__ __align__(16) float  g_gp2[KS * NN * OUT_F];
__device__ __align__(16) float  g_g2[NN * OUT_F];
__device__ __align__(16) float4 g_eli2[NN];
__device__ __align__(16) float4 g_ebd2[NN];
__device__ __align__(16) float4 g_frag2[(NN / 8) * 4 * OUT_F];     // 2MB fragment-ready g2
__device__ __align__(16) float  g_part[JS2 * NN * OUT_F];
__device__ float  g_psum[JS2 * NN];

// ---------------- pack adjacency ----------------
__global__ void pack_adj_kernel(const int* __restrict__ adj) {
    int i = blockIdx.x;
    int t = threadIdx.x;  // 256
    const int* row = adj + (size_t)i * NN;
#pragma unroll
    for (int k = 0; k < 8; k++) {
        int j = k * 256 + t;
        unsigned b = __ballot_sync(0xffffffffu, row[j] != 0);
        if ((t & 31) == 0) g_bits[i * NWORDS + (j >> 5)] = b;
    }
}

// ---------------- fp32 tiled GEMM, K-split via blockIdx.z ----------------
template <int BM, int BN, int BK>
__global__ __launch_bounds__(256) void gemm_kernel(const float* __restrict__ A,
                                                   const float* __restrict__ B,
                                                   float* __restrict__ C,
                                                   int M, int N, int Klen, int lda) {
    __shared__ float As[BM][BK + 1];
    __shared__ __align__(16) float Bs[BK][BN];
    const float* Ap = A + (size_t)blockIdx.z * Klen;
    const float* Bp = B + (size_t)blockIdx.z * Klen * N;
    float* Cp = C + (size_t)blockIdx.z * M * N;
    int bi = blockIdx.y * BM;
    int bn = blockIdx.x * BN;
    int t = threadIdx.x;
    int tn = (t % (BN / 4)) * 4;
    int ti = (t / (BN / 4)) * 4;
    ull acc2[4][2] = {};
    for (int k0 = 0; k0 < Klen; k0 += BK) {
        for (int e = t; e < BM * BK; e += 256) {
            int i = e / BK, k = e % BK;
            As[i][k] = Ap[(size_t)(bi + i) * lda + k0 + k];
        }
        for (int e = t; e < BK * BN; e += 256) {
            int k = e / BN, n = e % BN;
            Bs[k][n] = Bp[(size_t)(k0 + k) * N + bn + n];
        }
        __syncthreads();
#pragma unroll
        for (int k = 0; k < BK; k++) {
            ulonglong2 b2 = *(const ulonglong2*)&Bs[k][tn];
            ull a0 = pack2(As[ti + 0][k]);
            ull a1 = pack2(As[ti + 1][k]);
            ull a2 = pack2(As[ti + 2][k]);
            ull a3 = pack2(As[ti + 3][k]);
            acc2[0][0] = fma2(a0, b2.x, acc2[0][0]); acc2[0][1] = fma2(a0, b2.y, acc2[0][1]);
            acc2[1][0] = fma2(a1, b2.x, acc2[1][0]); acc2[1][1] = fma2(a1, b2.y, acc2[1][1]);
            acc2[2][0] = fma2(a2, b2.x, acc2[2][0]); acc2[2][1] = fma2(a2, b2.y, acc2[2][1]);
            acc2[3][0] = fma2(a3, b2.x, acc2[3][0]); acc2[3][1] = fma2(a3, b2.y, acc2[3][1]);
        }
        __syncthreads();
    }
#pragma unroll
    for (int r = 0; r < 4; r++) {
        float v0, v1, v2, v3;
        unpack2(acc2[r][0], v0, v1);
        unpack2(acc2[r][1], v2, v3);
        float* dst = Cp + (size_t)(bi + ti + r) * N + bn + tn;
        dst[0] = v0; dst[1] = v1; dst[2] = v2; dst[3] = v3;
    }
}

// ---------------- layer1: add K-partials, el/er exponentials (transposed out) ----------------
__global__ void elr1_kernel(const float* __restrict__ al, const float* __restrict__ ar) {
    int i = blockIdx.x;
    int t = threadIdx.x;  // 256
    float v = g_gp1[(size_t)i * HID + t] + g_gp1[(size_t)(NN + i) * HID + t];
    g_g1[(size_t)i * HID + t] = v;
    float pl = v * al[t & 31];
    float pr = v * ar[t & 31];
#pragma unroll
    for (int o = 16; o; o >>= 1) {
        pl += __shfl_down_sync(0xffffffffu, pl, o);
        pr += __shfl_down_sync(0xffffffffu, pr, o);
    }
    if ((t & 31) == 0) {
        int h = t >> 5;
        g_eli1t[h * NN + i] = make_float4(-pl, __expf(pl), __expf(0.2f * pl), 0.f);
        g_ebd1t[h * NN + i] = make_float4(pr, __expf(pr), __expf(0.2f * pr), 0.f);
    }
}

// ---------------- prep1: tf32 hi/lo fragment tensor for g1 ----------------
// g_frag1[((h*256 + jb)*4 + k)*32 + f] = {hi(g[8jb+k][h*32+f]), hi(g[8jb+k+4][..]), lo0, lo1}
__global__ void prep1_kernel() {
    int idx = blockIdx.x * 256 + threadIdx.x;   // < 262144
    int f = idx & 31, k = (idx >> 5) & 3, jb = (idx >> 7) & 255, h = idx >> 15;
    int j = jb * 8 + k;
    float v0 = g_g1[(size_t)j * HID + h * 32 + f];
    float v1 = g_g1[(size_t)(j + 4) * HID + h * 32 + f];
    u32 h0 = cvt_tf32(v0); float h0f = __uint_as_float(h0);
    u32 h1 = cvt_tf32(v1); float h1f = __uint_as_float(h1);
    u32 l0 = cvt_tf32(v0 - h0f);
    u32 l1 = cvt_tf32(v1 - h1f);
    g_frag1[idx] = make_float4(h0f, h1f, __uint_as_float(l0), __uint_as_float(l1));
}

// ---------------- layer1 aggregation: tf32 mma + cp.async double buffer ----------------
__global__ __launch_bounds__(256) void agg1_mma_kernel() {
    __shared__ __align__(16) float4 S4[2][4][4][34];   // 17.4KB
    __shared__ __align__(16) float4 ebd_s[2][32];
    int h = blockIdx.x >> 2;
    int p = blockIdx.x & 3;
    int bi = blockIdx.y * 128;
    int t = threadIdx.x;
    int lane = t & 31, w = t >> 5;
    int g = lane >> 2, tq = lane & 3;
    int iA = bi + w * 16 + g;
    int iB = iA + 8;
    float4 eA = g_eli1t[h * NN + iA];
    float4 eB = g_eli1t[h * NN + iB];
    float acc[4][4] = {};
    float lsA = 0.f, lsB = 0.f;

    const float4* fb = g_frag1 + (size_t)h * 256 * 4 * 32;
    int e0i = t, e1i = t + 256;  // staging entries
    int cc0 = e0i >> 7, k0 = (e0i >> 5) & 3, f0 = e0i & 31;
    int cc1 = e1i >> 7, k1 = (e1i >> 5) & 3, f1 = e1i & 31;

    int jstart = p * (NN / JS1);
    const int NC = (NN / JS1) / 32;  // 16

    // stage(b, j0)
#define STAGE1(b, j0) do { \
        int jb0 = (j0) >> 3; \
        cpa16((u32)__cvta_generic_to_shared(&S4[b][cc0][k0][f0]), fb + ((size_t)(jb0 + cc0) * 4 + k0) * 32 + f0); \
        cpa16((u32)__cvta_generic_to_shared(&S4[b][cc1][k1][f1]), fb + ((size_t)(jb0 + cc1) * 4 + k1) * 32 + f1); \
        if (t < 32) cpa16((u32)__cvta_generic_to_shared(&ebd_s[b][t]), g_ebd1t + h * NN + (j0) + t); \
    } while (0)

    STAGE1(0, jstart);
    CP_COMMIT;
    for (int c = 0; c < NC; c++) {
        int b = c & 1;
        if (c + 1 < NC) {
            STAGE1(b ^ 1, jstart + (c + 1) * 32);
            CP_COMMIT;
            CP_WAIT1;
        } else {
            CP_WAIT0;
        }
        __syncthreads();
        int j0 = jstart + c * 32;
        unsigned wordA = g_bits[(size_t)iA * NWORDS + (j0 >> 5)];
        unsigned wordB = g_bits[(size_t)iB * NWORDS + (j0 >> 5)];
#pragma unroll
        for (int cc = 0; cc < 4; cc++) {
            int jt = cc * 8 + tq;
            float4 e0 = ebd_s[b][jt];
            float4 e1 = ebd_s[b][jt + 4];
            float wA0 = (e0.x > eA.x) ? eA.y * e0.y : eA.z * e0.z;
            float wB0 = (e0.x > eB.x) ? eB.y * e0.y : eB.z * e0.z;
            float wA1 = (e1.x > eA.x) ? eA.y * e1.y : eA.z * e1.z;
            float wB1 = (e1.x > eB.x) ? eB.y * e1.y : eB.z * e1.z;
            wA0 = ((wordA >> jt) & 1u) ? wA0 : 0.f;
            wB0 = ((wordB >> jt) & 1u) ? wB0 : 0.f;
            wA1 = ((wordA >> (jt + 4)) & 1u) ? wA1 : 0.f;
            wB1 = ((wordB >> (jt + 4)) & 1u) ? wB1 : 0.f;
            lsA += wA0 + wA1;
            lsB += wB0 + wB1;
            u32 ah[4], al4[4];
            ah[0] = cvt_tf32(wA0); al4[0] = cvt_tf32(wA0 - __uint_as_float(ah[0]));
            ah[1] = cvt_tf32(wB0); al4[1] = cvt_tf32(wB0 - __uint_as_float(ah[1]));
            ah[2] = cvt_tf32(wA1); al4[2] = cvt_tf32(wA1 - __uint_as_float(ah[2]));
            ah[3] = cvt_tf32(wB1); al4[3] = cvt_tf32(wB1 - __uint_as_float(ah[3]));
#pragma unroll
            for (int nt = 0; nt < 4; nt++) {
                float4 bfr = S4[b][cc][tq][nt * 8 + g];
                u32 bh0 = __float_as_uint(bfr.x), bh1 = __float_as_uint(bfr.y);
                u32 bl0 = __float_as_uint(bfr.z), bl1 = __float_as_uint(bfr.w);
                mma8(acc[nt], ah, bh0, bh1);
                mma8(acc[nt], ah, bl0, bl1);
                mma8(acc[nt], al4, bh0, bh1);
            }
        }
        __syncthreads();
    }
    lsA += __shfl_xor_sync(0xffffffffu, lsA, 1);
    lsA += __shfl_xor_sync(0xffffffffu, lsA, 2);
    lsB += __shfl_xor_sync(0xffffffffu, lsB, 1);
    lsB += __shfl_xor_sync(0xffffffffu, lsB, 2);
    size_t rbase = (size_t)p * NN;
    if (tq == 0) {
        g_d1[(rbase + iA) * H1 + h] = lsA;
        g_d1[(rbase + iB) * H1 + h] = lsB;
    }
#pragma unroll
    for (int nt = 0; nt < 4; nt++) {
        int f = h * 32 + nt * 8 + tq * 2;
        *(float2*)(g_n1 + (rbase + iA) * HID + f) = make_float2(acc[nt][0], acc[nt][1]);
        *(float2*)(g_n1 + (rbase + iB) * HID + f) = make_float2(acc[nt][2], acc[nt][3]);
    }
}

// ---------------- layer1 reduce + divide + ELU ----------------
__global__ void reduce1_kernel() {
    int i = blockIdx.x;
    int t = threadIdx.x;  // 256
    int h = t >> 5;
    float num = 0.f, den = 0.f;
#pragma unroll
    for (int p = 0; p < JS1; p++) {
        num += g_n1[((size_t)p * NN + i) * HID + t];
        den += g_d1[(p * NN + i) * H1 + h];
    }
    float o = num / den;
    g_h1[(size_t)i * HID + t] = o > 0.f ? o : expm1f(o);
}

// ---------------- layer2 el/er ----------------
__global__ void elr2_kernel(const float* __restrict__ al, const float* __restrict__ ar) {
    __shared__ float sl[4], sr[4];
    int i = blockIdx.x;
    int t = threadIdx.x;  // 128
    float v = g_gp2[(size_t)i * OUT_F + t] + g_gp2[(size_t)(NN + i) * OUT_F + t];
    g_g2[(size_t)i * OUT_F + t] = v;
    float pl = v * al[t];
    float pr = v * ar[t];
#pragma unroll
    for (int o = 16; o; o >>= 1) {
        pl += __shfl_down_sync(0xffffffffu, pl, o);
        pr += __shfl_down_sync(0xffffffffu, pr, o);
    }
    if ((t & 31) == 0) { sl[t >> 5] = pl; sr[t >> 5] = pr; }
    __syncthreads();
    if (t == 0) {
        float el = sl[0] + sl[1] + sl[2] + sl[3];
        float er = sr[0] + sr[1] + sr[2] + sr[3];
        g_eli2[i] = make_float4(-el, __expf(el), __expf(0.2f * el), 0.f);
        g_ebd2[i] = make_float4(er, __expf(er), __expf(0.2f * er), 0.f);
    }
}

// ---------------- prep2 ----------------
__global__ void prep2_kernel() {
    int idx = blockIdx.x * 256 + threadIdx.x;   // < 131072
    int f = idx & 127, k = (idx >> 7) & 3, jb = idx >> 9;
    int j = jb * 8 + k;
    float v0 = g_g2[(size_t)j * OUT_F + f];
    float v1 = g_g2[(size_t)(j + 4) * OUT_F + f];
    u32 h0 = cvt_tf32(v0); float h0f = __uint_as_float(h0);
    u32 h1 = cvt_tf32(v1); float h1f = __uint_as_float(h1);
    u32 l0 = cvt_tf32(v0 - h0f);
    u32 l1 = cvt_tf32(v1 - h1f);
    g_frag2[idx] = make_float4(h0f, h1f, __uint_as_float(l0), __uint_as_float(l1));
}

// ---------------- layer2 aggregation: tf32 mma + cp.async double buffer (16-j chunks) ----------------
__global__ __launch_bounds__(256) void agg2_mma_kernel() {
    __shared__ __align__(16) float4 S4[2][2][4][130];  // 33.3KB
    __shared__ __align__(16) float4 ebd_s[2][16];
    int p = blockIdx.x;
    int bi = blockIdx.y * 128;
    int t = threadIdx.x;
    int lane = t & 31, w = t >> 5;
    int g = lane >> 2, tq = lane & 3;
    int iA = bi + w * 16 + g;
    int iB = iA + 8;
    float4 eA = g_eli2[iA];
    float4 eB = g_eli2[iB];
    float acc[16][4] = {};
    float lsA = 0.f, lsB = 0.f;

    int jstart = p * (NN / JS2);   // 128 j per block
    const int NC = (NN / JS2) / 16;  // 8

#define STAGE2(b, j0) do { \
        int jb0 = (j0) >> 3; \
        _Pragma("unroll") \
        for (int e = t; e < 1024; e += 256) { \
            int cc = e >> 9, k = (e >> 7) & 3, f = e & 127; \
            cpa16((u32)__cvta_generic_to_shared(&S4[b][cc][k][f]), \
                  g_frag2 + ((size_t)(jb0 + cc) * 4 + k) * 128 + f); \
        } \
        if (t < 16) cpa16((u32)__cvta_generic_to_shared(&ebd_s[b][t]), g_ebd2 + (j0) + t); \
    } while (0)

    STAGE2(0, jstart);
    CP_COMMIT;
    for (int c = 0; c < NC; c++) {
        int b = c & 1;
        if (c + 1 < NC) {
            STAGE2(b ^ 1, jstart + (c + 1) * 16);
            CP_COMMIT;
            CP_WAIT1;
        } else {
            CP_WAIT0;
        }
        __syncthreads();
        int j0 = jstart + c * 16;
        unsigned wordA = g_bits[(size_t)iA * NWORDS + (j0 >> 5)] >> (j0 & 31);
        unsigned wordB = g_bits[(size_t)iB * NWORDS + (j0 >> 5)] >> (j0 & 31);
#pragma unroll
        for (int cc = 0; cc < 2; cc++) {
            int jt = cc * 8 + tq;
            float4 e0 = ebd_s[b][jt];
            float4 e1 = ebd_s[b][jt + 4];
            float wA0 = (e0.x > eA.x) ? eA.y * e0.y : eA.z * e0.z;
            float wB0 = (e0.x > eB.x) ? eB.y * e0.y : eB.z * e0.z;
            float wA1 = (e1.x > eA.x) ? eA.y * e1.y : eA.z * e1.z;
            float wB1 = (e1.x > eB.x) ? eB.y * e1.y : eB.z * e1.z;
            wA0 = ((wordA >> jt) & 1u) ? wA0 : 0.f;
            wB0 = ((wordB >> jt) & 1u) ? wB0 : 0.f;
            wA1 = ((wordA >> (jt + 4)) & 1u) ? wA1 : 0.f;
            wB1 = ((wordB >> (jt + 4)) & 1u) ? wB1 : 0.f;
            lsA += wA0 + wA1;
            lsB += wB0 + wB1;
            u32 ah[4], al4[4];
            ah[0] = cvt_tf32(wA0); al4[0] = cvt_tf32(wA0 - __uint_as_float(ah[0]));
            ah[1] = cvt_tf32(wB0); al4[1] = cvt_tf32(wB0 - __uint_as_float(ah[1]));
            ah[2] = cvt_tf32(wA1); al4[2] = cvt_tf32(wA1 - __uint_as_float(ah[2]));
            ah[3] = cvt_tf32(wB1); al4[3] = cvt_tf32(wB1 - __uint_as_float(ah[3]));
#pragma unroll
            for (int nt = 0; nt < 16; nt++) {
                float4 bfr = S4[b][cc][tq][nt * 8 + g];
                u32 bh0 = __float_as_uint(bfr.x), bh1 = __float_as_uint(bfr.y);
                u32 bl0 = __float_as_uint(bfr.z), bl1 = __float_as_uint(bfr.w);
                mma8(acc[nt], ah, bh0, bh1);
                mma8(acc[nt], ah, bl0, bl1);
                mma8(acc[nt], al4, bh0, bh1);
            }
        }
        __syncthreads();
    }
    lsA += __shfl_xor_sync(0xffffffffu, lsA, 1);
    lsA += __shfl_xor_sync(0xffffffffu, lsA, 2);
    lsB += __shfl_xor_sync(0xffffffffu, lsB, 1);
    lsB += __shfl_xor_sync(0xffffffffu, lsB, 2);
    if (tq == 0) {
        g_psum[p * NN + iA] = lsA;
        g_psum[p * NN + iB] = lsB;
    }
    float* pb = g_part + (size_t)p * NN * OUT_F;
#pragma unroll
    for (int nt = 0; nt < 16; nt++) {
        int f = nt * 8 + tq * 2;
        *(float2*)(pb + (size_t)iA * OUT_F + f) = make_float2(acc[nt][0], acc[nt][1]);
        *(float2*)(pb + (size_t)iB * OUT_F + f) = make_float2(acc[nt][2], acc[nt][3]);
    }
}

// ---------------- final reduce + divide ----------------
__global__ void reduce2_kernel(float* __restrict__ out) {
    int i = blockIdx.x;
    int f = threadIdx.x;  // 128
    float num = 0.f, den = 0.f;
#pragma unroll
    for (int p = 0; p < JS2; p++) {
        num += g_part[(size_t)p * NN * OUT_F + (size_t)i * OUT_F + f];
        den += g_psum[p * NN + i];
    }
    out[i * OUT_F + f] = num / den;
}

// ---------------- launch ----------------
extern "C" void kernel_launch(void* const* d_in, const int* in_sizes, int n_in,
                              void* d_out, int out_size) {
    const float* x    = (const float*)d_in[0];
    const float* W1   = (const float*)d_in[1];
    const float* a1_l = (const float*)d_in[2];
    const float* a1_r = (const float*)d_in[3];
    const float* W2   = (const float*)d_in[4];
    const float* a2_l = (const float*)d_in[5];
    const float* a2_r = (const float*)d_in[6];
    const int*   adj  = (const int*)d_in[7];
    float* out = (float*)d_out;

    float* gp1 = nullptr; float* h1 = nullptr; float* gp2 = nullptr;
    cudaGetSymbolAddress((void**)&gp1, g_gp1);
    cudaGetSymbolAddress((void**)&h1, g_h1);
    cudaGetSymbolAddress((void**)&gp2, g_gp2);

    pack_adj_kernel<<<NN, 256>>>(adj);
    gemm_kernel<64, 64, 16><<<dim3(HID / 64, NN / 64, KS), 256>>>(
        x, W1, gp1, NN, HID, IN_F / KS, IN_F);
    elr1_kernel<<<NN, 256>>>(a1_l, a1_r);
    prep1_kernel<<<1024, 256>>>();
    agg1_mma_kernel<<<dim3(H1 * JS1, NN / 128), 256>>>();
    reduce1_kernel<<<NN, 256>>>();
    gemm_kernel<64, 64, 16><<<dim3(OUT_F / 64, NN / 64, KS), 256>>>(
        h1, W2, gp2, NN, OUT_F, HID / KS, HID);
    elr2_kernel<<<NN, 128>>>(a2_l, a2_r);
    prep2_kernel<<<512, 256>>>();
    agg2_mma_kernel<<<dim3(JS2, NN / 128), 256>>>();
    reduce2_kernel<<<NN, 128>>>(out);
}

// round 8
// speedup vs baseline: 1.8170x; 1.2408x over previous
#include <cuda_runtime.h>

#define NN     2048
#define IN_F   512
#define HID    256
#define OUT_F  128
#define H1     8
#define NWORDS 64   // NN/32
#define JS1    8    // agg1 j-split
#define JS2    16   // agg2 j-split
#define KSG    4    // gemm K-split

typedef unsigned long long ull;
typedef unsigned u32;

__device__ __forceinline__ ull fma2(ull a, ull b, ull c) {
    ull d; asm("fma.rn.f32x2 %0, %1, %2, %3;" : "=l"(d) : "l"(a), "l"(b), "l"(c)); return d;
}
__device__ __forceinline__ ull pack2(float v) {
    ull d; asm("mov.b64 %0, {%1, %1};" : "=l"(d) : "f"(v)); return d;
}
__device__ __forceinline__ void unpack2(ull v, float& lo, float& hi) {
    asm("mov.b64 {%0, %1}, %2;" : "=f"(lo), "=f"(hi) : "l"(v));
}
__device__ __forceinline__ u32 cvt_tf32(float x) {
    u32 u; asm("cvt.rna.tf32.f32 %0, %1;" : "=r"(u) : "f"(x)); return u;
}
__device__ __forceinline__ void mma8(float* d, const u32* a, u32 b0, u32 b1) {
    asm volatile(
        "mma.sync.aligned.m16n8k8.row.col.f32.tf32.tf32.f32 "
        "{%0,%1,%2,%3}, {%4,%5,%6,%7}, {%8,%9}, {%0,%1,%2,%3};"
        : "+f"(d[0]), "+f"(d[1]), "+f"(d[2]), "+f"(d[3])
        : "r"(a[0]), "r"(a[1]), "r"(a[2]), "r"(a[3]), "r"(b0), "r"(b1));
}
__device__ __forceinline__ void cpa16(u32 s, const void* g) {
    asm volatile("cp.async.ca.shared.global [%0], [%1], 16;" :: "r"(s), "l"(g));
}
#define CP_COMMIT asm volatile("cp.async.commit_group;")
#define CP_WAIT1  asm volatile("cp.async.wait_group 1;")
#define CP_WAIT0  asm volatile("cp.async.wait_group 0;")

// ---------------- scratch ----------------
__device__ __align__(16) float4 g_xAh[128 * 64 * 32];   // x A-fragments hi (4MB)
__device__ __align__(16) float4 g_xAl[128 * 64 * 32];   // x A-fragments lo
__device__ __align__(16) float4 g_w1B[64 * 32 * 32];    // W1 B-fragments {bh0,bh1,bl0,bl1}
__device__ __align__(16) float  g_gp1[KSG * NN * HID];
__device__ __align__(16) float  g_g1[NN * HID];
__device__ __align__(16) float4 g_eli1t[H1 * NN];   // [h][i] {-el, exp(el), exp(0.2el), 0}
__device__ __align__(16) float4 g_ebd1t[H1 * NN];   // [h][j]
__device__ __align__(16) float4 g_frag1[H1 * (NN / 8) * 4 * 32];   // agg1 B-frags (hi/lo)
__device__ unsigned g_bits[NN * NWORDS];
__device__ __align__(16) float  g_n1[JS1 * NN * HID];
__device__ float  g_d1[JS1 * NN * H1];
__device__ __align__(16) float  g_h1[NN * HID];
__device__ __align__(16) float  g_gp2[KSG * NN * OUT_F];
__device__ __align__(16) float  g_g2[NN * OUT_F];
__device__ __align__(16) float4 g_eli2[NN];
__device__ __align__(16) float4 g_ebd2[NN];
__device__ __align__(16) float4 g_frag2[(NN / 8) * 4 * OUT_F];
__device__ __align__(16) float  g_part[JS2 * NN * OUT_F];
__device__ float  g_psum[JS2 * NN];

// ---------------- pack adjacency ----------------
__global__ void pack_adj_kernel(const int* __restrict__ adj) {
    int i = blockIdx.x;
    int t = threadIdx.x;  // 256
    const int* row = adj + (size_t)i * NN;
#pragma unroll
    for (int k = 0; k < 8; k++) {
        int j = k * 256 + t;
        unsigned b = __ballot_sync(0xffffffffu, row[j] != 0);
        if ((t & 31) == 0) g_bits[i * NWORDS + (j >> 5)] = b;
    }
}

// ---------------- prep_in: x A-fragments + W1 B-fragments (tf32 hi/lo) ----------------
__global__ void prep_in_kernel(const float* __restrict__ x, const float* __restrict__ W1) {
    int idx = blockIdx.x * 256 + threadIdx.x;   // < 327680
    if (idx < 262144) {
        int lane = idx & 31, kt = (idx >> 5) & 63, it = idx >> 11;
        int g = lane >> 2, tq = lane & 3;
        int r = it * 16 + g, c = kt * 8 + tq;
        float v0 = x[(size_t)r * IN_F + c];
        float v1 = x[(size_t)(r + 8) * IN_F + c];
        float v2 = x[(size_t)r * IN_F + c + 4];
        float v3 = x[(size_t)(r + 8) * IN_F + c + 4];
        u32 h0 = cvt_tf32(v0), h1 = cvt_tf32(v1), h2 = cvt_tf32(v2), h3 = cvt_tf32(v3);
        float f0 = __uint_as_float(h0), f1 = __uint_as_float(h1);
        float f2 = __uint_as_float(h2), f3 = __uint_as_float(h3);
        g_xAh[idx] = make_float4(f0, f1, f2, f3);
        g_xAl[idx] = make_float4(__uint_as_float(cvt_tf32(v0 - f0)),
                                 __uint_as_float(cvt_tf32(v1 - f1)),
                                 __uint_as_float(cvt_tf32(v2 - f2)),
                                 __uint_as_float(cvt_tf32(v3 - f3)));
    } else {
        int e = idx - 262144;                   // < 65536
        int lane = e & 31, nt = (e >> 5) & 31, kt = e >> 10;
        int g = lane >> 2, tq = lane & 3;
        float b0 = W1[(size_t)(kt * 8 + tq) * HID + nt * 8 + g];
        float b1 = W1[(size_t)(kt * 8 + tq + 4) * HID + nt * 8 + g];
        u32 h0 = cvt_tf32(b0), h1 = cvt_tf32(b1);
        float f0 = __uint_as_float(h0), f1 = __uint_as_float(h1);
        g_w1B[e] = make_float4(f0, f1, __uint_as_float(cvt_tf32(b0 - f0)),
                               __uint_as_float(cvt_tf32(b1 - f1)));
    }
}

// ---------------- gemm1 tensor: 128i x 64n per block, K-split 4 ----------------
__global__ __launch_bounds__(256) void gemm1_mma_kernel() {
    __shared__ __align__(16) float4 Ah_s[2][8][2][32];   // 16KB
    __shared__ __align__(16) float4 Al_s[2][8][2][32];   // 16KB
    __shared__ __align__(16) float4 Bb_s[2][2][8][32];   // 8KB
    int z = blockIdx.z;
    int bi_t = blockIdx.y * 8;   // i-tile base
    int bn_t = blockIdx.x * 8;   // n-tile base
    int t = threadIdx.x;
    int lane = t & 31, w = t >> 5;
    float acc[8][4] = {};
    int ktz = z * 16;            // Klen = 128 -> 16 k-tiles, 8 chunks of 2

#define GM_STAGE(b, ch) do { \
        int kt0 = ktz + (ch) * 2; \
        _Pragma("unroll") \
        for (int q = 0; q < 2; q++) { \
            int e = t + q * 256; \
            int ln = e & 31, ktA = (e >> 5) & 1, itA = e >> 6; \
            size_t gi = ((size_t)(bi_t + itA) * 64 + kt0 + ktA) * 32 + ln; \
            cpa16((u32)__cvta_generic_to_shared(&Ah_s[b][itA][ktA][ln]), g_xAh + gi); \
            cpa16((u32)__cvta_generic_to_shared(&Al_s[b][itA][ktA][ln]), g_xAl + gi); \
            int ntB = (e >> 5) & 7, ktB = e >> 8; \
            size_t gb = ((size_t)(kt0 + ktB) * 32 + bn_t + ntB) * 32 + ln; \
            cpa16((u32)__cvta_generic_to_shared(&Bb_s[b][ktB][ntB][ln]), g_w1B + gb); \
        } \
    } while (0)

    GM_STAGE(0, 0);
    CP_COMMIT;
    for (int ch = 0; ch < 8; ch++) {
        int b = ch & 1;
        if (ch + 1 < 8) {
            GM_STAGE(b ^ 1, ch + 1);
            CP_COMMIT;
            CP_WAIT1;
        } else {
            CP_WAIT0;
        }
        __syncthreads();
#pragma unroll
        for (int kt = 0; kt < 2; kt++) {
            float4 a4h = Ah_s[b][w][kt][lane];
            float4 a4l = Al_s[b][w][kt][lane];
            u32 ah[4] = {__float_as_uint(a4h.x), __float_as_uint(a4h.y),
                         __float_as_uint(a4h.z), __float_as_uint(a4h.w)};
            u32 al[4] = {__float_as_uint(a4l.x), __float_as_uint(a4l.y),
                         __float_as_uint(a4l.z), __float_as_uint(a4l.w)};
#pragma unroll
            for (int nt = 0; nt < 8; nt++) {
                float4 bb = Bb_s[b][kt][nt][lane];
                u32 bh0 = __float_as_uint(bb.x), bh1 = __float_as_uint(bb.y);
                u32 bl0 = __float_as_uint(bb.z), bl1 = __float_as_uint(bb.w);
                mma8(acc[nt], ah, bh0, bh1);
                mma8(acc[nt], ah, bl0, bl1);
                mma8(acc[nt], al, bh0, bh1);
            }
        }
        __syncthreads();
    }
    int g = lane >> 2, tq = lane & 3;
    int r0 = blockIdx.y * 128 + w * 16 + g;
    float* Cz = g_gp1 + (size_t)z * NN * HID;
#pragma unroll
    for (int nt = 0; nt < 8; nt++) {
        int c = blockIdx.x * 64 + nt * 8 + tq * 2;
        *(float2*)(Cz + (size_t)r0 * HID + c) = make_float2(acc[nt][0], acc[nt][1]);
        *(float2*)(Cz + (size_t)(r0 + 8) * HID + c) = make_float2(acc[nt][2], acc[nt][3]);
    }
}

// ---------------- fp32 scalar GEMM (layer2), K-split via blockIdx.z ----------------
template <int BM, int BN, int BK>
__global__ __launch_bounds__(256) void gemm_kernel(const float* __restrict__ A,
                                                   const float* __restrict__ B,
                                                   float* __restrict__ C,
                                                   int M, int N, int Klen, int lda) {
    __shared__ float As[BM][BK + 1];
    __shared__ __align__(16) float Bs[BK][BN];
    const float* Ap = A + (size_t)blockIdx.z * Klen;
    const float* Bp = B + (size_t)blockIdx.z * Klen * N;
    float* Cp = C + (size_t)blockIdx.z * M * N;
    int bi = blockIdx.y * BM;
    int bn = blockIdx.x * BN;
    int t = threadIdx.x;
    int tn = (t % (BN / 4)) * 4;
    int ti = (t / (BN / 4)) * 4;
    ull acc2[4][2] = {};
    for (int k0 = 0; k0 < Klen; k0 += BK) {
        for (int e = t; e < BM * BK; e += 256) {
            int i = e / BK, k = e % BK;
            As[i][k] = Ap[(size_t)(bi + i) * lda + k0 + k];
        }
        for (int e = t; e < BK * BN; e += 256) {
            int k = e / BN, n = e % BN;
            Bs[k][n] = Bp[(size_t)(k0 + k) * N + bn + n];
        }
        __syncthreads();
#pragma unroll
        for (int k = 0; k < BK; k++) {
            ulonglong2 b2 = *(const ulonglong2*)&Bs[k][tn];
            ull a0 = pack2(As[ti + 0][k]);
            ull a1 = pack2(As[ti + 1][k]);
            ull a2 = pack2(As[ti + 2][k]);
            ull a3 = pack2(As[ti + 3][k]);
            acc2[0][0] = fma2(a0, b2.x, acc2[0][0]); acc2[0][1] = fma2(a0, b2.y, acc2[0][1]);
            acc2[1][0] = fma2(a1, b2.x, acc2[1][0]); acc2[1][1] = fma2(a1, b2.y, acc2[1][1]);
            acc2[2][0] = fma2(a2, b2.x, acc2[2][0]); acc2[2][1] = fma2(a2, b2.y, acc2[2][1]);
            acc2[3][0] = fma2(a3, b2.x, acc2[3][0]); acc2[3][1] = fma2(a3, b2.y, acc2[3][1]);
        }
        __syncthreads();
    }
#pragma unroll
    for (int r = 0; r < 4; r++) {
        float v0, v1, v2, v3;
        unpack2(acc2[r][0], v0, v1);
        unpack2(acc2[r][1], v2, v3);
        float* dst = Cp + (size_t)(bi + ti + r) * N + bn + tn;
        dst[0] = v0; dst[1] = v1; dst[2] = v2; dst[3] = v3;
    }
}

// ---------------- layer1: add K-partials, el/er exponentials ----------------
__global__ void elr1_kernel(const float* __restrict__ al, const float* __restrict__ ar) {
    int i = blockIdx.x;
    int t = threadIdx.x;  // 256
    float v = 0.f;
#pragma unroll
    for (int z = 0; z < KSG; z++) v += g_gp1[((size_t)z * NN + i) * HID + t];
    g_g1[(size_t)i * HID + t] = v;
    float pl = v * al[t & 31];
    float pr = v * ar[t & 31];
#pragma unroll
    for (int o = 16; o; o >>= 1) {
        pl += __shfl_down_sync(0xffffffffu, pl, o);
        pr += __shfl_down_sync(0xffffffffu, pr, o);
    }
    if ((t & 31) == 0) {
        int h = t >> 5;
        g_eli1t[h * NN + i] = make_float4(-pl, __expf(pl), __expf(0.2f * pl), 0.f);
        g_ebd1t[h * NN + i] = make_float4(pr, __expf(pr), __expf(0.2f * pr), 0.f);
    }
}

// ---------------- prep1: agg1 B-fragment tensor ----------------
__global__ void prep1_kernel() {
    int idx = blockIdx.x * 256 + threadIdx.x;   // < 262144
    int f = idx & 31, k = (idx >> 5) & 3, jb = (idx >> 7) & 255, h = idx >> 15;
    int j = jb * 8 + k;
    float v0 = g_g1[(size_t)j * HID + h * 32 + f];
    float v1 = g_g1[(size_t)(j + 4) * HID + h * 32 + f];
    u32 h0 = cvt_tf32(v0); float h0f = __uint_as_float(h0);
    u32 h1 = cvt_tf32(v1); float h1f = __uint_as_float(h1);
    u32 l0 = cvt_tf32(v0 - h0f);
    u32 l1 = cvt_tf32(v1 - h1f);
    g_frag1[idx] = make_float4(h0f, h1f, __uint_as_float(l0), __uint_as_float(l1));
}

// ---------------- layer1 aggregation ----------------
__global__ __launch_bounds__(256, 4) void agg1_mma_kernel() {
    __shared__ __align__(16) float4 S4[2][4][4][34];
    __shared__ __align__(16) float4 ebd_s[2][32];
    int h = blockIdx.x >> 3;
    int p = blockIdx.x & 7;
    int bi = blockIdx.y * 128;
    int t = threadIdx.x;
    int lane = t & 31, w = t >> 5;
    int g = lane >> 2, tq = lane & 3;
    int iA = bi + w * 16 + g;
    int iB = iA + 8;
    float4 eA = g_eli1t[h * NN + iA];
    float4 eB = g_eli1t[h * NN + iB];
    float acc[4][4] = {};
    float lsA = 0.f, lsB = 0.f;

    const float4* fb = g_frag1 + (size_t)h * 256 * 4 * 32;
    int e0i = t, e1i = t + 256;
    int cc0 = e0i >> 7, k0 = (e0i >> 5) & 3, f0 = e0i & 31;
    int cc1 = e1i >> 7, k1 = (e1i >> 5) & 3, f1 = e1i & 31;

    int jstart = p * (NN / JS1);   // 256 j
    const int NC = (NN / JS1) / 32;  // 8

#define STAGE1(b, j0) do { \
        int jb0 = (j0) >> 3; \
        cpa16((u32)__cvta_generic_to_shared(&S4[b][cc0][k0][f0]), fb + ((size_t)(jb0 + cc0) * 4 + k0) * 32 + f0); \
        cpa16((u32)__cvta_generic_to_shared(&S4[b][cc1][k1][f1]), fb + ((size_t)(jb0 + cc1) * 4 + k1) * 32 + f1); \
        if (t < 32) cpa16((u32)__cvta_generic_to_shared(&ebd_s[b][t]), g_ebd1t + h * NN + (j0) + t); \
    } while (0)

    STAGE1(0, jstart);
    CP_COMMIT;
    for (int c = 0; c < NC; c++) {
        int b = c & 1;
        if (c + 1 < NC) {
            STAGE1(b ^ 1, jstart + (c + 1) * 32);
            CP_COMMIT;
            CP_WAIT1;
        } else {
            CP_WAIT0;
        }
        __syncthreads();
        int j0 = jstart + c * 32;
        unsigned wordA = g_bits[(size_t)iA * NWORDS + (j0 >> 5)];
        unsigned wordB = g_bits[(size_t)iB * NWORDS + (j0 >> 5)];
#pragma unroll
        for (int cc = 0; cc < 4; cc++) {
            int jt = cc * 8 + tq;
            float4 e0 = ebd_s[b][jt];
            float4 e1 = ebd_s[b][jt + 4];
            float wA0 = (e0.x > eA.x) ? eA.y * e0.y : eA.z * e0.z;
            float wB0 = (e0.x > eB.x) ? eB.y * e0.y : eB.z * e0.z;
            float wA1 = (e1.x > eA.x) ? eA.y * e1.y : eA.z * e1.z;
            float wB1 = (e1.x > eB.x) ? eB.y * e1.y : eB.z * e1.z;
            wA0 = ((wordA >> jt) & 1u) ? wA0 : 0.f;
            wB0 = ((wordB >> jt) & 1u) ? wB0 : 0.f;
            wA1 = ((wordA >> (jt + 4)) & 1u) ? wA1 : 0.f;
            wB1 = ((wordB >> (jt + 4)) & 1u) ? wB1 : 0.f;
            lsA += wA0 + wA1;
            lsB += wB0 + wB1;
            u32 ah[4], al4[4];
            ah[0] = cvt_tf32(wA0); al4[0] = cvt_tf32(wA0 - __uint_as_float(ah[0]));
            ah[1] = cvt_tf32(wB0); al4[1] = cvt_tf32(wB0 - __uint_as_float(ah[1]));
            ah[2] = cvt_tf32(wA1); al4[2] = cvt_tf32(wA1 - __uint_as_float(ah[2]));
            ah[3] = cvt_tf32(wB1); al4[3] = cvt_tf32(wB1 - __uint_as_float(ah[3]));
#pragma unroll
            for (int nt = 0; nt < 4; nt++) {
                float4 bfr = S4[b][cc][tq][nt * 8 + g];
                u32 bh0 = __float_as_uint(bfr.x), bh1 = __float_as_uint(bfr.y);
                u32 bl0 = __float_as_uint(bfr.z), bl1 = __float_as_uint(bfr.w);
                mma8(acc[nt], ah, bh0, bh1);
                mma8(acc[nt], ah, bl0, bl1);
                mma8(acc[nt], al4, bh0, bh1);
            }
        }
        __syncthreads();
    }
    lsA += __shfl_xor_sync(0xffffffffu, lsA, 1);
    lsA += __shfl_xor_sync(0xffffffffu, lsA, 2);
    lsB += __shfl_xor_sync(0xffffffffu, lsB, 1);
    lsB += __shfl_xor_sync(0xffffffffu, lsB, 2);
    size_t rbase = (size_t)p * NN;
    if (tq == 0) {
        g_d1[(rbase + iA) * H1 + h] = lsA;
        g_d1[(rbase + iB) * H1 + h] = lsB;
    }
#pragma unroll
    for (int nt = 0; nt < 4; nt++) {
        int f = h * 32 + nt * 8 + tq * 2;
        *(float2*)(g_n1 + (rbase + iA) * HID + f) = make_float2(acc[nt][0], acc[nt][1]);
        *(float2*)(g_n1 + (rbase + iB) * HID + f) = make_float2(acc[nt][2], acc[nt][3]);
    }
}

// ---------------- layer1 reduce + divide + ELU ----------------
__global__ void reduce1_kernel() {
    int i = blockIdx.x;
    int t = threadIdx.x;  // 256
    int h = t >> 5;
    float num = 0.f, den = 0.f;
#pragma unroll
    for (int p = 0; p < JS1; p++) {
        num += g_n1[((size_t)p * NN + i) * HID + t];
        den += g_d1[(p * NN + i) * H1 + h];
    }
    float o = num / den;
    g_h1[(size_t)i * HID + t] = o > 0.f ? o : expm1f(o);
}

// ---------------- layer2 el/er ----------------
__global__ void elr2_kernel(const float* __restrict__ al, const float* __restrict__ ar) {
    __shared__ float sl[4], sr[4];
    int i = blockIdx.x;
    int t = threadIdx.x;  // 128
    float v = 0.f;
#pragma unroll
    for (int z = 0; z < KSG; z++) v += g_gp2[((size_t)z * NN + i) * OUT_F + t];
    g_g2[(size_t)i * OUT_F + t] = v;
    float pl = v * al[t];
    float pr = v * ar[t];
#pragma unroll
    for (int o = 16; o; o >>= 1) {
        pl += __shfl_down_sync(0xffffffffu, pl, o);
        pr += __shfl_down_sync(0xffffffffu, pr, o);
    }
    if ((t & 31) == 0) { sl[t >> 5] = pl; sr[t >> 5] = pr; }
    __syncthreads();
    if (t == 0) {
        float el = sl[0] + sl[1] + sl[2] + sl[3];
        float er = sr[0] + sr[1] + sr[2] + sr[3];
        g_eli2[i] = make_float4(-el, __expf(el), __expf(0.2f * el), 0.f);
        g_ebd2[i] = make_float4(er, __expf(er), __expf(0.2f * er), 0.f);
    }
}

// ---------------- prep2 ----------------
__global__ void prep2_kernel() {
    int idx = blockIdx.x * 256 + threadIdx.x;   // < 131072
    int f = idx & 127, k = (idx >> 7) & 3, jb = idx >> 9;
    int j = jb * 8 + k;
    float v0 = g_g2[(size_t)j * OUT_F + f];
    float v1 = g_g2[(size_t)(j + 4) * OUT_F + f];
    u32 h0 = cvt_tf32(v0); float h0f = __uint_as_float(h0);
    u32 h1 = cvt_tf32(v1); float h1f = __uint_as_float(h1);
    u32 l0 = cvt_tf32(v0 - h0f);
    u32 l1 = cvt_tf32(v1 - h1f);
    g_frag2[idx] = make_float4(h0f, h1f, __uint_as_float(l0), __uint_as_float(l1));
}

// ---------------- layer2 aggregation: 64-row tiles, 2 warps per i-tile ----------------
__global__ __launch_bounds__(256, 4) void agg2_mma_kernel() {
    __shared__ __align__(16) float4 S4[2][2][4][130];
    __shared__ __align__(16) float4 ebd_s[2][16];
    int p = blockIdx.x;          // 0..15
    int bi = blockIdx.y * 64;    // 32 tiles
    int t = threadIdx.x;
    int lane = t & 31, w = t >> 5;
    int g = lane >> 2, tq = lane & 3;
    int it = w >> 1, nth = w & 1;
    int iA = bi + it * 16 + g;
    int iB = iA + 8;
    float4 eA = g_eli2[iA];
    float4 eB = g_eli2[iB];
    float acc[8][4] = {};
    float lsA = 0.f, lsB = 0.f;

    int jstart = p * (NN / JS2);   // 128 j
    const int NC = (NN / JS2) / 16;  // 8

#define STAGE2(b, j0) do { \
        int jb0 = (j0) >> 3; \
        _Pragma("unroll") \
        for (int e = t; e < 1024; e += 256) { \
            int cc = e >> 9, k = (e >> 7) & 3, f = e & 127; \
            cpa16((u32)__cvta_generic_to_shared(&S4[b][cc][k][f]), \
                  g_frag2 + ((size_t)(jb0 + cc) * 4 + k) * 128 + f); \
        } \
        if (t < 16) cpa16((u32)__cvta_generic_to_shared(&ebd_s[b][t]), g_ebd2 + (j0) + t); \
    } while (0)

    STAGE2(0, jstart);
    CP_COMMIT;
    for (int c = 0; c < NC; c++) {
        int b = c & 1;
        if (c + 1 < NC) {
            STAGE2(b ^ 1, jstart + (c + 1) * 16);
            CP_COMMIT;
            CP_WAIT1;
        } else {
            CP_WAIT0;
        }
        __syncthreads();
        int j0 = jstart + c * 16;
        unsigned wordA = g_bits[(size_t)iA * NWORDS + (j0 >> 5)] >> (j0 & 31);
        unsigned wordB = g_bits[(size_t)iB * NWORDS + (j0 >> 5)] >> (j0 & 31);
#pragma unroll
        for (int cc = 0; cc < 2; cc++) {
            int jt = cc * 8 + tq;
            float4 e0 = ebd_s[b][jt];
            float4 e1 = ebd_s[b][jt + 4];
            float wA0 = (e0.x > eA.x) ? eA.y * e0.y : eA.z * e0.z;
            float wB0 = (e0.x > eB.x) ? eB.y * e0.y : eB.z * e0.z;
            float wA1 = (e1.x > eA.x) ? eA.y * e1.y : eA.z * e1.z;
            float wB1 = (e1.x > eB.x) ? eB.y * e1.y : eB.z * e1.z;
            wA0 = ((wordA >> jt) & 1u) ? wA0 : 0.f;
            wB0 = ((wordB >> jt) & 1u) ? wB0 : 0.f;
            wA1 = ((wordA >> (jt + 4)) & 1u) ? wA1 : 0.f;
            wB1 = ((wordB >> (jt + 4)) & 1u) ? wB1 : 0.f;
            lsA += wA0 + wA1;
            lsB += wB0 + wB1;
            u32 ah[4], al4[4];
            ah[0] = cvt_tf32(wA0); al4[0] = cvt_tf32(wA0 - __uint_as_float(ah[0]));
            ah[1] = cvt_tf32(wB0); al4[1] = cvt_tf32(wB0 - __uint_as_float(ah[1]));
            ah[2] = cvt_tf32(wA1); al4[2] = cvt_tf32(wA1 - __uint_as_float(ah[2]));
            ah[3] = cvt_tf32(wB1); al4[3] = cvt_tf32(wB1 - __uint_as_float(ah[3]));
#pragma unroll
            for (int nt = 0; nt < 8; nt++) {
                float4 bfr = S4[b][cc][tq][(nth * 8 + nt) * 8 + g];
                u32 bh0 = __float_as_uint(bfr.x), bh1 = __float_as_uint(bfr.y);
                u32 bl0 = __float_as_uint(bfr.z), bl1 = __float_as_uint(bfr.w);
                mma8(acc[nt], ah, bh0, bh1);
                mma8(acc[nt], ah, bl0, bl1);
                mma8(acc[nt], al4, bh0, bh1);
            }
        }
        __syncthreads();
    }
    lsA += __shfl_xor_sync(0xffffffffu, lsA, 1);
    lsA += __shfl_xor_sync(0xffffffffu, lsA, 2);
    lsB += __shfl_xor_sync(0xffffffffu, lsB, 1);
    lsB += __shfl_xor_sync(0xffffffffu, lsB, 2);
    if (tq == 0 && nth == 0) {
        g_psum[p * NN + iA] = lsA;
        g_psum[p * NN + iB] = lsB;
    }
    float* pb = g_part + (size_t)p * NN * OUT_F;
#pragma unroll
    for (int nt = 0; nt < 8; nt++) {
        int f = (nth * 8 + nt) * 8 + tq * 2;
        *(float2*)(pb + (size_t)iA * OUT_F + f) = make_float2(acc[nt][0], acc[nt][1]);
        *(float2*)(pb + (size_t)iB * OUT_F + f) = make_float2(acc[nt][2], acc[nt][3]);
    }
}

// ---------------- final reduce + divide ----------------
__global__ void reduce2_kernel(float* __restrict__ out) {
    int i = blockIdx.x;
    int f = threadIdx.x;  // 128
    float num = 0.f, den = 0.f;
#pragma unroll
    for (int p = 0; p < JS2; p++) {
        num += g_part[(size_t)p * NN * OUT_F + (size_t)i * OUT_F + f];
        den += g_psum[p * NN + i];
    }
    out[i * OUT_F + f] = num / den;
}

// ---------------- launch ----------------
extern "C" void kernel_launch(void* const* d_in, const int* in_sizes, int n_in,
                              void* d_out, int out_size) {
    const float* x    = (const float*)d_in[0];
    const float* W1   = (const float*)d_in[1];
    const float* a1_l = (const float*)d_in[2];
    const float* a1_r = (const float*)d_in[3];
    const float* W2   = (const float*)d_in[4];
    const float* a2_l = (const float*)d_in[5];
    const float* a2_r = (const float*)d_in[6];
    const int*   adj  = (const int*)d_in[7];
    float* out = (float*)d_out;

    float* h1 = nullptr; float* gp2 = nullptr;
    cudaGetSymbolAddress((void**)&h1, g_h1);
    cudaGetSymbolAddress((void**)&gp2, g_gp2);

    pack_adj_kernel<<<NN, 256>>>(adj);
    prep_in_kernel<<<1280, 256>>>(x, W1);
    gemm1_mma_kernel<<<dim3(4, 16, KSG), 256>>>();
    elr1_kernel<<<NN, 256>>>(a1_l, a1_r);
    prep1_kernel<<<1024, 256>>>();
    agg1_mma_kernel<<<dim3(H1 * JS1, NN / 128), 256>>>();
    reduce1_kernel<<<NN, 256>>>();
    gemm_kernel<64, 64, 16><<<dim3(OUT_F / 64, NN / 64, KSG), 256>>>(
        h1, W2, gp2, NN, OUT_F, HID / KSG, HID);
    elr2_kernel<<<NN, 128>>>(a2_l, a2_r);
    prep2_kernel<<<512, 256>>>();
    agg2_mma_kernel<<<dim3(JS2, NN / 64), 256>>>();
    reduce2_kernel<<<NN, 128>>>(out);
}

// round 9
// speedup vs baseline: 2.1506x; 1.1836x over previous
#include <cuda_runtime.h>

#define NN     2048
#define IN_F   512
#define HID    256
#define OUT_F  128
#define H1     8
#define NWORDS 64   // NN/32
#define JS1    8    // agg1 j-split
#define JS2    16   // agg2 j-split
#define KSG    4    // gemm K-split

typedef unsigned long long ull;
typedef unsigned u32;

__device__ __forceinline__ ull fma2(ull a, ull b, ull c) {
    ull d; asm("fma.rn.f32x2 %0, %1, %2, %3;" : "=l"(d) : "l"(a), "l"(b), "l"(c)); return d;
}
__device__ __forceinline__ ull pack2(float v) {
    ull d; asm("mov.b64 %0, {%1, %1};" : "=l"(d) : "f"(v)); return d;
}
__device__ __forceinline__ void unpack2(ull v, float& lo, float& hi) {
    asm("mov.b64 {%0, %1}, %2;" : "=f"(lo), "=f"(hi) : "l"(v));
}
__device__ __forceinline__ u32 cvt_tf32(float x) {
    u32 u; asm("cvt.rna.tf32.f32 %0, %1;" : "=r"(u) : "f"(x)); return u;
}
// pack {lo, hi} floats into bf16x2 (element0 = lo)
__device__ __forceinline__ u32 packbf(float lo, float hi) {
    u32 d; asm("cvt.rn.bf16x2.f32 %0, %1, %2;" : "=r"(d) : "f"(hi), "f"(lo)); return d;
}
__device__ __forceinline__ float bf_lo(u32 p) { return __uint_as_float(p << 16); }
__device__ __forceinline__ float bf_hi(u32 p) { return __uint_as_float(p & 0xffff0000u); }

__device__ __forceinline__ void mma8(float* d, const u32* a, u32 b0, u32 b1) {
    asm volatile(
        "mma.sync.aligned.m16n8k8.row.col.f32.tf32.tf32.f32 "
        "{%0,%1,%2,%3}, {%4,%5,%6,%7}, {%8,%9}, {%0,%1,%2,%3};"
        : "+f"(d[0]), "+f"(d[1]), "+f"(d[2]), "+f"(d[3])
        : "r"(a[0]), "r"(a[1]), "r"(a[2]), "r"(a[3]), "r"(b0), "r"(b1));
}
__device__ __forceinline__ void mma16(float* d, const u32* a, u32 b0, u32 b1) {
    asm volatile(
        "mma.sync.aligned.m16n8k16.row.col.f32.bf16.bf16.f32 "
        "{%0,%1,%2,%3}, {%4,%5,%6,%7}, {%8,%9}, {%0,%1,%2,%3};"
        : "+f"(d[0]), "+f"(d[1]), "+f"(d[2]), "+f"(d[3])
        : "r"(a[0]), "r"(a[1]), "r"(a[2]), "r"(a[3]), "r"(b0), "r"(b1));
}
__device__ __forceinline__ void cpa16(u32 s, const void* g) {
    asm volatile("cp.async.ca.shared.global [%0], [%1], 16;" :: "r"(s), "l"(g));
}
#define CP_COMMIT asm volatile("cp.async.commit_group;")
#define CP_WAIT1  asm volatile("cp.async.wait_group 1;")
#define CP_WAIT0  asm volatile("cp.async.wait_group 0;")

// ---------------- scratch ----------------
__device__ __align__(16) float4 g_xAh[128 * 64 * 32];   // x A-fragments hi (tf32, gemm1)
__device__ __align__(16) float4 g_xAl[128 * 64 * 32];
__device__ __align__(16) float4 g_w1B[64 * 32 * 32];    // W1 B-fragments
__device__ __align__(16) float  g_gp1[KSG * NN * HID];
__device__ __align__(16) float  g_g1[NN * HID];
__device__ __align__(16) float4 g_eli1t[H1 * NN];   // [h][i] {-el, exp(el), exp(0.2el), 0}
__device__ __align__(16) float4 g_ebd1t[H1 * NN];   // [h][j]
__device__ __align__(16) float4 g_frag1[H1 * 128 * 4 * 32];   // agg1 bf16 B-frags (2MB)
__device__ unsigned g_bits[NN * NWORDS];
__device__ __align__(16) float  g_n1[JS1 * NN * HID];
__device__ float  g_d1[JS1 * NN * H1];
__device__ __align__(16) float  g_h1[NN * HID];
__device__ __align__(16) float  g_gp2[KSG * NN * OUT_F];
__device__ __align__(16) float  g_g2[NN * OUT_F];
__device__ __align__(16) float4 g_eli2[NN];
__device__ __align__(16) float4 g_ebd2[NN];
__device__ __align__(16) float4 g_frag2[128 * 4 * OUT_F];     // agg2 bf16 B-frags (1MB)
__device__ __align__(16) float  g_part[JS2 * NN * OUT_F];
__device__ float  g_psum[JS2 * NN];

// ---------------- pack adjacency ----------------
__global__ void pack_adj_kernel(const int* __restrict__ adj) {
    int i = blockIdx.x;
    int t = threadIdx.x;  // 256
    const int* row = adj + (size_t)i * NN;
#pragma unroll
    for (int k = 0; k < 8; k++) {
        int j = k * 256 + t;
        unsigned b = __ballot_sync(0xffffffffu, row[j] != 0);
        if ((t & 31) == 0) g_bits[i * NWORDS + (j >> 5)] = b;
    }
}

// ---------------- prep_in: x A-fragments + W1 B-fragments (tf32 hi/lo) ----------------
__global__ void prep_in_kernel(const float* __restrict__ x, const float* __restrict__ W1) {
    int idx = blockIdx.x * 256 + threadIdx.x;   // < 327680
    if (idx < 262144) {
        int lane = idx & 31, kt = (idx >> 5) & 63, it = idx >> 11;
        int g = lane >> 2, tq = lane & 3;
        int r = it * 16 + g, c = kt * 8 + tq;
        float v0 = x[(size_t)r * IN_F + c];
        float v1 = x[(size_t)(r + 8) * IN_F + c];
        float v2 = x[(size_t)r * IN_F + c + 4];
        float v3 = x[(size_t)(r + 8) * IN_F + c + 4];
        u32 h0 = cvt_tf32(v0), h1 = cvt_tf32(v1), h2 = cvt_tf32(v2), h3 = cvt_tf32(v3);
        float f0 = __uint_as_float(h0), f1 = __uint_as_float(h1);
        float f2 = __uint_as_float(h2), f3 = __uint_as_float(h3);
        g_xAh[idx] = make_float4(f0, f1, f2, f3);
        g_xAl[idx] = make_float4(__uint_as_float(cvt_tf32(v0 - f0)),
                                 __uint_as_float(cvt_tf32(v1 - f1)),
                                 __uint_as_float(cvt_tf32(v2 - f2)),
                                 __uint_as_float(cvt_tf32(v3 - f3)));
    } else {
        int e = idx - 262144;                   // < 65536
        int lane = e & 31, nt = (e >> 5) & 31, kt = e >> 10;
        int g = lane >> 2, tq = lane & 3;
        float b0 = W1[(size_t)(kt * 8 + tq) * HID + nt * 8 + g];
        float b1 = W1[(size_t)(kt * 8 + tq + 4) * HID + nt * 8 + g];
        u32 h0 = cvt_tf32(b0), h1 = cvt_tf32(b1);
        float f0 = __uint_as_float(h0), f1 = __uint_as_float(h1);
        g_w1B[e] = make_float4(f0, f1, __uint_as_float(cvt_tf32(b0 - f0)),
                               __uint_as_float(cvt_tf32(b1 - f1)));
    }
}

// ---------------- gemm1 tensor: 128i x 64n per block, K-split 4 ----------------
__global__ __launch_bounds__(256) void gemm1_mma_kernel() {
    __shared__ __align__(16) float4 Ah_s[2][8][2][32];
    __shared__ __align__(16) float4 Al_s[2][8][2][32];
    __shared__ __align__(16) float4 Bb_s[2][2][8][32];
    int z = blockIdx.z;
    int bi_t = blockIdx.y * 8;
    int bn_t = blockIdx.x * 8;
    int t = threadIdx.x;
    int lane = t & 31, w = t >> 5;
    float acc[8][4] = {};
    int ktz = z * 16;

#define GM_STAGE(b, ch) do { \
        int kt0 = ktz + (ch) * 2; \
        _Pragma("unroll") \
        for (int q = 0; q < 2; q++) { \
            int e = t + q * 256; \
            int ln = e & 31, ktA = (e >> 5) & 1, itA = e >> 6; \
            size_t gi = ((size_t)(bi_t + itA) * 64 + kt0 + ktA) * 32 + ln; \
            cpa16((u32)__cvta_generic_to_shared(&Ah_s[b][itA][ktA][ln]), g_xAh + gi); \
            cpa16((u32)__cvta_generic_to_shared(&Al_s[b][itA][ktA][ln]), g_xAl + gi); \
            int ntB = (e >> 5) & 7, ktB = e >> 8; \
            size_t gb = ((size_t)(kt0 + ktB) * 32 + bn_t + ntB) * 32 + ln; \
            cpa16((u32)__cvta_generic_to_shared(&Bb_s[b][ktB][ntB][ln]), g_w1B + gb); \
        } \
    } while (0)

    GM_STAGE(0, 0);
    CP_COMMIT;
    for (int ch = 0; ch < 8; ch++) {
        int b = ch & 1;
        if (ch + 1 < 8) {
            GM_STAGE(b ^ 1, ch + 1);
            CP_COMMIT;
            CP_WAIT1;
        } else {
            CP_WAIT0;
        }
        __syncthreads();
#pragma unroll
        for (int kt = 0; kt < 2; kt++) {
            float4 a4h = Ah_s[b][w][kt][lane];
            float4 a4l = Al_s[b][w][kt][lane];
            u32 ah[4] = {__float_as_uint(a4h.x), __float_as_uint(a4h.y),
                         __float_as_uint(a4h.z), __float_as_uint(a4h.w)};
            u32 al[4] = {__float_as_uint(a4l.x), __float_as_uint(a4l.y),
                         __float_as_uint(a4l.z), __float_as_uint(a4l.w)};
#pragma unroll
            for (int nt = 0; nt < 8; nt++) {
                float4 bb = Bb_s[b][kt][nt][lane];
                u32 bh0 = __float_as_uint(bb.x), bh1 = __float_as_uint(bb.y);
                u32 bl0 = __float_as_uint(bb.z), bl1 = __float_as_uint(bb.w);
                mma8(acc[nt], ah, bh0, bh1);
                mma8(acc[nt], ah, bl0, bl1);
                mma8(acc[nt], al, bh0, bh1);
            }
        }
        __syncthreads();
    }
    int g = lane >> 2, tq = lane & 3;
    int r0 = blockIdx.y * 128 + w * 16 + g;
    float* Cz = g_gp1 + (size_t)z * NN * HID;
#pragma unroll
    for (int nt = 0; nt < 8; nt++) {
        int c = blockIdx.x * 64 + nt * 8 + tq * 2;
        *(float2*)(Cz + (size_t)r0 * HID + c) = make_float2(acc[nt][0], acc[nt][1]);
        *(float2*)(Cz + (size_t)(r0 + 8) * HID + c) = make_float2(acc[nt][2], acc[nt][3]);
    }
}

// ---------------- fp32 scalar GEMM (layer2), K-split via blockIdx.z ----------------
template <int BM, int BN, int BK>
__global__ __launch_bounds__(256) void gemm_kernel(const float* __restrict__ A,
                                                   const float* __restrict__ B,
                                                   float* __restrict__ C,
                                                   int M, int N, int Klen, int lda) {
    __shared__ float As[BM][BK + 1];
    __shared__ __align__(16) float Bs[BK][BN];
    const float* Ap = A + (size_t)blockIdx.z * Klen;
    const float* Bp = B + (size_t)blockIdx.z * Klen * N;
    float* Cp = C + (size_t)blockIdx.z * M * N;
    int bi = blockIdx.y * BM;
    int bn = blockIdx.x * BN;
    int t = threadIdx.x;
    int tn = (t % (BN / 4)) * 4;
    int ti = (t / (BN / 4)) * 4;
    ull acc2[4][2] = {};
    for (int k0 = 0; k0 < Klen; k0 += BK) {
        for (int e = t; e < BM * BK; e += 256) {
            int i = e / BK, k = e % BK;
            As[i][k] = Ap[(size_t)(bi + i) * lda + k0 + k];
        }
        for (int e = t; e < BK * BN; e += 256) {
            int k = e / BN, n = e % BN;
            Bs[k][n] = Bp[(size_t)(k0 + k) * N + bn + n];
        }
        __syncthreads();
#pragma unroll
        for (int k = 0; k < BK; k++) {
            ulonglong2 b2 = *(const ulonglong2*)&Bs[k][tn];
            ull a0 = pack2(As[ti + 0][k]);
            ull a1 = pack2(As[ti + 1][k]);
            ull a2 = pack2(As[ti + 2][k]);
            ull a3 = pack2(As[ti + 3][k]);
            acc2[0][0] = fma2(a0, b2.x, acc2[0][0]); acc2[0][1] = fma2(a0, b2.y, acc2[0][1]);
            acc2[1][0] = fma2(a1, b2.x, acc2[1][0]); acc2[1][1] = fma2(a1, b2.y, acc2[1][1]);
            acc2[2][0] = fma2(a2, b2.x, acc2[2][0]); acc2[2][1] = fma2(a2, b2.y, acc2[2][1]);
            acc2[3][0] = fma2(a3, b2.x, acc2[3][0]); acc2[3][1] = fma2(a3, b2.y, acc2[3][1]);
        }
        __syncthreads();
    }
#pragma unroll
    for (int r = 0; r < 4; r++) {
        float v0, v1, v2, v3;
        unpack2(acc2[r][0], v0, v1);
        unpack2(acc2[r][1], v2, v3);
        float* dst = Cp + (size_t)(bi + ti + r) * N + bn + tn;
        dst[0] = v0; dst[1] = v1; dst[2] = v2; dst[3] = v3;
    }
}

// ---------------- layer1: add K-partials, el/er exponentials ----------------
__global__ void elr1_kernel(const float* __restrict__ al, const float* __restrict__ ar) {
    int i = blockIdx.x;
    int t = threadIdx.x;  // 256
    float v = 0.f;
#pragma unroll
    for (int z = 0; z < KSG; z++) v += g_gp1[((size_t)z * NN + i) * HID + t];
    g_g1[(size_t)i * HID + t] = v;
    float pl = v * al[t & 31];
    float pr = v * ar[t & 31];
#pragma unroll
    for (int o = 16; o; o >>= 1) {
        pl += __shfl_down_sync(0xffffffffu, pl, o);
        pr += __shfl_down_sync(0xffffffffu, pr, o);
    }
    if ((t & 31) == 0) {
        int h = t >> 5;
        g_eli1t[h * NN + i] = make_float4(-pl, __expf(pl), __expf(0.2f * pl), 0.f);
        g_ebd1t[h * NN + i] = make_float4(pr, __expf(pr), __expf(0.2f * pr), 0.f);
    }
}

// ---------------- prep1: agg1 bf16 B-fragment tensor ----------------
// word[((h*128 + jt)*4 + tq)*32 + f] = {bh(j=jt16+2tq, 2tq+1), bh(2tq+8, 2tq+9), bl.., bl..}
__global__ void prep1_kernel() {
    int idx = blockIdx.x * 256 + threadIdx.x;   // < 131072
    int f = idx & 31, tq = (idx >> 5) & 3, jt = (idx >> 7) & 127, h = idx >> 14;
    int j0 = jt * 16 + 2 * tq;
    const float* base = g_g1 + h * 32 + f;
    float v0 = base[(size_t)j0 * HID];
    float v1 = base[(size_t)(j0 + 1) * HID];
    float v2 = base[(size_t)(j0 + 8) * HID];
    float v3 = base[(size_t)(j0 + 9) * HID];
    u32 bh0 = packbf(v0, v1), bh1 = packbf(v2, v3);
    u32 bl0 = packbf(v0 - bf_lo(bh0), v1 - bf_hi(bh0));
    u32 bl1 = packbf(v2 - bf_lo(bh1), v3 - bf_hi(bh1));
    g_frag1[idx] = make_float4(__uint_as_float(bh0), __uint_as_float(bh1),
                               __uint_as_float(bl0), __uint_as_float(bl1));
}

// ---------------- layer1 aggregation: bf16 m16n8k16, weights in registers ----------------
__global__ __launch_bounds__(256, 4) void agg1_mma_kernel() {
    __shared__ __align__(16) float4 S4[2][2][4][34];   // [buf][kt][tq][f pad34]
    __shared__ __align__(16) float4 ebd_s[2][32];
    int h = blockIdx.x >> 3;
    int p = blockIdx.x & 7;
    int bi = blockIdx.y * 128;
    int t = threadIdx.x;
    int lane = t & 31, w = t >> 5;
    int g = lane >> 2, tq = lane & 3;
    int iA = bi + w * 16 + g;
    int iB = iA + 8;
    float4 eA = g_eli1t[h * NN + iA];
    float4 eB = g_eli1t[h * NN + iB];
    float acc[4][4] = {};
    float lsA = 0.f, lsB = 0.f;

    int sf = t & 31, stq = (t >> 5) & 3, skt = t >> 7;
    const float4* fb = g_frag1 + (size_t)h * 128 * 4 * 32;
    int jstart = p * (NN / JS1);   // 256 j
    const int NC = (NN / JS1) / 32;  // 8

#define STAGE1(b, j0) do { \
        int jt0 = (j0) >> 4; \
        cpa16((u32)__cvta_generic_to_shared(&S4[b][skt][stq][sf]), \
              fb + ((size_t)(jt0 + skt) * 4 + stq) * 32 + sf); \
        if (t < 32) cpa16((u32)__cvta_generic_to_shared(&ebd_s[b][t]), g_ebd1t + h * NN + (j0) + t); \
    } while (0)

    STAGE1(0, jstart);
    CP_COMMIT;
    for (int c = 0; c < NC; c++) {
        int b = c & 1;
        if (c + 1 < NC) {
            STAGE1(b ^ 1, jstart + (c + 1) * 32);
            CP_COMMIT;
            CP_WAIT1;
        } else {
            CP_WAIT0;
        }
        __syncthreads();
        int j0 = jstart + c * 32;
        unsigned wordA = g_bits[(size_t)iA * NWORDS + (j0 >> 5)];
        unsigned wordB = g_bits[(size_t)iB * NWORDS + (j0 >> 5)];
#pragma unroll
        for (int kt = 0; kt < 2; kt++) {
            int jb = kt * 16 + 2 * tq;
            float4 e1 = ebd_s[b][jb];
            float4 e2 = ebd_s[b][jb + 1];
            float4 e3 = ebd_s[b][jb + 8];
            float4 e4 = ebd_s[b][jb + 9];
            float wA1 = (e1.x > eA.x) ? eA.y * e1.y : eA.z * e1.z;
            float wA2 = (e2.x > eA.x) ? eA.y * e2.y : eA.z * e2.z;
            float wA3 = (e3.x > eA.x) ? eA.y * e3.y : eA.z * e3.z;
            float wA4 = (e4.x > eA.x) ? eA.y * e4.y : eA.z * e4.z;
            float wB1 = (e1.x > eB.x) ? eB.y * e1.y : eB.z * e1.z;
            float wB2 = (e2.x > eB.x) ? eB.y * e2.y : eB.z * e2.z;
            float wB3 = (e3.x > eB.x) ? eB.y * e3.y : eB.z * e3.z;
            float wB4 = (e4.x > eB.x) ? eB.y * e4.y : eB.z * e4.z;
            wA1 = ((wordA >> jb) & 1u) ? wA1 : 0.f;
            wA2 = ((wordA >> (jb + 1)) & 1u) ? wA2 : 0.f;
            wA3 = ((wordA >> (jb + 8)) & 1u) ? wA3 : 0.f;
            wA4 = ((wordA >> (jb + 9)) & 1u) ? wA4 : 0.f;
            wB1 = ((wordB >> jb) & 1u) ? wB1 : 0.f;
            wB2 = ((wordB >> (jb + 1)) & 1u) ? wB2 : 0.f;
            wB3 = ((wordB >> (jb + 8)) & 1u) ? wB3 : 0.f;
            wB4 = ((wordB >> (jb + 9)) & 1u) ? wB4 : 0.f;
            lsA += (wA1 + wA2) + (wA3 + wA4);
            lsB += (wB1 + wB2) + (wB3 + wB4);
            u32 ah[4], al4[4];
            ah[0] = packbf(wA1, wA2); ah[1] = packbf(wB1, wB2);
            ah[2] = packbf(wA3, wA4); ah[3] = packbf(wB3, wB4);
            al4[0] = packbf(wA1 - bf_lo(ah[0]), wA2 - bf_hi(ah[0]));
            al4[1] = packbf(wB1 - bf_lo(ah[1]), wB2 - bf_hi(ah[1]));
            al4[2] = packbf(wA3 - bf_lo(ah[2]), wA4 - bf_hi(ah[2]));
            al4[3] = packbf(wB3 - bf_lo(ah[3]), wB4 - bf_hi(ah[3]));
#pragma unroll
            for (int nt = 0; nt < 4; nt++) {
                float4 bfr = S4[b][kt][tq][nt * 8 + g];
                u32 bh0 = __float_as_uint(bfr.x), bh1 = __float_as_uint(bfr.y);
                u32 bl0 = __float_as_uint(bfr.z), bl1 = __float_as_uint(bfr.w);
                mma16(acc[nt], ah, bh0, bh1);
                mma16(acc[nt], ah, bl0, bl1);
                mma16(acc[nt], al4, bh0, bh1);
            }
        }
        __syncthreads();
    }
    lsA += __shfl_xor_sync(0xffffffffu, lsA, 1);
    lsA += __shfl_xor_sync(0xffffffffu, lsA, 2);
    lsB += __shfl_xor_sync(0xffffffffu, lsB, 1);
    lsB += __shfl_xor_sync(0xffffffffu, lsB, 2);
    size_t rbase = (size_t)p * NN;
    if (tq == 0) {
        g_d1[(rbase + iA) * H1 + h] = lsA;
        g_d1[(rbase + iB) * H1 + h] = lsB;
    }
#pragma unroll
    for (int nt = 0; nt < 4; nt++) {
        int f = h * 32 + nt * 8 + tq * 2;
        *(float2*)(g_n1 + (rbase + iA) * HID + f) = make_float2(acc[nt][0], acc[nt][1]);
        *(float2*)(g_n1 + (rbase + iB) * HID + f) = make_float2(acc[nt][2], acc[nt][3]);
    }
}

// ---------------- layer1 reduce + divide + ELU ----------------
__global__ void reduce1_kernel() {
    int i = blockIdx.x;
    int t = threadIdx.x;  // 256
    int h = t >> 5;
    float num = 0.f, den = 0.f;
#pragma unroll
    for (int p = 0; p < JS1; p++) {
        num += g_n1[((size_t)p * NN + i) * HID + t];
        den += g_d1[(p * NN + i) * H1 + h];
    }
    float o = num / den;
    g_h1[(size_t)i * HID + t] = o > 0.f ? o : expm1f(o);
}

// ---------------- layer2 el/er ----------------
__global__ void elr2_kernel(const float* __restrict__ al, const float* __restrict__ ar) {
    __shared__ float sl[4], sr[4];
    int i = blockIdx.x;
    int t = threadIdx.x;  // 128
    float v = 0.f;
#pragma unroll
    for (int z = 0; z < KSG; z++) v += g_gp2[((size_t)z * NN + i) * OUT_F + t];
    g_g2[(size_t)i * OUT_F + t] = v;
    float pl = v * al[t];
    float pr = v * ar[t];
#pragma unroll
    for (int o = 16; o; o >>= 1) {
        pl += __shfl_down_sync(0xffffffffu, pl, o);
        pr += __shfl_down_sync(0xffffffffu, pr, o);
    }
    if ((t & 31) == 0) { sl[t >> 5] = pl; sr[t >> 5] = pr; }
    __syncthreads();
    if (t == 0) {
        float el = sl[0] + sl[1] + sl[2] + sl[3];
        float er = sr[0] + sr[1] + sr[2] + sr[3];
        g_eli2[i] = make_float4(-el, __expf(el), __expf(0.2f * el), 0.f);
        g_ebd2[i] = make_float4(er, __expf(er), __expf(0.2f * er), 0.f);
    }
}

// ---------------- prep2: agg2 bf16 B-fragments ----------------
__global__ void prep2_kernel() {
    int idx = blockIdx.x * 256 + threadIdx.x;   // < 65536
    int f = idx & 127, tq = (idx >> 7) & 3, jt = idx >> 9;
    int j0 = jt * 16 + 2 * tq;
    const float* base = g_g2 + f;
    float v0 = base[(size_t)j0 * OUT_F];
    float v1 = base[(size_t)(j0 + 1) * OUT_F];
    float v2 = base[(size_t)(j0 + 8) * OUT_F];
    float v3 = base[(size_t)(j0 + 9) * OUT_F];
    u32 bh0 = packbf(v0, v1), bh1 = packbf(v2, v3);
    u32 bl0 = packbf(v0 - bf_lo(bh0), v1 - bf_hi(bh0));
    u32 bl1 = packbf(v2 - bf_lo(bh1), v3 - bf_hi(bh1));
    g_frag2[idx] = make_float4(__uint_as_float(bh0), __uint_as_float(bh1),
                               __uint_as_float(bl0), __uint_as_float(bl1));
}

// ---------------- layer2 aggregation: bf16 m16n8k16, 64-row tiles ----------------
__global__ __launch_bounds__(256, 4) void agg2_mma_kernel() {
    __shared__ __align__(16) float4 S4[2][4][130];   // [buf][tq][f pad130]
    __shared__ __align__(16) float4 ebd_s[2][16];
    int p = blockIdx.x;          // 0..15
    int bi = blockIdx.y * 64;    // 32 tiles
    int t = threadIdx.x;
    int lane = t & 31, w = t >> 5;
    int g = lane >> 2, tq = lane & 3;
    int it = w >> 1, nth = w & 1;
    int iA = bi + it * 16 + g;
    int iB = iA + 8;
    float4 eA = g_eli2[iA];
    float4 eB = g_eli2[iB];
    float acc[8][4] = {};
    float lsA = 0.f, lsB = 0.f;

    int jstart = p * (NN / JS2);   // 128 j
    const int NC = (NN / JS2) / 16;  // 8

#define STAGE2(b, j0) do { \
        int jt0 = (j0) >> 4; \
        _Pragma("unroll") \
        for (int e = t; e < 512; e += 256) { \
            int sq = e >> 7, f = e & 127; \
            cpa16((u32)__cvta_generic_to_shared(&S4[b][sq][f]), \
                  g_frag2 + ((size_t)jt0 * 4 + sq) * 128 + f); \
        } \
        if (t < 16) cpa16((u32)__cvta_generic_to_shared(&ebd_s[b][t]), g_ebd2 + (j0) + t); \
    } while (0)

    STAGE2(0, jstart);
    CP_COMMIT;
    for (int c = 0; c < NC; c++) {
        int b = c & 1;
        if (c + 1 < NC) {
            STAGE2(b ^ 1, jstart + (c + 1) * 16);
            CP_COMMIT;
            CP_WAIT1;
        } else {
            CP_WAIT0;
        }
        __syncthreads();
        int j0 = jstart + c * 16;
        unsigned wordA = g_bits[(size_t)iA * NWORDS + (j0 >> 5)] >> (j0 & 31);
        unsigned wordB = g_bits[(size_t)iB * NWORDS + (j0 >> 5)] >> (j0 & 31);
        int jb = 2 * tq;
        float4 e1 = ebd_s[b][jb];
        float4 e2 = ebd_s[b][jb + 1];
        float4 e3 = ebd_s[b][jb + 8];
        float4 e4 = ebd_s[b][jb + 9];
        float wA1 = (e1.x > eA.x) ? eA.y * e1.y : eA.z * e1.z;
        float wA2 = (e2.x > eA.x) ? eA.y * e2.y : eA.z * e2.z;
        float wA3 = (e3.x > eA.x) ? eA.y * e3.y : eA.z * e3.z;
        float wA4 = (e4.x > eA.x) ? eA.y * e4.y : eA.z * e4.z;
        float wB1 = (e1.x > eB.x) ? eB.y * e1.y : eB.z * e1.z;
        float wB2 = (e2.x > eB.x) ? eB.y * e2.y : eB.z * e2.z;
        float wB3 = (e3.x > eB.x) ? eB.y * e3.y : eB.z * e3.z;
        float wB4 = (e4.x > eB.x) ? eB.y * e4.y : eB.z * e4.z;
        wA1 = ((wordA >> jb) & 1u) ? wA1 : 0.f;
        wA2 = ((wordA >> (jb + 1)) & 1u) ? wA2 : 0.f;
        wA3 = ((wordA >> (jb + 8)) & 1u) ? wA3 : 0.f;
        wA4 = ((wordA >> (jb + 9)) & 1u) ? wA4 : 0.f;
        wB1 = ((wordB >> jb) & 1u) ? wB1 : 0.f;
        wB2 = ((wordB >> (jb + 1)) & 1u) ? wB2 : 0.f;
        wB3 = ((wordB >> (jb + 8)) & 1u) ? wB3 : 0.f;
        wB4 = ((wordB >> (jb + 9)) & 1u) ? wB4 : 0.f;
        lsA += (wA1 + wA2) + (wA3 + wA4);
        lsB += (wB1 + wB2) + (wB3 + wB4);
        u32 ah[4], al4[4];
        ah[0] = packbf(wA1, wA2); ah[1] = packbf(wB1, wB2);
        ah[2] = packbf(wA3, wA4); ah[3] = packbf(wB3, wB4);
        al4[0] = packbf(wA1 - bf_lo(ah[0]), wA2 - bf_hi(ah[0]));
        al4[1] = packbf(wB1 - bf_lo(ah[1]), wB2 - bf_hi(ah[1]));
        al4[2] = packbf(wA3 - bf_lo(ah[2]), wA4 - bf_hi(ah[2]));
        al4[3] = packbf(wB3 - bf_lo(ah[3]), wB4 - bf_hi(ah[3]));
#pragma unroll
        for (int nt = 0; nt < 8; nt++) {
            float4 bfr = S4[b][tq][(nth * 8 + nt) * 8 + g];
            u32 bh0 = __float_as_uint(bfr.x), bh1 = __float_as_uint(bfr.y);
            u32 bl0 = __float_as_uint(bfr.z), bl1 = __float_as_uint(bfr.w);
            mma16(acc[nt], ah, bh0, bh1);
            mma16(acc[nt], ah, bl0, bl1);
            mma16(acc[nt], al4, bh0, bh1);
        }
        __syncthreads();
    }
    lsA += __shfl_xor_sync(0xffffffffu, lsA, 1);
    lsA += __shfl_xor_sync(0xffffffffu, lsA, 2);
    lsB += __shfl_xor_sync(0xffffffffu, lsB, 1);
    lsB += __shfl_xor_sync(0xffffffffu, lsB, 2);
    if (tq == 0 && nth == 0) {
        g_psum[p * NN + iA] = lsA;
        g_psum[p * NN + iB] = lsB;
    }
    float* pb = g_part + (size_t)p * NN * OUT_F;
#pragma unroll
    for (int nt = 0; nt < 8; nt++) {
        int f = (nth * 8 + nt) * 8 + tq * 2;
        *(float2*)(pb + (size_t)iA * OUT_F + f) = make_float2(acc[nt][0], acc[nt][1]);
        *(float2*)(pb + (size_t)iB * OUT_F + f) = make_float2(acc[nt][2], acc[nt][3]);
    }
}

// ---------------- final reduce + divide ----------------
__global__ void reduce2_kernel(float* __restrict__ out) {
    int i = blockIdx.x;
    int f = threadIdx.x;  // 128
    float num = 0.f, den = 0.f;
#pragma unroll
    for (int p = 0; p < JS2; p++) {
        num += g_part[(size_t)p * NN * OUT_F + (size_t)i * OUT_F + f];
        den += g_psum[p * NN + i];
    }
    out[i * OUT_F + f] = num / den;
}

// ---------------- launch ----------------
extern "C" void kernel_launch(void* const* d_in, const int* in_sizes, int n_in,
                              void* d_out, int out_size) {
    const float* x    = (const float*)d_in[0];
    const float* W1   = (const float*)d_in[1];
    const float* a1_l = (const float*)d_in[2];
    const float* a1_r = (const float*)d_in[3];
    const float* W2   = (const float*)d_in[4];
    const float* a2_l = (const float*)d_in[5];
    const float* a2_r = (const float*)d_in[6];
    const int*   adj  = (const int*)d_in[7];
    float* out = (float*)d_out;

    float* h1 = nullptr; float* gp2 = nullptr;
    cudaGetSymbolAddress((void**)&h1, g_h1);
    cudaGetSymbolAddress((void**)&gp2, g_gp2);

    pack_adj_kernel<<<NN, 256>>>(adj);
    prep_in_kernel<<<1280, 256>>>(x, W1);
    gemm1_mma_kernel<<<dim3(4, 16, KSG), 256>>>();
    elr1_kernel<<<NN, 256>>>(a1_l, a1_r);
    prep1_kernel<<<512, 256>>>();
    agg1_mma_kernel<<<dim3(H1 * JS1, NN / 128), 256>>>();
    reduce1_kernel<<<NN, 256>>>();
    gemm_kernel<64, 64, 16><<<dim3(OUT_F / 64, NN / 64, KSG), 256>>>(
        h1, W2, gp2, NN, OUT_F, HID / KSG, HID);
    elr2_kernel<<<NN, 128>>>(a2_l, a2_r);
    prep2_kernel<<<256, 256>>>();
    agg2_mma_kernel<<<dim3(JS2, NN / 64), 256>>>();
    reduce2_kernel<<<NN, 128>>>(out);
}

// round 10
// speedup vs baseline: 2.4208x; 1.1256x over previous
#include <cuda_runtime.h>

#define NN     2048
#define IN_F   512
#define HID    256
#define OUT_F  128
#define H1     8
#define NWORDS 64   // NN/32
#define JS1    4    // agg1 j-split
#define JS2    8    // agg2 j-split
#define KS1G   2    // gemm1 K-split
#define KS2G   4    // gemm2 K-split

typedef unsigned long long ull;
typedef unsigned u32;

__device__ __forceinline__ ull fma2(ull a, ull b, ull c) {
    ull d; asm("fma.rn.f32x2 %0, %1, %2, %3;" : "=l"(d) : "l"(a), "l"(b), "l"(c)); return d;
}
__device__ __forceinline__ ull pack2(float v) {
    ull d; asm("mov.b64 %0, {%1, %1};" : "=l"(d) : "f"(v)); return d;
}
__device__ __forceinline__ void unpack2(ull v, float& lo, float& hi) {
    asm("mov.b64 {%0, %1}, %2;" : "=f"(lo), "=f"(hi) : "l"(v));
}
// pack {lo, hi} floats into bf16x2 (element0 = lo)
__device__ __forceinline__ u32 packbf(float lo, float hi) {
    u32 d; asm("cvt.rn.bf16x2.f32 %0, %1, %2;" : "=r"(d) : "f"(hi), "f"(lo)); return d;
}
__device__ __forceinline__ float bf_lo(u32 p) { return __uint_as_float(p << 16); }
__device__ __forceinline__ float bf_hi(u32 p) { return __uint_as_float(p & 0xffff0000u); }

__device__ __forceinline__ void mma16(float* d, const u32* a, u32 b0, u32 b1) {
    asm volatile(
        "mma.sync.aligned.m16n8k16.row.col.f32.bf16.bf16.f32 "
        "{%0,%1,%2,%3}, {%4,%5,%6,%7}, {%8,%9}, {%0,%1,%2,%3};"
        : "+f"(d[0]), "+f"(d[1]), "+f"(d[2]), "+f"(d[3])
        : "r"(a[0]), "r"(a[1]), "r"(a[2]), "r"(a[3]), "r"(b0), "r"(b1));
}
__device__ __forceinline__ void cpa16(u32 s, const void* g) {
    asm volatile("cp.async.ca.shared.global [%0], [%1], 16;" :: "r"(s), "l"(g));
}
#define CP_COMMIT asm volatile("cp.async.commit_group;")
#define CP_WAIT1  asm volatile("cp.async.wait_group 1;")
#define CP_WAIT0  asm volatile("cp.async.wait_group 0;")

// ---------------- scratch ----------------
__device__ __align__(16) float4 g_xAh[128 * 32 * 32];   // x A-frag hi (bf16 words, 2MB)
__device__ __align__(16) float4 g_xAl[128 * 32 * 32];   // x A-frag lo
__device__ __align__(16) float4 g_w1B[32 * 32 * 32];    // W1 B-frags {bh0,bh1,bl0,bl1}
__device__ __align__(16) float  g_gp1[KS1G * NN * HID];
__device__ __align__(16) float4 g_eli1t[H1 * NN];   // [h][i] {-el, exp(el), exp(0.2el), 0}
__device__ __align__(16) float4 g_ebd1t[H1 * NN];   // [h][j]
__device__ __align__(16) float4 g_frag1[H1 * 128 * 4 * 32];   // agg1 bf16 B-frags (2MB)
__device__ unsigned g_bits[NN * NWORDS];
__device__ __align__(16) float  g_n1[JS1 * NN * HID];
__device__ float  g_d1[JS1 * NN * H1];
__device__ __align__(16) float  g_h1[NN * HID];
__device__ __align__(16) float  g_gp2[KS2G * NN * OUT_F];
__device__ __align__(16) float4 g_eli2[NN];
__device__ __align__(16) float4 g_ebd2[NN];
__device__ __align__(16) float4 g_frag2[128 * 4 * 128];       // agg2 bf16 B-frags (1MB)
__device__ __align__(16) float  g_part[JS2 * NN * OUT_F];
__device__ float  g_psum[JS2 * NN];

// ---------------- pack adjacency ----------------
__global__ void pack_adj_kernel(const int* __restrict__ adj) {
    int i = blockIdx.x;
    int t = threadIdx.x;  // 256
    const int* row = adj + (size_t)i * NN;
#pragma unroll
    for (int k = 0; k < 8; k++) {
        int j = k * 256 + t;
        unsigned b = __ballot_sync(0xffffffffu, row[j] != 0);
        if ((t & 31) == 0) g_bits[i * NWORDS + (j >> 5)] = b;
    }
}

// ---------------- prep_in: x A-frags + W1 B-frags (bf16 hi/lo) ----------------
__global__ void prep_in_kernel(const float* __restrict__ x, const float* __restrict__ W1) {
    int idx = blockIdx.x * 256 + threadIdx.x;   // < 163840
    if (idx < 131072) {
        int lane = idx & 31, kt = (idx >> 5) & 31, it = idx >> 10;
        int g = lane >> 2, tq = lane & 3;
        int r = it * 16 + g, c = kt * 16 + 2 * tq;
        const float* xr = x + (size_t)r * IN_F + c;
        float2 p0 = *(const float2*)xr;
        float2 p1 = *(const float2*)(xr + 8 * IN_F);
        float2 p2 = *(const float2*)(xr + 8);
        float2 p3 = *(const float2*)(xr + 8 * IN_F + 8);
        u32 a0 = packbf(p0.x, p0.y), a1 = packbf(p1.x, p1.y);
        u32 a2 = packbf(p2.x, p2.y), a3 = packbf(p3.x, p3.y);
        g_xAh[idx] = make_float4(__uint_as_float(a0), __uint_as_float(a1),
                                 __uint_as_float(a2), __uint_as_float(a3));
        u32 l0 = packbf(p0.x - bf_lo(a0), p0.y - bf_hi(a0));
        u32 l1 = packbf(p1.x - bf_lo(a1), p1.y - bf_hi(a1));
        u32 l2 = packbf(p2.x - bf_lo(a2), p2.y - bf_hi(a2));
        u32 l3 = packbf(p3.x - bf_lo(a3), p3.y - bf_hi(a3));
        g_xAl[idx] = make_float4(__uint_as_float(l0), __uint_as_float(l1),
                                 __uint_as_float(l2), __uint_as_float(l3));
    } else {
        int e = idx - 131072;                   // < 32768
        int lane = e & 31, nt = (e >> 5) & 31, kt = e >> 10;
        int g = lane >> 2, tq = lane & 3;
        int n = nt * 8 + g, k0 = kt * 16 + 2 * tq;
        float b0a = W1[(size_t)k0 * HID + n];
        float b0b = W1[(size_t)(k0 + 1) * HID + n];
        float b1a = W1[(size_t)(k0 + 8) * HID + n];
        float b1b = W1[(size_t)(k0 + 9) * HID + n];
        u32 bh0 = packbf(b0a, b0b), bh1 = packbf(b1a, b1b);
        u32 bl0 = packbf(b0a - bf_lo(bh0), b0b - bf_hi(bh0));
        u32 bl1 = packbf(b1a - bf_lo(bh1), b1b - bf_hi(bh1));
        g_w1B[e] = make_float4(__uint_as_float(bh0), __uint_as_float(bh1),
                               __uint_as_float(bl0), __uint_as_float(bl1));
    }
}

// ---------------- gemm1 bf16 tensor: 64i x 64n per block, K-split 2 ----------------
__global__ __launch_bounds__(256) void gemm1_mma_kernel() {
    __shared__ __align__(16) float4 Ah_s[2][4][2][32];   // 8KB
    __shared__ __align__(16) float4 Al_s[2][4][2][32];   // 8KB
    __shared__ __align__(16) float4 Bb_s[2][2][8][32];   // 16KB
    int z = blockIdx.z;
    int bi_t = blockIdx.y * 4;   // 16-row i-tile base
    int bn_t = blockIdx.x * 8;   // 8-col n-tile base
    int t = threadIdx.x;
    int lane = t & 31, w = t >> 5;
    int itw = w >> 1, nh = w & 1;
    float acc[4][4] = {};
    int ktz = z * 16;            // 16 k-tiles per z (K=512 -> 32 kt)

#define GM_STAGE(b, ch) do { \
        int kt0 = ktz + (ch) * 2; \
        { int e = t; int ln = e & 31, kk = (e >> 5) & 1, it = e >> 6; \
          size_t gi = ((size_t)(bi_t + it) * 32 + kt0 + kk) * 32 + ln; \
          cpa16((u32)__cvta_generic_to_shared(&Ah_s[b][it][kk][ln]), g_xAh + gi); \
          cpa16((u32)__cvta_generic_to_shared(&Al_s[b][it][kk][ln]), g_xAl + gi); } \
        _Pragma("unroll") \
        for (int q = 0; q < 2; q++) { int e = t + q * 256; \
          int ln = e & 31, nt = (e >> 5) & 7, kk = e >> 8; \
          size_t gb = ((size_t)(kt0 + kk) * 32 + bn_t + nt) * 32 + ln; \
          cpa16((u32)__cvta_generic_to_shared(&Bb_s[b][kk][nt][ln]), g_w1B + gb); } \
    } while (0)

    GM_STAGE(0, 0);
    CP_COMMIT;
    for (int ch = 0; ch < 8; ch++) {
        int b = ch & 1;
        if (ch + 1 < 8) {
            GM_STAGE(b ^ 1, ch + 1);
            CP_COMMIT;
            CP_WAIT1;
        } else {
            CP_WAIT0;
        }
        __syncthreads();
#pragma unroll
        for (int kt = 0; kt < 2; kt++) {
            float4 a4h = Ah_s[b][itw][kt][lane];
            float4 a4l = Al_s[b][itw][kt][lane];
            u32 ah[4] = {__float_as_uint(a4h.x), __float_as_uint(a4h.y),
                         __float_as_uint(a4h.z), __float_as_uint(a4h.w)};
            u32 alr[4] = {__float_as_uint(a4l.x), __float_as_uint(a4l.y),
                          __float_as_uint(a4l.z), __float_as_uint(a4l.w)};
#pragma unroll
            for (int n4 = 0; n4 < 4; n4++) {
                float4 bb = Bb_s[b][kt][nh * 4 + n4][lane];
                u32 bh0 = __float_as_uint(bb.x), bh1 = __float_as_uint(bb.y);
                u32 bl0 = __float_as_uint(bb.z), bl1 = __float_as_uint(bb.w);
                mma16(acc[n4], ah, bh0, bh1);
                mma16(acc[n4], ah, bl0, bl1);
                mma16(acc[n4], alr, bh0, bh1);
            }
        }
        __syncthreads();
    }
    int g = lane >> 2, tq = lane & 3;
    int r0 = blockIdx.y * 64 + itw * 16 + g;
    float* Cz = g_gp1 + (size_t)z * NN * HID;
#pragma unroll
    for (int n4 = 0; n4 < 4; n4++) {
        int c = blockIdx.x * 64 + (nh * 4 + n4) * 8 + tq * 2;
        *(float2*)(Cz + (size_t)r0 * HID + c) = make_float2(acc[n4][0], acc[n4][1]);
        *(float2*)(Cz + (size_t)(r0 + 8) * HID + c) = make_float2(acc[n4][2], acc[n4][3]);
    }
}

// ---------------- fp32 scalar GEMM (layer2), K-split via blockIdx.z ----------------
template <int BM, int BN, int BK>
__global__ __launch_bounds__(256) void gemm_kernel(const float* __restrict__ A,
                                                   const float* __restrict__ B,
                                                   float* __restrict__ C,
                                                   int M, int N, int Klen, int lda) {
    __shared__ float As[BM][BK + 1];
    __shared__ __align__(16) float Bs[BK][BN];
    const float* Ap = A + (size_t)blockIdx.z * Klen;
    const float* Bp = B + (size_t)blockIdx.z * Klen * N;
    float* Cp = C + (size_t)blockIdx.z * M * N;
    int bi = blockIdx.y * BM;
    int bn = blockIdx.x * BN;
    int t = threadIdx.x;
    int tn = (t % (BN / 4)) * 4;
    int ti = (t / (BN / 4)) * 4;
    ull acc2[4][2] = {};
    for (int k0 = 0; k0 < Klen; k0 += BK) {
        for (int e = t; e < BM * BK; e += 256) {
            int i = e / BK, k = e % BK;
            As[i][k] = Ap[(size_t)(bi + i) * lda + k0 + k];
        }
        for (int e = t; e < BK * BN; e += 256) {
            int k = e / BN, n = e % BN;
            Bs[k][n] = Bp[(size_t)(k0 + k) * N + bn + n];
        }
        __syncthreads();
#pragma unroll
        for (int k = 0; k < BK; k++) {
            ulonglong2 b2 = *(const ulonglong2*)&Bs[k][tn];
            ull a0 = pack2(As[ti + 0][k]);
            ull a1 = pack2(As[ti + 1][k]);
            ull a2 = pack2(As[ti + 2][k]);
            ull a3 = pack2(As[ti + 3][k]);
            acc2[0][0] = fma2(a0, b2.x, acc2[0][0]); acc2[0][1] = fma2(a0, b2.y, acc2[0][1]);
            acc2[1][0] = fma2(a1, b2.x, acc2[1][0]); acc2[1][1] = fma2(a1, b2.y, acc2[1][1]);
            acc2[2][0] = fma2(a2, b2.x, acc2[2][0]); acc2[2][1] = fma2(a2, b2.y, acc2[2][1]);
            acc2[3][0] = fma2(a3, b2.x, acc2[3][0]); acc2[3][1] = fma2(a3, b2.y, acc2[3][1]);
        }
        __syncthreads();
    }
#pragma unroll
    for (int r = 0; r < 4; r++) {
        float v0, v1, v2, v3;
        unpack2(acc2[r][0], v0, v1);
        unpack2(acc2[r][1], v2, v3);
        float* dst = Cp + (size_t)(bi + ti + r) * N + bn + tn;
        dst[0] = v0; dst[1] = v1; dst[2] = v2; dst[3] = v3;
    }
}

// ---------------- elr1f: fused K-partial sum + el/er exp + bf16 fragment emit ----------------
// One block = 16 nodes (jt group). Eliminates g_g1 and prep1.
__global__ __launch_bounds__(256) void elr1f_kernel(const float* __restrict__ al,
                                                    const float* __restrict__ ar) {
    __shared__ float v_s[16][256];    // 16KB
    __shared__ float elbuf[8][16], erbuf[8][16];
    int jt = blockIdx.x;              // 128 blocks
    int base = jt * 16;
    int t = threadIdx.x;
    int lane = t & 31, h = t >> 5;

    // phase1: sum K-partials; keep in regs + smem
    float v[16];
#pragma unroll
    for (int s = 0; s < 16; s++) {
        float x = 0.f;
#pragma unroll
        for (int z = 0; z < KS1G; z++)
            x += g_gp1[((size_t)z * NN + base + s) * HID + t];
        v[s] = x;
        v_s[s][t] = x;
    }
    // phase2: el/er per (node, head=h) via warp reduce
    float alv = al[lane], arv = ar[lane];
#pragma unroll
    for (int s = 0; s < 16; s++) {
        float pl = v[s] * alv, pr = v[s] * arv;
#pragma unroll
        for (int o = 16; o; o >>= 1) {
            pl += __shfl_down_sync(0xffffffffu, pl, o);
            pr += __shfl_down_sync(0xffffffffu, pr, o);
        }
        if (lane == 0) { elbuf[h][s] = pl; erbuf[h][s] = pr; }
    }
    __syncthreads();
    // phase2.5: exponentials -> global
    if (t < 128) {
        int hh = t >> 4, s = t & 15;
        float el = elbuf[hh][s], er = erbuf[hh][s];
        g_eli1t[hh * NN + base + s] = make_float4(-el, __expf(el), __expf(0.2f * el), 0.f);
        g_ebd1t[hh * NN + base + s] = make_float4(er, __expf(er), __expf(0.2f * er), 0.f);
    }
    // phase3: emit 1024 bf16 fragment words (4 per thread)
#pragma unroll
    for (int q = 0; q < 4; q++) {
        int widx = t + q * 256;           // 0..1023
        int f = widx & 31, tq = (widx >> 5) & 3, hh = widx >> 7;
        int col = hh * 32 + f;
        float v0 = v_s[2 * tq][col];
        float v1 = v_s[2 * tq + 1][col];
        float v2 = v_s[2 * tq + 8][col];
        float v3 = v_s[2 * tq + 9][col];
        u32 bh0 = packbf(v0, v1), bh1 = packbf(v2, v3);
        u32 bl0 = packbf(v0 - bf_lo(bh0), v1 - bf_hi(bh0));
        u32 bl1 = packbf(v2 - bf_lo(bh1), v3 - bf_hi(bh1));
        g_frag1[((size_t)(hh * 128 + jt) * 4 + tq) * 32 + f] =
            make_float4(__uint_as_float(bh0), __uint_as_float(bh1),
                        __uint_as_float(bl0), __uint_as_float(bl1));
    }
}

// ---------------- layer1 aggregation: bf16 m16n8k16 ----------------
__global__ __launch_bounds__(256, 4) void agg1_mma_kernel() {
    __shared__ __align__(16) float4 S4[2][2][4][34];
    __shared__ __align__(16) float4 ebd_s[2][32];
    int h = blockIdx.x >> 2;
    int p = blockIdx.x & 3;
    int bi = blockIdx.y * 128;
    int t = threadIdx.x;
    int lane = t & 31, w = t >> 5;
    int g = lane >> 2, tq = lane & 3;
    int iA = bi + w * 16 + g;
    int iB = iA + 8;
    float4 eA = g_eli1t[h * NN + iA];
    float4 eB = g_eli1t[h * NN + iB];
    float acc[4][4] = {};
    float lsA = 0.f, lsB = 0.f;

    int sf = t & 31, stq = (t >> 5) & 3, skt = t >> 7;
    const float4* fb = g_frag1 + (size_t)h * 128 * 4 * 32;
    int jstart = p * (NN / JS1);   // 512 j
    const int NC = (NN / JS1) / 32;  // 16

#define STAGE1(b, j0) do { \
        int jt0 = (j0) >> 4; \
        cpa16((u32)__cvta_generic_to_shared(&S4[b][skt][stq][sf]), \
              fb + ((size_t)(jt0 + skt) * 4 + stq) * 32 + sf); \
        if (t < 32) cpa16((u32)__cvta_generic_to_shared(&ebd_s[b][t]), g_ebd1t + h * NN + (j0) + t); \
    } while (0)

    STAGE1(0, jstart);
    CP_COMMIT;
    for (int c = 0; c < NC; c++) {
        int b = c & 1;
        if (c + 1 < NC) {
            STAGE1(b ^ 1, jstart + (c + 1) * 32);
            CP_COMMIT;
            CP_WAIT1;
        } else {
            CP_WAIT0;
        }
        __syncthreads();
        int j0 = jstart + c * 32;
        unsigned wordA = g_bits[(size_t)iA * NWORDS + (j0 >> 5)];
        unsigned wordB = g_bits[(size_t)iB * NWORDS + (j0 >> 5)];
#pragma unroll
        for (int kt = 0; kt < 2; kt++) {
            int jb = kt * 16 + 2 * tq;
            float4 e1 = ebd_s[b][jb];
            float4 e2 = ebd_s[b][jb + 1];
            float4 e3 = ebd_s[b][jb + 8];
            float4 e4 = ebd_s[b][jb + 9];
            float wA1 = (e1.x > eA.x) ? eA.y * e1.y : eA.z * e1.z;
            float wA2 = (e2.x > eA.x) ? eA.y * e2.y : eA.z * e2.z;
            float wA3 = (e3.x > eA.x) ? eA.y * e3.y : eA.z * e3.z;
            float wA4 = (e4.x > eA.x) ? eA.y * e4.y : eA.z * e4.z;
            float wB1 = (e1.x > eB.x) ? eB.y * e1.y : eB.z * e1.z;
            float wB2 = (e2.x > eB.x) ? eB.y * e2.y : eB.z * e2.z;
            float wB3 = (e3.x > eB.x) ? eB.y * e3.y : eB.z * e3.z;
            float wB4 = (e4.x > eB.x) ? eB.y * e4.y : eB.z * e4.z;
            wA1 = ((wordA >> jb) & 1u) ? wA1 : 0.f;
            wA2 = ((wordA >> (jb + 1)) & 1u) ? wA2 : 0.f;
            wA3 = ((wordA >> (jb + 8)) & 1u) ? wA3 : 0.f;
            wA4 = ((wordA >> (jb + 9)) & 1u) ? wA4 : 0.f;
            wB1 = ((wordB >> jb) & 1u) ? wB1 : 0.f;
            wB2 = ((wordB >> (jb + 1)) & 1u) ? wB2 : 0.f;
            wB3 = ((wordB >> (jb + 8)) & 1u) ? wB3 : 0.f;
            wB4 = ((wordB >> (jb + 9)) & 1u) ? wB4 : 0.f;
            lsA += (wA1 + wA2) + (wA3 + wA4);
            lsB += (wB1 + wB2) + (wB3 + wB4);
            u32 ah[4], al4[4];
            ah[0] = packbf(wA1, wA2); ah[1] = packbf(wB1, wB2);
            ah[2] = packbf(wA3, wA4); ah[3] = packbf(wB3, wB4);
            al4[0] = packbf(wA1 - bf_lo(ah[0]), wA2 - bf_hi(ah[0]));
            al4[1] = packbf(wB1 - bf_lo(ah[1]), wB2 - bf_hi(ah[1]));
            al4[2] = packbf(wA3 - bf_lo(ah[2]), wA4 - bf_hi(ah[2]));
            al4[3] = packbf(wB3 - bf_lo(ah[3]), wB4 - bf_hi(ah[3]));
#pragma unroll
            for (int nt = 0; nt < 4; nt++) {
                float4 bfr = S4[b][kt][tq][nt * 8 + g];
                u32 bh0 = __float_as_uint(bfr.x), bh1 = __float_as_uint(bfr.y);
                u32 bl0 = __float_as_uint(bfr.z), bl1 = __float_as_uint(bfr.w);
                mma16(acc[nt], ah, bh0, bh1);
                mma16(acc[nt], ah, bl0, bl1);
                mma16(acc[nt], al4, bh0, bh1);
            }
        }
        __syncthreads();
    }
    lsA += __shfl_xor_sync(0xffffffffu, lsA, 1);
    lsA += __shfl_xor_sync(0xffffffffu, lsA, 2);
    lsB += __shfl_xor_sync(0xffffffffu, lsB, 1);
    lsB += __shfl_xor_sync(0xffffffffu, lsB, 2);
    size_t rbase = (size_t)p * NN;
    if (tq == 0) {
        g_d1[(rbase + iA) * H1 + h] = lsA;
        g_d1[(rbase + iB) * H1 + h] = lsB;
    }
#pragma unroll
    for (int nt = 0; nt < 4; nt++) {
        int f = h * 32 + nt * 8 + tq * 2;
        *(float2*)(g_n1 + (rbase + iA) * HID + f) = make_float2(acc[nt][0], acc[nt][1]);
        *(float2*)(g_n1 + (rbase + iB) * HID + f) = make_float2(acc[nt][2], acc[nt][3]);
    }
}

// ---------------- layer1 reduce + divide + ELU ----------------
__global__ void reduce1_kernel() {
    int i = blockIdx.x;
    int t = threadIdx.x;  // 256
    int h = t >> 5;
    float num = 0.f, den = 0.f;
#pragma unroll
    for (int p = 0; p < JS1; p++) {
        num += g_n1[((size_t)p * NN + i) * HID + t];
        den += g_d1[(p * NN + i) * H1 + h];
    }
    float o = num / den;
    g_h1[(size_t)i * HID + t] = o > 0.f ? o : expm1f(o);
}

// ---------------- elr2f: fused K-partial sum + el/er + bf16 fragment emit ----------------
__global__ __launch_bounds__(256) void elr2f_kernel(const float* __restrict__ al,
                                                    const float* __restrict__ ar) {
    __shared__ float v_s[16][128];   // 8KB
    __shared__ float pel[16][4], per[16][4];
    int jt = blockIdx.x;             // 128 blocks
    int base = jt * 16;
    int t = threadIdx.x;
    int f = t & 127, th = t >> 7;
    int wq = (t >> 5) & 3, lane = t & 31;

    float v[8];
#pragma unroll
    for (int s = 0; s < 8; s++) {
        int node = 2 * s + th;
        float x = 0.f;
#pragma unroll
        for (int z = 0; z < KS2G; z++)
            x += g_gp2[((size_t)z * NN + base + node) * OUT_F + f];
        v[s] = x;
        v_s[node][f] = x;
    }
    float alv = al[f], arv = ar[f];
#pragma unroll
    for (int s = 0; s < 8; s++) {
        float pl = v[s] * alv, pr = v[s] * arv;
#pragma unroll
        for (int o = 16; o; o >>= 1) {
            pl += __shfl_down_sync(0xffffffffu, pl, o);
            pr += __shfl_down_sync(0xffffffffu, pr, o);
        }
        if (lane == 0) { pel[2 * s + th][wq] = pl; per[2 * s + th][wq] = pr; }
    }
    __syncthreads();
    if (t < 16) {
        float el = pel[t][0] + pel[t][1] + pel[t][2] + pel[t][3];
        float er = per[t][0] + per[t][1] + per[t][2] + per[t][3];
        g_eli2[base + t] = make_float4(-el, __expf(el), __expf(0.2f * el), 0.f);
        g_ebd2[base + t] = make_float4(er, __expf(er), __expf(0.2f * er), 0.f);
    }
#pragma unroll
    for (int q = 0; q < 2; q++) {
        int widx = t + q * 256;          // 0..511
        int ff = widx & 127, tq = widx >> 7;
        float v0 = v_s[2 * tq][ff];
        float v1 = v_s[2 * tq + 1][ff];
        float v2 = v_s[2 * tq + 8][ff];
        float v3 = v_s[2 * tq + 9][ff];
        u32 bh0 = packbf(v0, v1), bh1 = packbf(v2, v3);
        u32 bl0 = packbf(v0 - bf_lo(bh0), v1 - bf_hi(bh0));
        u32 bl1 = packbf(v2 - bf_lo(bh1), v3 - bf_hi(bh1));
        g_frag2[((size_t)jt * 4 + tq) * 128 + ff] =
            make_float4(__uint_as_float(bh0), __uint_as_float(bh1),
                        __uint_as_float(bl0), __uint_as_float(bl1));
    }
}

// ---------------- layer2 aggregation: bf16 m16n8k16, 64-row tiles ----------------
__global__ __launch_bounds__(256, 4) void agg2_mma_kernel() {
    __shared__ __align__(16) float4 S4[2][4][130];
    __shared__ __align__(16) float4 ebd_s[2][16];
    int p = blockIdx.x;          // 0..7
    int bi = blockIdx.y * 64;    // 32 tiles
    int t = threadIdx.x;
    int lane = t & 31, w = t >> 5;
    int g = lane >> 2, tq = lane & 3;
    int it = w >> 1, nth = w & 1;
    int iA = bi + it * 16 + g;
    int iB = iA + 8;
    float4 eA = g_eli2[iA];
    float4 eB = g_eli2[iB];
    float acc[8][4] = {};
    float lsA = 0.f, lsB = 0.f;

    int jstart = p * (NN / JS2);     // 256 j
    const int NC = (NN / JS2) / 16;  // 16

#define STAGE2(b, j0) do { \
        int jt0 = (j0) >> 4; \
        _Pragma("unroll") \
        for (int e = t; e < 512; e += 256) { \
            int sq = e >> 7, ff = e & 127; \
            cpa16((u32)__cvta_generic_to_shared(&S4[b][sq][ff]), \
                  g_frag2 + ((size_t)jt0 * 4 + sq) * 128 + ff); \
        } \
        if (t < 16) cpa16((u32)__cvta_generic_to_shared(&ebd_s[b][t]), g_ebd2 + (j0) + t); \
    } while (0)

    STAGE2(0, jstart);
    CP_COMMIT;
    for (int c = 0; c < NC; c++) {
        int b = c & 1;
        if (c + 1 < NC) {
            STAGE2(b ^ 1, jstart + (c + 1) * 16);
            CP_COMMIT;
            CP_WAIT1;
        } else {
            CP_WAIT0;
        }
        __syncthreads();
        int j0 = jstart + c * 16;
        unsigned wordA = g_bits[(size_t)iA * NWORDS + (j0 >> 5)] >> (j0 & 31);
        unsigned wordB = g_bits[(size_t)iB * NWORDS + (j0 >> 5)] >> (j0 & 31);
        int jb = 2 * tq;
        float4 e1 = ebd_s[b][jb];
        float4 e2 = ebd_s[b][jb + 1];
        float4 e3 = ebd_s[b][jb + 8];
        float4 e4 = ebd_s[b][jb + 9];
        float wA1 = (e1.x > eA.x) ? eA.y * e1.y : eA.z * e1.z;
        float wA2 = (e2.x > eA.x) ? eA.y * e2.y : eA.z * e2.z;
        float wA3 = (e3.x > eA.x) ? eA.y * e3.y : eA.z * e3.z;
        float wA4 = (e4.x > eA.x) ? eA.y * e4.y : eA.z * e4.z;
        float wB1 = (e1.x > eB.x) ? eB.y * e1.y : eB.z * e1.z;
        float wB2 = (e2.x > eB.x) ? eB.y * e2.y : eB.z * e2.z;
        float wB3 = (e3.x > eB.x) ? eB.y * e3.y : eB.z * e3.z;
        float wB4 = (e4.x > eB.x) ? eB.y * e4.y : eB.z * e4.z;
        wA1 = ((wordA >> jb) & 1u) ? wA1 : 0.f;
        wA2 = ((wordA >> (jb + 1)) & 1u) ? wA2 : 0.f;
        wA3 = ((wordA >> (jb + 8)) & 1u) ? wA3 : 0.f;
        wA4 = ((wordA >> (jb + 9)) & 1u) ? wA4 : 0.f;
        wB1 = ((wordB >> jb) & 1u) ? wB1 : 0.f;
        wB2 = ((wordB >> (jb + 1)) & 1u) ? wB2 : 0.f;
        wB3 = ((wordB >> (jb + 8)) & 1u) ? wB3 : 0.f;
        wB4 = ((wordB >> (jb + 9)) & 1u) ? wB4 : 0.f;
        lsA += (wA1 + wA2) + (wA3 + wA4);
        lsB += (wB1 + wB2) + (wB3 + wB4);
        u32 ah[4], al4[4];
        ah[0] = packbf(wA1, wA2); ah[1] = packbf(wB1, wB2);
        ah[2] = packbf(wA3, wA4); ah[3] = packbf(wB3, wB4);
        al4[0] = packbf(wA1 - bf_lo(ah[0]), wA2 - bf_hi(ah[0]));
        al4[1] = packbf(wB1 - bf_lo(ah[1]), wB2 - bf_hi(ah[1]));
        al4[2] = packbf(wA3 - bf_lo(ah[2]), wA4 - bf_hi(ah[2]));
        al4[3] = packbf(wB3 - bf_lo(ah[3]), wB4 - bf_hi(ah[3]));
#pragma unroll
        for (int nt = 0; nt < 8; nt++) {
            float4 bfr = S4[b][tq][(nth * 8 + nt) * 8 + g];
            u32 bh0 = __float_as_uint(bfr.x), bh1 = __float_as_uint(bfr.y);
            u32 bl0 = __float_as_uint(bfr.z), bl1 = __float_as_uint(bfr.w);
            mma16(acc[nt], ah, bh0, bh1);
            mma16(acc[nt], ah, bl0, bl1);
            mma16(acc[nt], al4, bh0, bh1);
        }
        __syncthreads();
    }
    lsA += __shfl_xor_sync(0xffffffffu, lsA, 1);
    lsA += __shfl_xor_sync(0xffffffffu, lsA, 2);
    lsB += __shfl_xor_sync(0xffffffffu, lsB, 1);
    lsB += __shfl_xor_sync(0xffffffffu, lsB, 2);
    if (tq == 0 && nth == 0) {
        g_psum[p * NN + iA] = lsA;
        g_psum[p * NN + iB] = lsB;
    }
    float* pb = g_part + (size_t)p * NN * OUT_F;
#pragma unroll
    for (int nt = 0; nt < 8; nt++) {
        int f = (nth * 8 + nt) * 8 + tq * 2;
        *(float2*)(pb + (size_t)iA * OUT_F + f) = make_float2(acc[nt][0], acc[nt][1]);
        *(float2*)(pb + (size_t)iB * OUT_F + f) = make_float2(acc[nt][2], acc[nt][3]);
    }
}

// ---------------- final reduce + divide ----------------
__global__ void reduce2_kernel(float* __restrict__ out) {
    int i = blockIdx.x;
    int f = threadIdx.x;  // 128
    float num = 0.f, den = 0.f;
#pragma unroll
    for (int p = 0; p < JS2; p++) {
        num += g_part[(size_t)p * NN * OUT_F + (size_t)i * OUT_F + f];
        den += g_psum[p * NN + i];
    }
    out[i * OUT_F + f] = num / den;
}

// ---------------- launch ----------------
extern "C" void kernel_launch(void* const* d_in, const int* in_sizes, int n_in,
                              void* d_out, int out_size) {
    const float* x    = (const float*)d_in[0];
    const float* W1   = (const float*)d_in[1];
    const float* a1_l = (const float*)d_in[2];
    const float* a1_r = (const float*)d_in[3];
    const float* W2   = (const float*)d_in[4];
    const float* a2_l = (const float*)d_in[5];
    const float* a2_r = (const float*)d_in[6];
    const int*   adj  = (const int*)d_in[7];
    float* out = (float*)d_out;

    float* h1 = nullptr; float* gp2 = nullptr;
    cudaGetSymbolAddress((void**)&h1, g_h1);
    cudaGetSymbolAddress((void**)&gp2, g_gp2);

    pack_adj_kernel<<<NN, 256>>>(adj);
    prep_in_kernel<<<640, 256>>>(x, W1);
    gemm1_mma_kernel<<<dim3(4, 32, KS1G), 256>>>();
    elr1f_kernel<<<128, 256>>>(a1_l, a1_r);
    agg1_mma_kernel<<<dim3(H1 * JS1, NN / 128), 256>>>();
    reduce1_kernel<<<NN, 256>>>();
    gemm_kernel<64, 64, 16><<<dim3(OUT_F / 64, NN / 64, KS2G), 256>>>(
        h1, W2, gp2, NN, OUT_F, HID / KS2G, HID);
    elr2f_kernel<<<128, 256>>>(a2_l, a2_r);
    agg2_mma_kernel<<<dim3(JS2, NN / 64), 256>>>();
    reduce2_kernel<<<NN, 128>>>(out);
}

// round 11
// speedup vs baseline: 2.6277x; 1.0855x over previous
#include <cuda_runtime.h>

#define NN     2048
#define IN_F   512
#define HID    256
#define OUT_F  128
#define H1     8
#define NWORDS 64   // NN/32
#define JS1    4    // agg1 j-split
#define JS2    8    // agg2 j-split
#define KS1G   2    // gemm1 K-split
#define KS2G   4    // gemm2 K-split

typedef unsigned long long ull;
typedef unsigned u32;

// pack {lo, hi} floats into bf16x2 (element0 = lo)
__device__ __forceinline__ u32 packbf(float lo, float hi) {
    u32 d; asm("cvt.rn.bf16x2.f32 %0, %1, %2;" : "=r"(d) : "f"(hi), "f"(lo)); return d;
}
__device__ __forceinline__ float bf_lo(u32 p) { return __uint_as_float(p << 16); }
__device__ __forceinline__ float bf_hi(u32 p) { return __uint_as_float(p & 0xffff0000u); }

__device__ __forceinline__ void mma16(float* d, const u32* a, u32 b0, u32 b1) {
    asm volatile(
        "mma.sync.aligned.m16n8k16.row.col.f32.bf16.bf16.f32 "
        "{%0,%1,%2,%3}, {%4,%5,%6,%7}, {%8,%9}, {%0,%1,%2,%3};"
        : "+f"(d[0]), "+f"(d[1]), "+f"(d[2]), "+f"(d[3])
        : "r"(a[0]), "r"(a[1]), "r"(a[2]), "r"(a[3]), "r"(b0), "r"(b1));
}
__device__ __forceinline__ void cpa16(u32 s, const void* g) {
    asm volatile("cp.async.ca.shared.global [%0], [%1], 16;" :: "r"(s), "l"(g));
}
#define CP_COMMIT asm volatile("cp.async.commit_group;")
#define CP_WAIT1  asm volatile("cp.async.wait_group 1;")
#define CP_WAIT0  asm volatile("cp.async.wait_group 0;")

// ---------------- scratch ----------------
__device__ __align__(16) float4 g_xAh[128 * 32 * 32];   // x A-frag hi (2MB)
__device__ __align__(16) float4 g_xAl[128 * 32 * 32];
__device__ __align__(16) float4 g_w1B[32 * 32 * 32];    // W1 B-frags
__device__ __align__(16) float4 g_w2B[16 * 16 * 32];    // W2 B-frags
__device__ __align__(16) float  g_gp1[KS1G * NN * HID];
__device__ __align__(16) float4 g_eli1t[H1 * NN];   // [h][i] {-el, exp(el), exp(0.2el), 0}
__device__ __align__(16) float4 g_ebd1t[H1 * NN];   // [h][j]
__device__ __align__(16) float4 g_frag1[H1 * 128 * 4 * 32];   // agg1 bf16 B-frags (2MB)
__device__ unsigned g_bits[NN * NWORDS];
__device__ __align__(16) float  g_n1[JS1 * NN * HID];
__device__ float  g_d1[JS1 * NN * H1];
__device__ __align__(16) float4 g_h1Ah[128 * 16 * 32];  // h1 A-frags hi (1MB)
__device__ __align__(16) float4 g_h1Al[128 * 16 * 32];
__device__ __align__(16) float  g_gp2[KS2G * NN * OUT_F];
__device__ __align__(16) float4 g_eli2[NN];
__device__ __align__(16) float4 g_ebd2[NN];
__device__ __align__(16) float4 g_frag2[128 * 4 * 128];       // agg2 bf16 B-frags (1MB)
__device__ __align__(16) float  g_part[JS2 * NN * OUT_F];
__device__ float  g_psum[JS2 * NN];

// ---------------- pack adjacency ----------------
__global__ void pack_adj_kernel(const int* __restrict__ adj) {
    int i = blockIdx.x;
    int t = threadIdx.x;  // 256
    const int* row = adj + (size_t)i * NN;
#pragma unroll
    for (int k = 0; k < 8; k++) {
        int j = k * 256 + t;
        unsigned b = __ballot_sync(0xffffffffu, row[j] != 0);
        if ((t & 31) == 0) g_bits[i * NWORDS + (j >> 5)] = b;
    }
}

// ---------------- prep_in: x A-frags + W1 B-frags + W2 B-frags (bf16 hi/lo) ----------------
__global__ void prep_in_kernel(const float* __restrict__ x, const float* __restrict__ W1,
                               const float* __restrict__ W2) {
    int idx = blockIdx.x * 256 + threadIdx.x;   // < 172032
    if (idx < 131072) {
        int lane = idx & 31, kt = (idx >> 5) & 31, it = idx >> 10;
        int g = lane >> 2, tq = lane & 3;
        int r = it * 16 + g, c = kt * 16 + 2 * tq;
        const float* xr = x + (size_t)r * IN_F + c;
        float2 p0 = *(const float2*)xr;
        float2 p1 = *(const float2*)(xr + 8 * IN_F);
        float2 p2 = *(const float2*)(xr + 8);
        float2 p3 = *(const float2*)(xr + 8 * IN_F + 8);
        u32 a0 = packbf(p0.x, p0.y), a1 = packbf(p1.x, p1.y);
        u32 a2 = packbf(p2.x, p2.y), a3 = packbf(p3.x, p3.y);
        g_xAh[idx] = make_float4(__uint_as_float(a0), __uint_as_float(a1),
                                 __uint_as_float(a2), __uint_as_float(a3));
        u32 l0 = packbf(p0.x - bf_lo(a0), p0.y - bf_hi(a0));
        u32 l1 = packbf(p1.x - bf_lo(a1), p1.y - bf_hi(a1));
        u32 l2 = packbf(p2.x - bf_lo(a2), p2.y - bf_hi(a2));
        u32 l3 = packbf(p3.x - bf_lo(a3), p3.y - bf_hi(a3));
        g_xAl[idx] = make_float4(__uint_as_float(l0), __uint_as_float(l1),
                                 __uint_as_float(l2), __uint_as_float(l3));
    } else if (idx < 163840) {
        int e = idx - 131072;                   // < 32768
        int lane = e & 31, nt = (e >> 5) & 31, kt = e >> 10;
        int g = lane >> 2, tq = lane & 3;
        int n = nt * 8 + g, k0 = kt * 16 + 2 * tq;
        float b0a = W1[(size_t)k0 * HID + n];
        float b0b = W1[(size_t)(k0 + 1) * HID + n];
        float b1a = W1[(size_t)(k0 + 8) * HID + n];
        float b1b = W1[(size_t)(k0 + 9) * HID + n];
        u32 bh0 = packbf(b0a, b0b), bh1 = packbf(b1a, b1b);
        u32 bl0 = packbf(b0a - bf_lo(bh0), b0b - bf_hi(bh0));
        u32 bl1 = packbf(b1a - bf_lo(bh1), b1b - bf_hi(bh1));
        g_w1B[e] = make_float4(__uint_as_float(bh0), __uint_as_float(bh1),
                               __uint_as_float(bl0), __uint_as_float(bl1));
    } else {
        int e = idx - 163840;                   // < 8192
        int lane = e & 31, nt = (e >> 5) & 15, kt = e >> 9;
        int g = lane >> 2, tq = lane & 3;
        int n = nt * 8 + g, k0 = kt * 16 + 2 * tq;
        float b0a = W2[(size_t)k0 * OUT_F + n];
        float b0b = W2[(size_t)(k0 + 1) * OUT_F + n];
        float b1a = W2[(size_t)(k0 + 8) * OUT_F + n];
        float b1b = W2[(size_t)(k0 + 9) * OUT_F + n];
        u32 bh0 = packbf(b0a, b0b), bh1 = packbf(b1a, b1b);
        u32 bl0 = packbf(b0a - bf_lo(bh0), b0b - bf_hi(bh0));
        u32 bl1 = packbf(b1a - bf_lo(bh1), b1b - bf_hi(bh1));
        g_w2B[e] = make_float4(__uint_as_float(bh0), __uint_as_float(bh1),
                               __uint_as_float(bl0), __uint_as_float(bl1));
    }
}

// ---------------- gemm1 bf16 tensor: 64i x 64n per block, K-split 2 ----------------
__global__ __launch_bounds__(256) void gemm1_mma_kernel() {
    __shared__ __align__(16) float4 Ah_s[2][4][2][32];
    __shared__ __align__(16) float4 Al_s[2][4][2][32];
    __shared__ __align__(16) float4 Bb_s[2][2][8][32];
    int z = blockIdx.z;
    int bi_t = blockIdx.y * 4;
    int bn_t = blockIdx.x * 8;
    int t = threadIdx.x;
    int lane = t & 31, w = t >> 5;
    int itw = w >> 1, nh = w & 1;
    float acc[4][4] = {};
    int ktz = z * 16;

#define GM_STAGE(b, ch) do { \
        int kt0 = ktz + (ch) * 2; \
        { int e = t; int ln = e & 31, kk = (e >> 5) & 1, it = e >> 6; \
          size_t gi = ((size_t)(bi_t + it) * 32 + kt0 + kk) * 32 + ln; \
          cpa16((u32)__cvta_generic_to_shared(&Ah_s[b][it][kk][ln]), g_xAh + gi); \
          cpa16((u32)__cvta_generic_to_shared(&Al_s[b][it][kk][ln]), g_xAl + gi); } \
        _Pragma("unroll") \
        for (int q = 0; q < 2; q++) { int e = t + q * 256; \
          int ln = e & 31, nt = (e >> 5) & 7, kk = e >> 8; \
          size_t gb = ((size_t)(kt0 + kk) * 32 + bn_t + nt) * 32 + ln; \
          cpa16((u32)__cvta_generic_to_shared(&Bb_s[b][kk][nt][ln]), g_w1B + gb); } \
    } while (0)

    GM_STAGE(0, 0);
    CP_COMMIT;
    for (int ch = 0; ch < 8; ch++) {
        int b = ch & 1;
        if (ch + 1 < 8) {
            GM_STAGE(b ^ 1, ch + 1);
            CP_COMMIT;
            CP_WAIT1;
        } else {
            CP_WAIT0;
        }
        __syncthreads();
#pragma unroll
        for (int kt = 0; kt < 2; kt++) {
            float4 a4h = Ah_s[b][itw][kt][lane];
            float4 a4l = Al_s[b][itw][kt][lane];
            u32 ah[4] = {__float_as_uint(a4h.x), __float_as_uint(a4h.y),
                         __float_as_uint(a4h.z), __float_as_uint(a4h.w)};
            u32 alr[4] = {__float_as_uint(a4l.x), __float_as_uint(a4l.y),
                          __float_as_uint(a4l.z), __float_as_uint(a4l.w)};
#pragma unroll
            for (int n4 = 0; n4 < 4; n4++) {
                float4 bb = Bb_s[b][kt][nh * 4 + n4][lane];
                u32 bh0 = __float_as_uint(bb.x), bh1 = __float_as_uint(bb.y);
                u32 bl0 = __float_as_uint(bb.z), bl1 = __float_as_uint(bb.w);
                mma16(acc[n4], ah, bh0, bh1);
                mma16(acc[n4], ah, bl0, bl1);
                mma16(acc[n4], alr, bh0, bh1);
            }
        }
        __syncthreads();
    }
    int g = lane >> 2, tq = lane & 3;
    int r0 = blockIdx.y * 64 + itw * 16 + g;
    float* Cz = g_gp1 + (size_t)z * NN * HID;
#pragma unroll
    for (int n4 = 0; n4 < 4; n4++) {
        int c = blockIdx.x * 64 + (nh * 4 + n4) * 8 + tq * 2;
        *(float2*)(Cz + (size_t)r0 * HID + c) = make_float2(acc[n4][0], acc[n4][1]);
        *(float2*)(Cz + (size_t)(r0 + 8) * HID + c) = make_float2(acc[n4][2], acc[n4][3]);
    }
}

// ---------------- elr1f: per-(jt,head) fused partial-sum + el/er + frag emit ----------------
__global__ __launch_bounds__(128) void elr1f_kernel(const float* __restrict__ al,
                                                    const float* __restrict__ ar) {
    __shared__ float v_s[16][32];
    __shared__ float elb[16], erb[16];
    int jt = blockIdx.x;       // 128
    int h = blockIdx.y;        // 8
    int base = jt * 16;
    int t = threadIdx.x;       // 128
    int f = t & 31, wr = t >> 5;
    float alv = al[f], arv = ar[f];
#pragma unroll
    for (int s4 = 0; s4 < 4; s4++) {
        int node = wr * 4 + s4;
        float x = 0.f;
#pragma unroll
        for (int z = 0; z < KS1G; z++)
            x += g_gp1[((size_t)z * NN + base + node) * HID + h * 32 + f];
        v_s[node][f] = x;
        float pl = x * alv, pr = x * arv;
#pragma unroll
        for (int o = 16; o; o >>= 1) {
            pl += __shfl_down_sync(0xffffffffu, pl, o);
            pr += __shfl_down_sync(0xffffffffu, pr, o);
        }
        if (f == 0) { elb[node] = pl; erb[node] = pr; }
    }
    __syncthreads();
    if (t < 16) {
        float el = elb[t], er = erb[t];
        g_eli1t[h * NN + base + t] = make_float4(-el, __expf(el), __expf(0.2f * el), 0.f);
        g_ebd1t[h * NN + base + t] = make_float4(er, __expf(er), __expf(0.2f * er), 0.f);
    }
    int tq = t >> 5, ff = t & 31;
    float v0 = v_s[2 * tq][ff];
    float v1 = v_s[2 * tq + 1][ff];
    float v2 = v_s[2 * tq + 8][ff];
    float v3 = v_s[2 * tq + 9][ff];
    u32 bh0 = packbf(v0, v1), bh1 = packbf(v2, v3);
    u32 bl0 = packbf(v0 - bf_lo(bh0), v1 - bf_hi(bh0));
    u32 bl1 = packbf(v2 - bf_lo(bh1), v3 - bf_hi(bh1));
    g_frag1[((size_t)(h * 128 + jt) * 4 + tq) * 32 + ff] =
        make_float4(__uint_as_float(bh0), __uint_as_float(bh1),
                    __uint_as_float(bl0), __uint_as_float(bl1));
}

// ---------------- layer1 aggregation: bf16 m16n8k16 ----------------
__global__ __launch_bounds__(256, 4) void agg1_mma_kernel() {
    __shared__ __align__(16) float4 S4[2][2][4][34];
    __shared__ __align__(16) float4 ebd_s[2][32];
    int h = blockIdx.x >> 2;
    int p = blockIdx.x & 3;
    int bi = blockIdx.y * 128;
    int t = threadIdx.x;
    int lane = t & 31, w = t >> 5;
    int g = lane >> 2, tq = lane & 3;
    int iA = bi + w * 16 + g;
    int iB = iA + 8;
    float4 eA = g_eli1t[h * NN + iA];
    float4 eB = g_eli1t[h * NN + iB];
    float acc[4][4] = {};
    float lsA = 0.f, lsB = 0.f;

    int sf = t & 31, stq = (t >> 5) & 3, skt = t >> 7;
    const float4* fb = g_frag1 + (size_t)h * 128 * 4 * 32;
    int jstart = p * (NN / JS1);   // 512 j
    const int NC = (NN / JS1) / 32;  // 16

#define STAGE1(b, j0) do { \
        int jt0 = (j0) >> 4; \
        cpa16((u32)__cvta_generic_to_shared(&S4[b][skt][stq][sf]), \
              fb + ((size_t)(jt0 + skt) * 4 + stq) * 32 + sf); \
        if (t < 32) cpa16((u32)__cvta_generic_to_shared(&ebd_s[b][t]), g_ebd1t + h * NN + (j0) + t); \
    } while (0)

    STAGE1(0, jstart);
    CP_COMMIT;
    for (int c = 0; c < NC; c++) {
        int b = c & 1;
        if (c + 1 < NC) {
            STAGE1(b ^ 1, jstart + (c + 1) * 32);
            CP_COMMIT;
            CP_WAIT1;
        } else {
            CP_WAIT0;
        }
        __syncthreads();
        int j0 = jstart + c * 32;
        unsigned wordA = g_bits[(size_t)iA * NWORDS + (j0 >> 5)];
        unsigned wordB = g_bits[(size_t)iB * NWORDS + (j0 >> 5)];
#pragma unroll
        for (int kt = 0; kt < 2; kt++) {
            int jb = kt * 16 + 2 * tq;
            float4 e1 = ebd_s[b][jb];
            float4 e2 = ebd_s[b][jb + 1];
            float4 e3 = ebd_s[b][jb + 8];
            float4 e4 = ebd_s[b][jb + 9];
            float wA1 = (e1.x > eA.x) ? eA.y * e1.y : eA.z * e1.z;
            float wA2 = (e2.x > eA.x) ? eA.y * e2.y : eA.z * e2.z;
            float wA3 = (e3.x > eA.x) ? eA.y * e3.y : eA.z * e3.z;
            float wA4 = (e4.x > eA.x) ? eA.y * e4.y : eA.z * e4.z;
            float wB1 = (e1.x > eB.x) ? eB.y * e1.y : eB.z * e1.z;
            float wB2 = (e2.x > eB.x) ? eB.y * e2.y : eB.z * e2.z;
            float wB3 = (e3.x > eB.x) ? eB.y * e3.y : eB.z * e3.z;
            float wB4 = (e4.x > eB.x) ? eB.y * e4.y : eB.z * e4.z;
            wA1 = ((wordA >> jb) & 1u) ? wA1 : 0.f;
            wA2 = ((wordA >> (jb + 1)) & 1u) ? wA2 : 0.f;
            wA3 = ((wordA >> (jb + 8)) & 1u) ? wA3 : 0.f;
            wA4 = ((wordA >> (jb + 9)) & 1u) ? wA4 : 0.f;
            wB1 = ((wordB >> jb) & 1u) ? wB1 : 0.f;
            wB2 = ((wordB >> (jb + 1)) & 1u) ? wB2 : 0.f;
            wB3 = ((wordB >> (jb + 8)) & 1u) ? wB3 : 0.f;
            wB4 = ((wordB >> (jb + 9)) & 1u) ? wB4 : 0.f;
            lsA += (wA1 + wA2) + (wA3 + wA4);
            lsB += (wB1 + wB2) + (wB3 + wB4);
            u32 ah[4], al4[4];
            ah[0] = packbf(wA1, wA2); ah[1] = packbf(wB1, wB2);
            ah[2] = packbf(wA3, wA4); ah[3] = packbf(wB3, wB4);
            al4[0] = packbf(wA1 - bf_lo(ah[0]), wA2 - bf_hi(ah[0]));
            al4[1] = packbf(wB1 - bf_lo(ah[1]), wB2 - bf_hi(ah[1]));
            al4[2] = packbf(wA3 - bf_lo(ah[2]), wA4 - bf_hi(ah[2]));
            al4[3] = packbf(wB3 - bf_lo(ah[3]), wB4 - bf_hi(ah[3]));
#pragma unroll
            for (int nt = 0; nt < 4; nt++) {
                float4 bfr = S4[b][kt][tq][nt * 8 + g];
                u32 bh0 = __float_as_uint(bfr.x), bh1 = __float_as_uint(bfr.y);
                u32 bl0 = __float_as_uint(bfr.z), bl1 = __float_as_uint(bfr.w);
                mma16(acc[nt], ah, bh0, bh1);
                mma16(acc[nt], ah, bl0, bl1);
                mma16(acc[nt], al4, bh0, bh1);
            }
        }
        __syncthreads();
    }
    lsA += __shfl_xor_sync(0xffffffffu, lsA, 1);
    lsA += __shfl_xor_sync(0xffffffffu, lsA, 2);
    lsB += __shfl_xor_sync(0xffffffffu, lsB, 1);
    lsB += __shfl_xor_sync(0xffffffffu, lsB, 2);
    size_t rbase = (size_t)p * NN;
    if (tq == 0) {
        g_d1[(rbase + iA) * H1 + h] = lsA;
        g_d1[(rbase + iB) * H1 + h] = lsB;
    }
#pragma unroll
    for (int nt = 0; nt < 4; nt++) {
        int f = h * 32 + nt * 8 + tq * 2;
        *(float2*)(g_n1 + (rbase + iA) * HID + f) = make_float2(acc[nt][0], acc[nt][1]);
        *(float2*)(g_n1 + (rbase + iB) * HID + f) = make_float2(acc[nt][2], acc[nt][3]);
    }
}

// ---------------- reduce1f: partial reduce + divide + ELU + bf16 A-frag emit ----------------
__global__ __launch_bounds__(256) void reduce1f_kernel() {
    __shared__ float v_s[16][132];
    int jt = blockIdx.x;        // 128
    int fh = blockIdx.y;        // 2
    int base = jt * 16;
    int t = threadIdx.x;        // 256
    int f = t & 127, nh = t >> 7;
    int gf = fh * 128 + f;
    int h = gf >> 5;
#pragma unroll
    for (int s8 = 0; s8 < 8; s8++) {
        int node = nh * 8 + s8;
        float num = 0.f, den = 0.f;
#pragma unroll
        for (int p = 0; p < JS1; p++) {
            num += g_n1[((size_t)p * NN + base + node) * HID + gf];
            den += g_d1[(p * NN + base + node) * H1 + h];
        }
        float o = num / den;
        v_s[node][f] = o > 0.f ? o : expm1f(o);
    }
    __syncthreads();
    int lane = t & 31, ktl = t >> 5;   // 8 local k-tiles
    int kt = fh * 8 + ktl;
    int g = lane >> 2, tq = lane & 3;
    int c = ktl * 16 + 2 * tq;
    float p0a = v_s[g][c],     p0b = v_s[g][c + 1];
    float p1a = v_s[g + 8][c], p1b = v_s[g + 8][c + 1];
    float p2a = v_s[g][c + 8],     p2b = v_s[g][c + 9];
    float p3a = v_s[g + 8][c + 8], p3b = v_s[g + 8][c + 9];
    u32 a0 = packbf(p0a, p0b), a1 = packbf(p1a, p1b);
    u32 a2 = packbf(p2a, p2b), a3 = packbf(p3a, p3b);
    size_t widx = ((size_t)jt * 16 + kt) * 32 + lane;
    g_h1Ah[widx] = make_float4(__uint_as_float(a0), __uint_as_float(a1),
                               __uint_as_float(a2), __uint_as_float(a3));
    u32 l0 = packbf(p0a - bf_lo(a0), p0b - bf_hi(a0));
    u32 l1 = packbf(p1a - bf_lo(a1), p1b - bf_hi(a1));
    u32 l2 = packbf(p2a - bf_lo(a2), p2b - bf_hi(a2));
    u32 l3 = packbf(p3a - bf_lo(a3), p3b - bf_hi(a3));
    g_h1Al[widx] = make_float4(__uint_as_float(l0), __uint_as_float(l1),
                               __uint_as_float(l2), __uint_as_float(l3));
}

// ---------------- gemm2 bf16 tensor: 64i x 64n per block, K-split 4 ----------------
__global__ __launch_bounds__(256) void gemm2_mma_kernel() {
    __shared__ __align__(16) float4 Ah_s[2][4][2][32];
    __shared__ __align__(16) float4 Al_s[2][4][2][32];
    __shared__ __align__(16) float4 Bb_s[2][2][8][32];
    int z = blockIdx.z;          // 0..3
    int bi_t = blockIdx.y * 4;
    int bn_t = blockIdx.x * 8;   // 0 or 8
    int t = threadIdx.x;
    int lane = t & 31, w = t >> 5;
    int itw = w >> 1, nh = w & 1;
    float acc[4][4] = {};
    int ktz = z * 4;             // 4 k-tiles per z (K=256 -> 16 kt)

#define GM2_STAGE(b, ch) do { \
        int kt0 = ktz + (ch) * 2; \
        { int e = t; int ln = e & 31, kk = (e >> 5) & 1, it = e >> 6; \
          size_t gi = ((size_t)(bi_t + it) * 16 + kt0 + kk) * 32 + ln; \
          cpa16((u32)__cvta_generic_to_shared(&Ah_s[b][it][kk][ln]), g_h1Ah + gi); \
          cpa16((u32)__cvta_generic_to_shared(&Al_s[b][it][kk][ln]), g_h1Al + gi); } \
        _Pragma("unroll") \
        for (int q = 0; q < 2; q++) { int e = t + q * 256; \
          int ln = e & 31, nt = (e >> 5) & 7, kk = e >> 8; \
          size_t gb = ((size_t)(kt0 + kk) * 16 + bn_t + nt) * 32 + ln; \
          cpa16((u32)__cvta_generic_to_shared(&Bb_s[b][kk][nt][ln]), g_w2B + gb); } \
    } while (0)

    GM2_STAGE(0, 0);
    CP_COMMIT;
    for (int ch = 0; ch < 2; ch++) {
        int b = ch & 1;
        if (ch + 1 < 2) {
            GM2_STAGE(b ^ 1, ch + 1);
            CP_COMMIT;
            CP_WAIT1;
        } else {
            CP_WAIT0;
        }
        __syncthreads();
#pragma unroll
        for (int kt = 0; kt < 2; kt++) {
            float4 a4h = Ah_s[b][itw][kt][lane];
            float4 a4l = Al_s[b][itw][kt][lane];
            u32 ah[4] = {__float_as_uint(a4h.x), __float_as_uint(a4h.y),
                         __float_as_uint(a4h.z), __float_as_uint(a4h.w)};
            u32 alr[4] = {__float_as_uint(a4l.x), __float_as_uint(a4l.y),
                          __float_as_uint(a4l.z), __float_as_uint(a4l.w)};
#pragma unroll
            for (int n4 = 0; n4 < 4; n4++) {
                float4 bb = Bb_s[b][kt][nh * 4 + n4][lane];
                u32 bh0 = __float_as_uint(bb.x), bh1 = __float_as_uint(bb.y);
                u32 bl0 = __float_as_uint(bb.z), bl1 = __float_as_uint(bb.w);
                mma16(acc[n4], ah, bh0, bh1);
                mma16(acc[n4], ah, bl0, bl1);
                mma16(acc[n4], alr, bh0, bh1);
            }
        }
        __syncthreads();
    }
    int g = lane >> 2, tq = lane & 3;
    int r0 = blockIdx.y * 64 + itw * 16 + g;
    float* Cz = g_gp2 + (size_t)z * NN * OUT_F;
#pragma unroll
    for (int n4 = 0; n4 < 4; n4++) {
        int c = blockIdx.x * 64 + (nh * 4 + n4) * 8 + tq * 2;
        *(float2*)(Cz + (size_t)r0 * OUT_F + c) = make_float2(acc[n4][0], acc[n4][1]);
        *(float2*)(Cz + (size_t)(r0 + 8) * OUT_F + c) = make_float2(acc[n4][2], acc[n4][3]);
    }
}

// ---------------- elr2f: fused K-partial sum + el/er + bf16 fragment emit ----------------
__global__ __launch_bounds__(256) void elr2f_kernel(const float* __restrict__ al,
                                                    const float* __restrict__ ar) {
    __shared__ float v_s[16][128];
    __shared__ float pel[16][4], per[16][4];
    int jt = blockIdx.x;             // 128 blocks
    int base = jt * 16;
    int t = threadIdx.x;
    int f = t & 127, th = t >> 7;
    int wq = (t >> 5) & 3, lane = t & 31;

    float v[8];
#pragma unroll
    for (int s = 0; s < 8; s++) {
        int node = 2 * s + th;
        float x = 0.f;
#pragma unroll
        for (int z = 0; z < KS2G; z++)
            x += g_gp2[((size_t)z * NN + base + node) * OUT_F + f];
        v[s] = x;
        v_s[node][f] = x;
    }
    float alv = al[f], arv = ar[f];
#pragma unroll
    for (int s = 0; s < 8; s++) {
        float pl = v[s] * alv, pr = v[s] * arv;
#pragma unroll
        for (int o = 16; o; o >>= 1) {
            pl += __shfl_down_sync(0xffffffffu, pl, o);
            pr += __shfl_down_sync(0xffffffffu, pr, o);
        }
        if (lane == 0) { pel[2 * s + th][wq] = pl; per[2 * s + th][wq] = pr; }
    }
    __syncthreads();
    if (t < 16) {
        float el = pel[t][0] + pel[t][1] + pel[t][2] + pel[t][3];
        float er = per[t][0] + per[t][1] + per[t][2] + per[t][3];
        g_eli2[base + t] = make_float4(-el, __expf(el), __expf(0.2f * el), 0.f);
        g_ebd2[base + t] = make_float4(er, __expf(er), __expf(0.2f * er), 0.f);
    }
#pragma unroll
    for (int q = 0; q < 2; q++) {
        int widx = t + q * 256;          // 0..511
        int ff = widx & 127, tq = widx >> 7;
        float v0 = v_s[2 * tq][ff];
        float v1 = v_s[2 * tq + 1][ff];
        float v2 = v_s[2 * tq + 8][ff];
        float v3 = v_s[2 * tq + 9][ff];
        u32 bh0 = packbf(v0, v1), bh1 = packbf(v2, v3);
        u32 bl0 = packbf(v0 - bf_lo(bh0), v1 - bf_hi(bh0));
        u32 bl1 = packbf(v2 - bf_lo(bh1), v3 - bf_hi(bh1));
        g_frag2[((size_t)jt * 4 + tq) * 128 + ff] =
            make_float4(__uint_as_float(bh0), __uint_as_float(bh1),
                        __uint_as_float(bl0), __uint_as_float(bl1));
    }
}

// ---------------- layer2 aggregation: bf16 m16n8k16, 64-row tiles ----------------
__global__ __launch_bounds__(256, 4) void agg2_mma_kernel() {
    __shared__ __align__(16) float4 S4[2][4][130];
    __shared__ __align__(16) float4 ebd_s[2][16];
    int p = blockIdx.x;          // 0..7
    int bi = blockIdx.y * 64;
    int t = threadIdx.x;
    int lane = t & 31, w = t >> 5;
    int g = lane >> 2, tq = lane & 3;
    int it = w >> 1, nth = w & 1;
    int iA = bi + it * 16 + g;
    int iB = iA + 8;
    float4 eA = g_eli2[iA];
    float4 eB = g_eli2[iB];
    float acc[8][4] = {};
    float lsA = 0.f, lsB = 0.f;

    int jstart = p * (NN / JS2);     // 256 j
    const int NC = (NN / JS2) / 16;  // 16

#define STAGE2(b, j0) do { \
        int jt0 = (j0) >> 4; \
        _Pragma("unroll") \
        for (int e = t; e < 512; e += 256) { \
            int sq = e >> 7, ff = e & 127; \
            cpa16((u32)__cvta_generic_to_shared(&S4[b][sq][ff]), \
                  g_frag2 + ((size_t)jt0 * 4 + sq) * 128 + ff); \
        } \
        if (t < 16) cpa16((u32)__cvta_generic_to_shared(&ebd_s[b][t]), g_ebd2 + (j0) + t); \
    } while (0)

    STAGE2(0, jstart);
    CP_COMMIT;
    for (int c = 0; c < NC; c++) {
        int b = c & 1;
        if (c + 1 < NC) {
            STAGE2(b ^ 1, jstart + (c + 1) * 16);
            CP_COMMIT;
            CP_WAIT1;
        } else {
            CP_WAIT0;
        }
        __syncthreads();
        int j0 = jstart + c * 16;
        unsigned wordA = g_bits[(size_t)iA * NWORDS + (j0 >> 5)] >> (j0 & 31);
        unsigned wordB = g_bits[(size_t)iB * NWORDS + (j0 >> 5)] >> (j0 & 31);
        int jb = 2 * tq;
        float4 e1 = ebd_s[b][jb];
        float4 e2 = ebd_s[b][jb + 1];
        float4 e3 = ebd_s[b][jb + 8];
        float4 e4 = ebd_s[b][jb + 9];
        float wA1 = (e1.x > eA.x) ? eA.y * e1.y : eA.z * e1.z;
        float wA2 = (e2.x > eA.x) ? eA.y * e2.y : eA.z * e2.z;
        float wA3 = (e3.x > eA.x) ? eA.y * e3.y : eA.z * e3.z;
        float wA4 = (e4.x > eA.x) ? eA.y * e4.y : eA.z * e4.z;
        float wB1 = (e1.x > eB.x) ? eB.y * e1.y : eB.z * e1.z;
        float wB2 = (e2.x > eB.x) ? eB.y * e2.y : eB.z * e2.z;
        float wB3 = (e3.x > eB.x) ? eB.y * e3.y : eB.z * e3.z;
        float wB4 = (e4.x > eB.x) ? eB.y * e4.y : eB.z * e4.z;
        wA1 = ((wordA >> jb) & 1u) ? wA1 : 0.f;
        wA2 = ((wordA >> (jb + 1)) & 1u) ? wA2 : 0.f;
        wA3 = ((wordA >> (jb + 8)) & 1u) ? wA3 : 0.f;
        wA4 = ((wordA >> (jb + 9)) & 1u) ? wA4 : 0.f;
        wB1 = ((wordB >> jb) & 1u) ? wB1 : 0.f;
        wB2 = ((wordB >> (jb + 1)) & 1u) ? wB2 : 0.f;
        wB3 = ((wordB >> (jb + 8)) & 1u) ? wB3 : 0.f;
        wB4 = ((wordB >> (jb + 9)) & 1u) ? wB4 : 0.f;
        lsA += (wA1 + wA2) + (wA3 + wA4);
        lsB += (wB1 + wB2) + (wB3 + wB4);
        u32 ah[4], al4[4];
        ah[0] = packbf(wA1, wA2); ah[1] = packbf(wB1, wB2);
        ah[2] = packbf(wA3, wA4); ah[3] = packbf(wB3, wB4);
        al4[0] = packbf(wA1 - bf_lo(ah[0]), wA2 - bf_hi(ah[0]));
        al4[1] = packbf(wB1 - bf_lo(ah[1]), wB2 - bf_hi(ah[1]));
        al4[2] = packbf(wA3 - bf_lo(ah[2]), wA4 - bf_hi(ah[2]));
        al4[3] = packbf(wB3 - bf_lo(ah[3]), wB4 - bf_hi(ah[3]));
#pragma unroll
        for (int nt = 0; nt < 8; nt++) {
            float4 bfr = S4[b][tq][(nth * 8 + nt) * 8 + g];
            u32 bh0 = __float_as_uint(bfr.x), bh1 = __float_as_uint(bfr.y);
            u32 bl0 = __float_as_uint(bfr.z), bl1 = __float_as_uint(bfr.w);
            mma16(acc[nt], ah, bh0, bh1);
            mma16(acc[nt], ah, bl0, bl1);
            mma16(acc[nt], al4, bh0, bh1);
        }
        __syncthreads();
    }
    lsA += __shfl_xor_sync(0xffffffffu, lsA, 1);
    lsA += __shfl_xor_sync(0xffffffffu, lsA, 2);
    lsB += __shfl_xor_sync(0xffffffffu, lsB, 1);
    lsB += __shfl_xor_sync(0xffffffffu, lsB, 2);
    if (tq == 0 && nth == 0) {
        g_psum[p * NN + iA] = lsA;
        g_psum[p * NN + iB] = lsB;
    }
    float* pb = g_part + (size_t)p * NN * OUT_F;
#pragma unroll
    for (int nt = 0; nt < 8; nt++) {
        int f = (nth * 8 + nt) * 8 + tq * 2;
        *(float2*)(pb + (size_t)iA * OUT_F + f) = make_float2(acc[nt][0], acc[nt][1]);
        *(float2*)(pb + (size_t)iB * OUT_F + f) = make_float2(acc[nt][2], acc[nt][3]);
    }
}

// ---------------- final reduce + divide ----------------
__global__ void reduce2_kernel(float* __restrict__ out) {
    int i = blockIdx.x;
    int f = threadIdx.x;  // 128
    float num = 0.f, den = 0.f;
#pragma unroll
    for (int p = 0; p < JS2; p++) {
        num += g_part[(size_t)p * NN * OUT_F + (size_t)i * OUT_F + f];
        den += g_psum[p * NN + i];
    }
    out[i * OUT_F + f] = num / den;
}

// ---------------- launch ----------------
extern "C" void kernel_launch(void* const* d_in, const int* in_sizes, int n_in,
                              void* d_out, int out_size) {
    const float* x    = (const float*)d_in[0];
    const float* W1   = (const float*)d_in[1];
    const float* a1_l = (const float*)d_in[2];
    const float* a1_r = (const float*)d_in[3];
    const float* W2   = (const float*)d_in[4];
    const float* a2_l = (const float*)d_in[5];
    const float* a2_r = (const float*)d_in[6];
    const int*   adj  = (const int*)d_in[7];
    float* out = (float*)d_out;

    pack_adj_kernel<<<NN, 256>>>(adj);
    prep_in_kernel<<<672, 256>>>(x, W1, W2);
    gemm1_mma_kernel<<<dim3(4, 32, KS1G), 256>>>();
    elr1f_kernel<<<dim3(128, H1), 128>>>(a1_l, a1_r);
    agg1_mma_kernel<<<dim3(H1 * JS1, NN / 128), 256>>>();
    reduce1f_kernel<<<dim3(128, 2), 256>>>();
    gemm2_mma_kernel<<<dim3(2, 32, KS2G), 256>>>();
    elr2f_kernel<<<128, 256>>>(a2_l, a2_r);
    agg2_mma_kernel<<<dim3(JS2, NN / 64), 256>>>();
    reduce2_kernel<<<NN, 128>>>(out);
}